// round 1
// baseline (speedup 1.0000x reference)
#include <cuda_runtime.h>
#include <math.h>

// Problem constants
#define BB 2
#define TT 2048
#define CC 768
#define HH 12
#define DD 64
#define MROWS (BB*TT)   // 4096

// ---------------- scratch (device globals; no allocations allowed) ----------
__device__ float g_qkv[(size_t)MROWS * 3 * CC];  // 4096 x 2304
__device__ float g_att[(size_t)MROWS * CC];      // attention output (reused)
__device__ float g_res[(size_t)MROWS * CC];      // pre-LN residual sum (reused 3x)
__device__ float g_x1 [(size_t)MROWS * CC];
__device__ float g_cq [(size_t)MROWS * CC];
__device__ float g_ck [(size_t)MROWS * CC];
__device__ float g_cv [(size_t)MROWS * CC];
__device__ float g_x2 [(size_t)MROWS * CC];
__device__ float g_h  [(size_t)MROWS * 4 * CC];  // 4096 x 3072

// ---------------- SGEMM 128x128x8, 256 threads, 8x8 per thread --------------
enum { EPI_NONE = 0, EPI_RELU = 1, EPI_RES = 2 };

template<int EPI>
__global__ __launch_bounds__(256)
void sgemm_bias(const float* __restrict__ A, const float* __restrict__ Bm,
                const float* __restrict__ bias, const float* __restrict__ res,
                float* __restrict__ Cm, int M, int N, int K)
{
    __shared__ float As[8][128];
    __shared__ float Bs[8][128];

    const int tid = threadIdx.x;
    const int tx = tid & 15;        // 0..15 -> N
    const int ty = tid >> 4;        // 0..15 -> M
    const int mBase = blockIdx.y * 128;
    const int nBase = blockIdx.x * 128;

    // global load indices (one float4 of A and one of B per thread per step)
    const int arow = tid >> 1;            // 0..127
    const int acol = (tid & 1) * 4;       // 0 or 4
    const int brow = tid >> 5;            // 0..7
    const int bcol = (tid & 31) * 4;      // 0..124

    const float* Aptr = A + (size_t)(mBase + arow) * K + acol;
    const float* Bptr = Bm + (size_t)brow * N + nBase + bcol;

    float acc[8][8];
    #pragma unroll
    for (int i = 0; i < 8; i++)
        #pragma unroll
        for (int j = 0; j < 8; j++) acc[i][j] = 0.f;

    for (int k0 = 0; k0 < K; k0 += 8) {
        float4 av = *(const float4*)Aptr;
        float4 bv = *(const float4*)Bptr;
        Aptr += 8;
        Bptr += (size_t)8 * N;

        As[acol + 0][arow] = av.x;
        As[acol + 1][arow] = av.y;
        As[acol + 2][arow] = av.z;
        As[acol + 3][arow] = av.w;
        *(float4*)&Bs[brow][bcol] = bv;
        __syncthreads();

        #pragma unroll
        for (int kk = 0; kk < 8; kk++) {
            float a[8], b[8];
            *(float4*)(a)     = *(const float4*)&As[kk][ty * 8];
            *(float4*)(a + 4) = *(const float4*)&As[kk][ty * 8 + 4];
            *(float4*)(b)     = *(const float4*)&Bs[kk][tx * 8];
            *(float4*)(b + 4) = *(const float4*)&Bs[kk][tx * 8 + 4];
            #pragma unroll
            for (int i = 0; i < 8; i++)
                #pragma unroll
                for (int j = 0; j < 8; j++)
                    acc[i][j] = fmaf(a[i], b[j], acc[i][j]);
        }
        __syncthreads();
    }

    #pragma unroll
    for (int i = 0; i < 8; i++) {
        const int row = mBase + ty * 8 + i;
        #pragma unroll
        for (int j = 0; j < 8; j++) {
            const int col = nBase + tx * 8 + j;
            float v = acc[i][j] + bias[col];
            if (EPI == EPI_RELU) v = fmaxf(v, 0.f);
            if (EPI == EPI_RES)  v += res[(size_t)row * N + col];
            Cm[(size_t)row * N + col] = v;
        }
    }
}

// ---------------- streaming-softmax attention -------------------------------
// One warp per query row; 8 warps (8 queries) per block; K/V staged in SMEM
// in 64-key tiles. Lane l owns output dims {2l, 2l+1}.
template<bool CAUSAL>
__global__ __launch_bounds__(256)
void attn_k(const float* __restrict__ Q, const float* __restrict__ Kp,
            const float* __restrict__ Vp, float* __restrict__ O,
            int qstride, int kvstride)
{
    __shared__ float Ks[64][64];
    __shared__ float Vs[64][64];

    const int b = blockIdx.z, h = blockIdx.y;
    const int warp = threadIdx.x >> 5, lane = threadIdx.x & 31;
    const int tq = blockIdx.x * 8 + warp;

    const float* qrow = Q + (size_t)(b * TT + tq) * qstride + h * DD;
    const float q0 = qrow[2 * lane];
    const float q1 = qrow[2 * lane + 1];

    const float* kbase = Kp + (size_t)(b * TT) * kvstride + h * DD;
    const float* vbase = Vp + (size_t)(b * TT) * kvstride + h * DD;

    float m = -1e30f, l = 0.f, o0 = 0.f, o1 = 0.f;

    const int blk_kmax = CAUSAL ? (blockIdx.x * 8 + 8) : TT;   // block-uniform
    const int my_kmax  = CAUSAL ? (tq + 1) : TT;               // per-warp
    const int ntiles = (blk_kmax + 63) >> 6;

    for (int t = 0; t < ntiles; t++) {
        __syncthreads();
        #pragma unroll
        for (int i = 0; i < 4; i++) {
            const int idx = threadIdx.x + i * 256;    // 0..1023
            const int key = idx >> 4;                 // 0..63
            const int c4 = (idx & 15) << 2;           // 0..60
            const size_t goff = (size_t)(t * 64 + key) * kvstride + c4;
            *(float4*)&Ks[key][c4] = *(const float4*)(kbase + goff);
            *(float4*)&Vs[key][c4] = *(const float4*)(vbase + goff);
        }
        __syncthreads();

        const int kend = min(64, my_kmax - t * 64);
        for (int kk = 0; kk < kend; kk++) {
            const float2 kf = *(const float2*)&Ks[kk][2 * lane];
            float p = q0 * kf.x + q1 * kf.y;
            #pragma unroll
            for (int off = 16; off; off >>= 1)
                p += __shfl_xor_sync(0xffffffffu, p, off);
            const float s = p * 0.125f;               // 1/sqrt(64)
            const float mnew = fmaxf(m, s);
            const float corr = __expf(m - mnew);
            const float pe = __expf(s - mnew);
            const float2 vf = *(const float2*)&Vs[kk][2 * lane];
            l = l * corr + pe;
            o0 = fmaf(o0, corr, pe * vf.x);
            o1 = fmaf(o1, corr, pe * vf.y);
            m = mnew;
        }
    }

    const float inv = 1.f / l;
    float* orow = O + (size_t)(b * TT + tq) * CC + h * DD;
    orow[2 * lane]     = o0 * inv;
    orow[2 * lane + 1] = o1 * inv;
}

// ---------------- LayerNorm (one block per row of 768) ----------------------
__global__ __launch_bounds__(256)
void layernorm_k(const float* __restrict__ in, const float* __restrict__ g,
                 const float* __restrict__ b, float* __restrict__ out)
{
    const int row = blockIdx.x;
    const int tid = threadIdx.x;
    const float* x = in + (size_t)row * CC;

    const float v0 = x[tid], v1 = x[tid + 256], v2 = x[tid + 512];
    float s = v0 + v1 + v2;
    float sq = v0 * v0 + v1 * v1 + v2 * v2;

    #pragma unroll
    for (int off = 16; off; off >>= 1) {
        s  += __shfl_xor_sync(0xffffffffu, s, off);
        sq += __shfl_xor_sync(0xffffffffu, sq, off);
    }
    __shared__ float red[16];
    const int wid = tid >> 5, lane = tid & 31;
    if (lane == 0) { red[wid] = s; red[wid + 8] = sq; }
    __syncthreads();

    float ts = 0.f, tq = 0.f;
    #pragma unroll
    for (int i = 0; i < 8; i++) { ts += red[i]; tq += red[i + 8]; }

    const float mu = ts * (1.f / CC);
    const float var = tq * (1.f / CC) - mu * mu;
    const float rstd = rsqrtf(var + 1e-5f);

    float* orow = out + (size_t)row * CC;
    orow[tid]       = (v0 - mu) * rstd * g[tid]       + b[tid];
    orow[tid + 256] = (v1 - mu) * rstd * g[tid + 256] + b[tid + 256];
    orow[tid + 512] = (v2 - mu) * rstd * g[tid + 512] + b[tid + 512];
}

// ---------------- launch ----------------------------------------------------
extern "C" void kernel_launch(void* const* d_in, const int* in_sizes, int n_in,
                              void* d_out, int out_size)
{
    const float* x      = (const float*)d_in[0];
    const float* enc    = (const float*)d_in[1];
    const float* ln1_g  = (const float*)d_in[2];
    const float* ln1_b  = (const float*)d_in[3];
    const float* qkv_w  = (const float*)d_in[4];
    const float* qkv_b  = (const float*)d_in[5];
    const float* proj_w = (const float*)d_in[6];
    const float* proj_b = (const float*)d_in[7];
    const float* ln2_g  = (const float*)d_in[8];
    const float* ln2_b  = (const float*)d_in[9];
    const float* caq_w  = (const float*)d_in[10];
    const float* caq_b  = (const float*)d_in[11];
    const float* cak_w  = (const float*)d_in[12];
    const float* cak_b  = (const float*)d_in[13];
    const float* cav_w  = (const float*)d_in[14];
    const float* cav_b  = (const float*)d_in[15];
    const float* cao_w  = (const float*)d_in[16];
    const float* cao_b  = (const float*)d_in[17];
    const float* ln3_g  = (const float*)d_in[18];
    const float* ln3_b  = (const float*)d_in[19];
    const float* fc_w   = (const float*)d_in[20];
    const float* fc_b   = (const float*)d_in[21];
    const float* fc2_w  = (const float*)d_in[22];
    const float* fc2_b  = (const float*)d_in[23];
    float* out = (float*)d_out;

    float *qkv, *att, *res, *x1, *cq, *ck, *cv, *x2, *hbuf;
    cudaGetSymbolAddress((void**)&qkv,  g_qkv);
    cudaGetSymbolAddress((void**)&att,  g_att);
    cudaGetSymbolAddress((void**)&res,  g_res);
    cudaGetSymbolAddress((void**)&x1,   g_x1);
    cudaGetSymbolAddress((void**)&cq,   g_cq);
    cudaGetSymbolAddress((void**)&ck,   g_ck);
    cudaGetSymbolAddress((void**)&cv,   g_cv);
    cudaGetSymbolAddress((void**)&x2,   g_x2);
    cudaGetSymbolAddress((void**)&hbuf, g_h);

    const dim3 thr(256);
    const dim3 g768(CC / 128, MROWS / 128);          // (6, 32)
    const dim3 gqkv(3 * CC / 128, MROWS / 128);      // (18, 32)
    const dim3 gfc(4 * CC / 128, MROWS / 128);       // (24, 32)
    const dim3 gattn(TT / 8, HH, BB);                // (256, 12, 2)

    // 1) qkv = x @ W_qkv + b
    sgemm_bias<EPI_NONE><<<gqkv, thr>>>(x, qkv_w, qkv_b, nullptr, qkv,
                                        MROWS, 3 * CC, CC);
    // 2) causal self-attention (q/k/v are column slices of qkv, stride 2304)
    attn_k<true><<<gattn, thr>>>(qkv, qkv + CC, qkv + 2 * CC, att, 3 * CC, 3 * CC);
    // 3) sa @ proj + b + x  -> res ; LN1 -> x1
    sgemm_bias<EPI_RES><<<g768, thr>>>(att, proj_w, proj_b, x, res,
                                       MROWS, CC, CC);
    layernorm_k<<<MROWS, thr>>>(res, ln1_g, ln1_b, x1);
    // 4) cross-attn projections
    sgemm_bias<EPI_NONE><<<g768, thr>>>(x1,  caq_w, caq_b, nullptr, cq, MROWS, CC, CC);
    sgemm_bias<EPI_NONE><<<g768, thr>>>(enc, cak_w, cak_b, nullptr, ck, MROWS, CC, CC);
    sgemm_bias<EPI_NONE><<<g768, thr>>>(enc, cav_w, cav_b, nullptr, cv, MROWS, CC, CC);
    // 5) cross attention (non-causal)
    attn_k<false><<<gattn, thr>>>(cq, ck, cv, att, CC, CC);
    // 6) ca @ o_w + b + x1 -> res ; LN2 -> x2
    sgemm_bias<EPI_RES><<<g768, thr>>>(att, cao_w, cao_b, x1, res,
                                       MROWS, CC, CC);
    layernorm_k<<<MROWS, thr>>>(res, ln2_g, ln2_b, x2);
    // 7) MLP
    sgemm_bias<EPI_RELU><<<gfc, thr>>>(x2, fc_w, fc_b, nullptr, hbuf,
                                       MROWS, 4 * CC, CC);
    sgemm_bias<EPI_RES><<<g768, thr>>>(hbuf, fc2_w, fc2_b, x2, res,
                                       MROWS, CC, 4 * CC);
    // 8) LN3 -> out
    layernorm_k<<<MROWS, thr>>>(res, ln3_g, ln3_b, out);
}

// round 2
// speedup vs baseline: 2.0169x; 2.0169x over previous
#include <cuda_runtime.h>
#include <math.h>

// Problem constants
#define BB 2
#define TT 2048
#define CC 768
#define HH 12
#define DD 64
#define MROWS (BB*TT)   // 4096

// ---------------- scratch (device globals; no allocations allowed) ----------
__device__ float g_qkv[(size_t)MROWS * 3 * CC];  // 4096 x 2304
__device__ float g_att[(size_t)MROWS * CC];      // attention output (reused)
__device__ float g_res[(size_t)MROWS * CC];      // pre-LN residual sum (reused 3x)
__device__ float g_x1 [(size_t)MROWS * CC];
__device__ float g_cq [(size_t)MROWS * CC];
__device__ float g_ck [(size_t)MROWS * CC];
__device__ float g_cv [(size_t)MROWS * CC];
__device__ float g_x2 [(size_t)MROWS * CC];
__device__ float g_h  [(size_t)MROWS * 4 * CC];  // 4096 x 3072

// ---------------- SGEMM 128x128x8, 256 threads, 8x8 per thread --------------
enum { EPI_NONE = 0, EPI_RELU = 1, EPI_RES = 2 };

template<int EPI>
__global__ __launch_bounds__(256)
void sgemm_bias(const float* __restrict__ A, const float* __restrict__ Bm,
                const float* __restrict__ bias, const float* __restrict__ res,
                float* __restrict__ Cm, int M, int N, int K)
{
    __shared__ float As[8][128];
    __shared__ float Bs[8][128];

    const int tid = threadIdx.x;
    const int tx = tid & 15;        // 0..15 -> N
    const int ty = tid >> 4;        // 0..15 -> M
    const int mBase = blockIdx.y * 128;
    const int nBase = blockIdx.x * 128;

    const int arow = tid >> 1;            // 0..127
    const int acol = (tid & 1) * 4;       // 0 or 4
    const int brow = tid >> 5;            // 0..7
    const int bcol = (tid & 31) * 4;      // 0..124

    const float* Aptr = A + (size_t)(mBase + arow) * K + acol;
    const float* Bptr = Bm + (size_t)brow * N + nBase + bcol;

    float acc[8][8];
    #pragma unroll
    for (int i = 0; i < 8; i++)
        #pragma unroll
        for (int j = 0; j < 8; j++) acc[i][j] = 0.f;

    for (int k0 = 0; k0 < K; k0 += 8) {
        float4 av = *(const float4*)Aptr;
        float4 bv = *(const float4*)Bptr;
        Aptr += 8;
        Bptr += (size_t)8 * N;

        As[acol + 0][arow] = av.x;
        As[acol + 1][arow] = av.y;
        As[acol + 2][arow] = av.z;
        As[acol + 3][arow] = av.w;
        *(float4*)&Bs[brow][bcol] = bv;
        __syncthreads();

        #pragma unroll
        for (int kk = 0; kk < 8; kk++) {
            float a[8], b[8];
            *(float4*)(a)     = *(const float4*)&As[kk][ty * 8];
            *(float4*)(a + 4) = *(const float4*)&As[kk][ty * 8 + 4];
            *(float4*)(b)     = *(const float4*)&Bs[kk][tx * 8];
            *(float4*)(b + 4) = *(const float4*)&Bs[kk][tx * 8 + 4];
            #pragma unroll
            for (int i = 0; i < 8; i++)
                #pragma unroll
                for (int j = 0; j < 8; j++)
                    acc[i][j] = fmaf(a[i], b[j], acc[i][j]);
        }
        __syncthreads();
    }

    #pragma unroll
    for (int i = 0; i < 8; i++) {
        const int row = mBase + ty * 8 + i;
        #pragma unroll
        for (int j = 0; j < 8; j++) {
            const int col = nBase + tx * 8 + j;
            float v = acc[i][j] + bias[col];
            if (EPI == EPI_RELU) v = fmaxf(v, 0.f);
            if (EPI == EPI_RES)  v += res[(size_t)row * N + col];
            Cm[(size_t)row * N + col] = v;
        }
    }
}

// ---------------- tiled flash attention --------------------------------------
// Block: 256 threads, tile = 128 queries x 64 keys, d=64.
// Thread (ty = tid>>4, tx = tid&15) owns S/P rows {ty+16i, i<8} x cols {tx+16j, j<4}.
// Interleaved column ownership keeps all SMEM b-reads bank-conflict-free.
// Q,K stored d-major (transposed) in SMEM; V row-major; P transposed [k][q].
#define QT 128
#define KT 64
#define QST 129   // Qst/Pt row stride (floats)
#define KST 65    // Kst/Vs row stride (floats)

#define SM_QST 0
#define SM_KST (64*QST)               // 8256
#define SM_VS  (SM_KST + 64*KST)      // +4160
#define SM_PT  (SM_VS  + 64*KST)      // +4160
#define SM_TOT (SM_PT  + 64*QST)      // 24832 floats = 99328 B

template<bool CAUSAL>
__global__ __launch_bounds__(256, 2)
void attn_tiled(const float* __restrict__ Q, const float* __restrict__ Kp,
                const float* __restrict__ Vp, float* __restrict__ O,
                int qstride, int kvstride)
{
    extern __shared__ float sm[];
    float* Qst = sm + SM_QST;
    float* Kst = sm + SM_KST;
    float* Vs  = sm + SM_VS;
    float* Pt  = sm + SM_PT;

    const int b = blockIdx.z, h = blockIdx.y, qt = blockIdx.x;
    const int tid = threadIdx.x;
    const int tx = tid & 15, ty = tid >> 4;
    const int qbase = qt * QT;

    // load Q tile (scaled by 1/sqrt(d)=0.125), transposed to [d][q]
    const float* Qbase = Q + (size_t)(b * TT + qbase) * qstride + h * DD;
    #pragma unroll
    for (int i = 0; i < 8; i++) {
        const int lin = tid + i * 256;        // 0..2047
        const int q = lin >> 4;               // 0..127
        const int d4 = (lin & 15) << 2;       // 0..60
        float4 v = *(const float4*)(Qbase + (size_t)q * qstride + d4);
        Qst[(d4 + 0) * QST + q] = v.x * 0.125f;
        Qst[(d4 + 1) * QST + q] = v.y * 0.125f;
        Qst[(d4 + 2) * QST + q] = v.z * 0.125f;
        Qst[(d4 + 3) * QST + q] = v.w * 0.125f;
    }

    const float* Kbase = Kp + (size_t)(b * TT) * kvstride + h * DD;
    const float* Vbase = Vp + (size_t)(b * TT) * kvstride + h * DD;

    float o[8][4], m[8], l[8];
    #pragma unroll
    for (int i = 0; i < 8; i++) {
        m[i] = -1e30f; l[i] = 0.f;
        #pragma unroll
        for (int j = 0; j < 4; j++) o[i][j] = 0.f;
    }

    const int nkt = CAUSAL ? (2 * qt + 2) : (TT / KT);

    for (int kt = 0; kt < nkt; kt++) {
        __syncthreads();   // protect Kst/Vs/Pt overwrite vs previous reads (+Q first iter)

        // load K (transposed) and V (row-major) tiles
        const int kbase = kt * KT;
        #pragma unroll
        for (int i = 0; i < 4; i++) {
            const int lin = tid + i * 256;    // 0..1023
            const int tok = lin >> 4;         // 0..63
            const int d4 = (lin & 15) << 2;
            float4 kv = *(const float4*)(Kbase + (size_t)(kbase + tok) * kvstride + d4);
            float4 vv = *(const float4*)(Vbase + (size_t)(kbase + tok) * kvstride + d4);
            Kst[(d4 + 0) * KST + tok] = kv.x;
            Kst[(d4 + 1) * KST + tok] = kv.y;
            Kst[(d4 + 2) * KST + tok] = kv.z;
            Kst[(d4 + 3) * KST + tok] = kv.w;
            Vs[tok * KST + d4 + 0] = vv.x;
            Vs[tok * KST + d4 + 1] = vv.y;
            Vs[tok * KST + d4 + 2] = vv.z;
            Vs[tok * KST + d4 + 3] = vv.w;
        }
        __syncthreads();

        // GEMM1: s[i][j] = sum_d Q[q][d] * K[k][d]
        float s[8][4];
        #pragma unroll
        for (int i = 0; i < 8; i++)
            #pragma unroll
            for (int j = 0; j < 4; j++) s[i][j] = 0.f;

        for (int d = 0; d < DD; d++) {
            float a[8], bb[4];
            #pragma unroll
            for (int i = 0; i < 8; i++) a[i] = Qst[d * QST + ty + 16 * i];
            #pragma unroll
            for (int j = 0; j < 4; j++) bb[j] = Kst[d * KST + tx + 16 * j];
            #pragma unroll
            for (int i = 0; i < 8; i++)
                #pragma unroll
                for (int j = 0; j < 4; j++)
                    s[i][j] = fmaf(a[i], bb[j], s[i][j]);
        }

        // causal mask (only tiles that touch the diagonal)
        if (CAUSAL && kbase + KT - 1 > qbase) {
            #pragma unroll
            for (int i = 0; i < 8; i++) {
                const int qg = qbase + ty + 16 * i;
                #pragma unroll
                for (int j = 0; j < 4; j++) {
                    const int kg = kbase + tx + 16 * j;
                    if (kg > qg) s[i][j] = -1e30f;
                }
            }
        }

        // online softmax + write P^T
        #pragma unroll
        for (int i = 0; i < 8; i++) {
            float rm = s[i][0];
            #pragma unroll
            for (int j = 1; j < 4; j++) rm = fmaxf(rm, s[i][j]);
            #pragma unroll
            for (int off = 8; off; off >>= 1)
                rm = fmaxf(rm, __shfl_xor_sync(0xffffffffu, rm, off));
            const float mn = fmaxf(m[i], rm);
            const float corr = __expf(m[i] - mn);
            m[i] = mn;
            float rs = 0.f;
            #pragma unroll
            for (int j = 0; j < 4; j++) {
                const float p = __expf(s[i][j] - mn);
                s[i][j] = p;
                rs += p;
            }
            #pragma unroll
            for (int off = 8; off; off >>= 1)
                rs += __shfl_xor_sync(0xffffffffu, rs, off);
            l[i] = l[i] * corr + rs;
            #pragma unroll
            for (int j = 0; j < 4; j++) o[i][j] *= corr;
            #pragma unroll
            for (int j = 0; j < 4; j++)
                Pt[(tx + 16 * j) * QST + ty + 16 * i] = s[i][j];
        }
        __syncthreads();

        // GEMM2: o[i][j] += sum_k P[q][k] * V[k][dc]
        for (int k = 0; k < KT; k++) {
            float a[8], bb[4];
            #pragma unroll
            for (int i = 0; i < 8; i++) a[i] = Pt[k * QST + ty + 16 * i];
            #pragma unroll
            for (int j = 0; j < 4; j++) bb[j] = Vs[k * KST + tx + 16 * j];
            #pragma unroll
            for (int i = 0; i < 8; i++)
                #pragma unroll
                for (int j = 0; j < 4; j++)
                    o[i][j] = fmaf(a[i], bb[j], o[i][j]);
        }
    }

    // normalize and store
    #pragma unroll
    for (int i = 0; i < 8; i++) {
        const float inv = 1.f / l[i];
        const int qg = qbase + ty + 16 * i;
        float* orow = O + (size_t)(b * TT + qg) * CC + h * DD;
        #pragma unroll
        for (int j = 0; j < 4; j++)
            orow[tx + 16 * j] = o[i][j] * inv;
    }
}

// ---------------- LayerNorm (one block per row of 768) ----------------------
__global__ __launch_bounds__(256)
void layernorm_k(const float* __restrict__ in, const float* __restrict__ g,
                 const float* __restrict__ b, float* __restrict__ out)
{
    const int row = blockIdx.x;
    const int tid = threadIdx.x;
    const float* x = in + (size_t)row * CC;

    const float v0 = x[tid], v1 = x[tid + 256], v2 = x[tid + 512];
    float s = v0 + v1 + v2;
    float sq = v0 * v0 + v1 * v1 + v2 * v2;

    #pragma unroll
    for (int off = 16; off; off >>= 1) {
        s  += __shfl_xor_sync(0xffffffffu, s, off);
        sq += __shfl_xor_sync(0xffffffffu, sq, off);
    }
    __shared__ float red[16];
    const int wid = tid >> 5, lane = tid & 31;
    if (lane == 0) { red[wid] = s; red[wid + 8] = sq; }
    __syncthreads();

    float ts = 0.f, tq = 0.f;
    #pragma unroll
    for (int i = 0; i < 8; i++) { ts += red[i]; tq += red[i + 8]; }

    const float mu = ts * (1.f / CC);
    const float var = tq * (1.f / CC) - mu * mu;
    const float rstd = rsqrtf(var + 1e-5f);

    float* orow = out + (size_t)row * CC;
    orow[tid]       = (v0 - mu) * rstd * g[tid]       + b[tid];
    orow[tid + 256] = (v1 - mu) * rstd * g[tid + 256] + b[tid + 256];
    orow[tid + 512] = (v2 - mu) * rstd * g[tid + 512] + b[tid + 512];
}

// ---------------- launch ----------------------------------------------------
extern "C" void kernel_launch(void* const* d_in, const int* in_sizes, int n_in,
                              void* d_out, int out_size)
{
    const float* x      = (const float*)d_in[0];
    const float* enc    = (const float*)d_in[1];
    const float* ln1_g  = (const float*)d_in[2];
    const float* ln1_b  = (const float*)d_in[3];
    const float* qkv_w  = (const float*)d_in[4];
    const float* qkv_b  = (const float*)d_in[5];
    const float* proj_w = (const float*)d_in[6];
    const float* proj_b = (const float*)d_in[7];
    const float* ln2_g  = (const float*)d_in[8];
    const float* ln2_b  = (const float*)d_in[9];
    const float* caq_w  = (const float*)d_in[10];
    const float* caq_b  = (const float*)d_in[11];
    const float* cak_w  = (const float*)d_in[12];
    const float* cak_b  = (const float*)d_in[13];
    const float* cav_w  = (const float*)d_in[14];
    const float* cav_b  = (const float*)d_in[15];
    const float* cao_w  = (const float*)d_in[16];
    const float* cao_b  = (const float*)d_in[17];
    const float* ln3_g  = (const float*)d_in[18];
    const float* ln3_b  = (const float*)d_in[19];
    const float* fc_w   = (const float*)d_in[20];
    const float* fc_b   = (const float*)d_in[21];
    const float* fc2_w  = (const float*)d_in[22];
    const float* fc2_b  = (const float*)d_in[23];
    float* out = (float*)d_out;

    float *qkv, *att, *res, *x1, *cq, *ck, *cv, *x2, *hbuf;
    cudaGetSymbolAddress((void**)&qkv,  g_qkv);
    cudaGetSymbolAddress((void**)&att,  g_att);
    cudaGetSymbolAddress((void**)&res,  g_res);
    cudaGetSymbolAddress((void**)&x1,   g_x1);
    cudaGetSymbolAddress((void**)&cq,   g_cq);
    cudaGetSymbolAddress((void**)&ck,   g_ck);
    cudaGetSymbolAddress((void**)&cv,   g_cv);
    cudaGetSymbolAddress((void**)&x2,   g_x2);
    cudaGetSymbolAddress((void**)&hbuf, g_h);

    const int attn_smem = SM_TOT * sizeof(float);   // 99328 B
    cudaFuncSetAttribute(attn_tiled<true>,
                         cudaFuncAttributeMaxDynamicSharedMemorySize, attn_smem);
    cudaFuncSetAttribute(attn_tiled<false>,
                         cudaFuncAttributeMaxDynamicSharedMemorySize, attn_smem);

    const dim3 thr(256);
    const dim3 g768(CC / 128, MROWS / 128);          // (6, 32)
    const dim3 gqkv(3 * CC / 128, MROWS / 128);      // (18, 32)
    const dim3 gfc(4 * CC / 128, MROWS / 128);       // (24, 32)
    const dim3 gattn(TT / QT, HH, BB);               // (16, 12, 2)

    // 1) qkv = x @ W_qkv + b
    sgemm_bias<EPI_NONE><<<gqkv, thr>>>(x, qkv_w, qkv_b, nullptr, qkv,
                                        MROWS, 3 * CC, CC);
    // 2) causal self-attention (q/k/v are column slices of qkv, stride 2304)
    attn_tiled<true><<<gattn, thr, attn_smem>>>(qkv, qkv + CC, qkv + 2 * CC, att,
                                                3 * CC, 3 * CC);
    // 3) sa @ proj + b + x  -> res ; LN1 -> x1
    sgemm_bias<EPI_RES><<<g768, thr>>>(att, proj_w, proj_b, x, res,
                                       MROWS, CC, CC);
    layernorm_k<<<MROWS, thr>>>(res, ln1_g, ln1_b, x1);
    // 4) cross-attn projections
    sgemm_bias<EPI_NONE><<<g768, thr>>>(x1,  caq_w, caq_b, nullptr, cq, MROWS, CC, CC);
    sgemm_bias<EPI_NONE><<<g768, thr>>>(enc, cak_w, cak_b, nullptr, ck, MROWS, CC, CC);
    sgemm_bias<EPI_NONE><<<g768, thr>>>(enc, cav_w, cav_b, nullptr, cv, MROWS, CC, CC);
    // 5) cross attention (non-causal)
    attn_tiled<false><<<gattn, thr, attn_smem>>>(cq, ck, cv, att, CC, CC);
    // 6) ca @ o_w + b + x1 -> res ; LN2 -> x2
    sgemm_bias<EPI_RES><<<g768, thr>>>(att, cao_w, cao_b, x1, res,
                                       MROWS, CC, CC);
    layernorm_k<<<MROWS, thr>>>(res, ln2_g, ln2_b, x2);
    // 7) MLP
    sgemm_bias<EPI_RELU><<<gfc, thr>>>(x2, fc_w, fc_b, nullptr, hbuf,
                                       MROWS, 4 * CC, CC);
    sgemm_bias<EPI_RES><<<g768, thr>>>(hbuf, fc2_w, fc2_b, x2, res,
                                       MROWS, CC, 4 * CC);
    // 8) LN3 -> out
    layernorm_k<<<MROWS, thr>>>(res, ln3_g, ln3_b, out);
}

// round 3
// speedup vs baseline: 3.6055x; 1.7877x over previous
#include <cuda_runtime.h>
#include <math.h>
#include <stdint.h>

// Problem constants
#define BB 2
#define TT 2048
#define CC 768
#define HH 12
#define DD 64
#define MROWS (BB*TT)   // 4096

// ---------------- scratch (device globals; no allocations allowed) ----------
__device__ float g_qkv[(size_t)MROWS * 3 * CC];  // 4096 x 2304
__device__ float g_att[(size_t)MROWS * CC];
__device__ float g_res[(size_t)MROWS * CC];
__device__ float g_x1 [(size_t)MROWS * CC];
__device__ float g_cq [(size_t)MROWS * CC];
__device__ float g_ck [(size_t)MROWS * CC];
__device__ float g_cv [(size_t)MROWS * CC];
__device__ float g_x2 [(size_t)MROWS * CC];
__device__ float g_h  [(size_t)MROWS * 4 * CC];  // 4096 x 3072

enum { EPI_NONE = 0, EPI_RELU = 1, EPI_RES = 2 };

// ---------------- tf32 tensor-core GEMM, 128x128x32, cp.async 2-stage -------
// Warp tile 64x32 (warps 2x4), mma.m16n8k8.tf32, fragments 4(m) x 4(n).
// SMEM: A [m][k] stride 36 (LDS bank = 4r+q, conflict-free),
//       B [k][n] stride 132 (LDS bank = 4q+r, conflict-free).
#define ASTR 36
#define BSTR 132
#define ABUF (128*ASTR)          // 4608 floats
#define GBUFSZ (ABUF + 32*BSTR)  // 4608 + 4224 = 8832 floats per stage
#define GSMEM (2*GBUFSZ*4)       // 70656 bytes

__device__ __forceinline__ void cp16(uint32_t s, const void* g) {
    asm volatile("cp.async.cg.shared.global [%0], [%1], 16;" :: "r"(s), "l"(g));
}

__device__ __forceinline__ void mma_tf32(float* d, const uint32_t* a,
                                         const uint32_t* b) {
    asm volatile(
        "mma.sync.aligned.m16n8k8.row.col.f32.tf32.tf32.f32 "
        "{%0,%1,%2,%3}, {%4,%5,%6,%7}, {%8,%9}, {%0,%1,%2,%3};\n"
        : "+f"(d[0]), "+f"(d[1]), "+f"(d[2]), "+f"(d[3])
        : "r"(a[0]), "r"(a[1]), "r"(a[2]), "r"(a[3]), "r"(b[0]), "r"(b[1]));
}

template<int EPI>
__global__ __launch_bounds__(256, 2)
void tgemm_bias(const float* __restrict__ A, const float* __restrict__ Bm,
                const float* __restrict__ bias, const float* __restrict__ res,
                float* __restrict__ Cm, int M, int N, int K)
{
    extern __shared__ float sm[];
    const int tid = threadIdx.x;
    const int lane = tid & 31, warp = tid >> 5;
    const int wm = warp >> 2, wn = warp & 3;       // warp grid 2(m) x 4(n)
    const int r = lane >> 2, q = lane & 3;
    const int mBase = blockIdx.y * 128, nBase = blockIdx.x * 128;

    const uint32_t smemBase = (uint32_t)__cvta_generic_to_shared(sm);

    float acc[4][4][4];
    #pragma unroll
    for (int mt = 0; mt < 4; mt++)
        #pragma unroll
        for (int nt = 0; nt < 4; nt++)
            #pragma unroll
            for (int e = 0; e < 4; e++) acc[mt][nt][e] = 0.f;

    const int nchunk = K >> 5;

    auto issue = [&](int c) {
        const int kc = c << 5;
        const uint32_t sb = smemBase + (uint32_t)((c & 1) * GBUFSZ * 4);
        #pragma unroll
        for (int i = 0; i < 4; i++) {                 // A tile 128x32
            const int fid = tid + (i << 8);
            const int row = fid >> 3, k4 = (fid & 7) << 2;
            cp16(sb + (uint32_t)((row * ASTR + k4) * 4),
                 A + (size_t)(mBase + row) * K + kc + k4);
        }
        #pragma unroll
        for (int i = 0; i < 4; i++) {                 // B tile 32x128
            const int fid = tid + (i << 8);
            const int kr = fid >> 5, n4 = (fid & 31) << 2;
            cp16(sb + (uint32_t)((ABUF + kr * BSTR + n4) * 4),
                 Bm + (size_t)(kc + kr) * N + nBase + n4);
        }
        asm volatile("cp.async.commit_group;");
    };

    issue(0);

    for (int c = 0; c < nchunk; c++) {
        if (c + 1 < nchunk) {
            issue(c + 1);
            asm volatile("cp.async.wait_group 1;");
        } else {
            asm volatile("cp.async.wait_group 0;");
        }
        __syncthreads();

        const uint32_t* AsU = (const uint32_t*)sm + (c & 1) * GBUFSZ;
        const uint32_t* BsU = AsU + ABUF;

        #pragma unroll
        for (int ks = 0; ks < 4; ks++) {
            uint32_t af[4][4], bf[4][2];
            #pragma unroll
            for (int mt = 0; mt < 4; mt++) {
                const int base = (wm * 64 + mt * 16 + r) * ASTR + ks * 8 + q;
                af[mt][0] = AsU[base];
                af[mt][1] = AsU[base + 8 * ASTR];
                af[mt][2] = AsU[base + 4];
                af[mt][3] = AsU[base + 8 * ASTR + 4];
            }
            #pragma unroll
            for (int nt = 0; nt < 4; nt++) {
                const int base = (ks * 8 + q) * BSTR + wn * 32 + nt * 8 + r;
                bf[nt][0] = BsU[base];
                bf[nt][1] = BsU[base + 4 * BSTR];
            }
            #pragma unroll
            for (int mt = 0; mt < 4; mt++)
                #pragma unroll
                for (int nt = 0; nt < 4; nt++)
                    mma_tf32(acc[mt][nt], af[mt], bf[nt]);
        }
        __syncthreads();
    }

    // epilogue: c0,c1 at (row, 2q..2q+1), c2,c3 at (row+8, ...)
    #pragma unroll
    for (int mt = 0; mt < 4; mt++) {
        const int row0 = mBase + wm * 64 + mt * 16 + r;
        #pragma unroll
        for (int nt = 0; nt < 4; nt++) {
            const int col = nBase + wn * 32 + nt * 8 + 2 * q;
            const float2 bv = *(const float2*)(bias + col);
            float2 v0 = make_float2(acc[mt][nt][0] + bv.x, acc[mt][nt][1] + bv.y);
            float2 v1 = make_float2(acc[mt][nt][2] + bv.x, acc[mt][nt][3] + bv.y);
            if (EPI == EPI_RELU) {
                v0.x = fmaxf(v0.x, 0.f); v0.y = fmaxf(v0.y, 0.f);
                v1.x = fmaxf(v1.x, 0.f); v1.y = fmaxf(v1.y, 0.f);
            }
            if (EPI == EPI_RES) {
                const float2 r0 = *(const float2*)(res + (size_t)row0 * N + col);
                const float2 r1 = *(const float2*)(res + (size_t)(row0 + 8) * N + col);
                v0.x += r0.x; v0.y += r0.y;
                v1.x += r1.x; v1.y += r1.y;
            }
            *(float2*)(Cm + (size_t)row0 * N + col) = v0;
            *(float2*)(Cm + (size_t)(row0 + 8) * N + col) = v1;
        }
    }
}

// ---------------- tiled flash attention (fp32 SIMT, unchanged from R2) ------
#define QT 128
#define KT 64
#define QST 129
#define KST 65

#define SM_QST 0
#define SM_KST (64*QST)
#define SM_VS  (SM_KST + 64*KST)
#define SM_PT  (SM_VS  + 64*KST)
#define SM_TOT (SM_PT  + 64*QST)

template<bool CAUSAL>
__global__ __launch_bounds__(256, 2)
void attn_tiled(const float* __restrict__ Q, const float* __restrict__ Kp,
                const float* __restrict__ Vp, float* __restrict__ O,
                int qstride, int kvstride)
{
    extern __shared__ float sm[];
    float* Qst = sm + SM_QST;
    float* Kst = sm + SM_KST;
    float* Vs  = sm + SM_VS;
    float* Pt  = sm + SM_PT;

    const int b = blockIdx.z, h = blockIdx.y, qt = blockIdx.x;
    const int tid = threadIdx.x;
    const int tx = tid & 15, ty = tid >> 4;
    const int qbase = qt * QT;

    const float* Qbase = Q + (size_t)(b * TT + qbase) * qstride + h * DD;
    #pragma unroll
    for (int i = 0; i < 8; i++) {
        const int lin = tid + i * 256;
        const int qq = lin >> 4;
        const int d4 = (lin & 15) << 2;
        float4 v = *(const float4*)(Qbase + (size_t)qq * qstride + d4);
        Qst[(d4 + 0) * QST + qq] = v.x * 0.125f;
        Qst[(d4 + 1) * QST + qq] = v.y * 0.125f;
        Qst[(d4 + 2) * QST + qq] = v.z * 0.125f;
        Qst[(d4 + 3) * QST + qq] = v.w * 0.125f;
    }

    const float* Kbase = Kp + (size_t)(b * TT) * kvstride + h * DD;
    const float* Vbase = Vp + (size_t)(b * TT) * kvstride + h * DD;

    float o[8][4], m[8], l[8];
    #pragma unroll
    for (int i = 0; i < 8; i++) {
        m[i] = -1e30f; l[i] = 0.f;
        #pragma unroll
        for (int j = 0; j < 4; j++) o[i][j] = 0.f;
    }

    const int nkt = CAUSAL ? (2 * qt + 2) : (TT / KT);

    for (int kt = 0; kt < nkt; kt++) {
        __syncthreads();
        const int kbase = kt * KT;
        #pragma unroll
        for (int i = 0; i < 4; i++) {
            const int lin = tid + i * 256;
            const int tok = lin >> 4;
            const int d4 = (lin & 15) << 2;
            float4 kv = *(const float4*)(Kbase + (size_t)(kbase + tok) * kvstride + d4);
            float4 vv = *(const float4*)(Vbase + (size_t)(kbase + tok) * kvstride + d4);
            Kst[(d4 + 0) * KST + tok] = kv.x;
            Kst[(d4 + 1) * KST + tok] = kv.y;
            Kst[(d4 + 2) * KST + tok] = kv.z;
            Kst[(d4 + 3) * KST + tok] = kv.w;
            Vs[tok * KST + d4 + 0] = vv.x;
            Vs[tok * KST + d4 + 1] = vv.y;
            Vs[tok * KST + d4 + 2] = vv.z;
            Vs[tok * KST + d4 + 3] = vv.w;
        }
        __syncthreads();

        float s[8][4];
        #pragma unroll
        for (int i = 0; i < 8; i++)
            #pragma unroll
            for (int j = 0; j < 4; j++) s[i][j] = 0.f;

        for (int d = 0; d < DD; d++) {
            float a[8], bb[4];
            #pragma unroll
            for (int i = 0; i < 8; i++) a[i] = Qst[d * QST + ty + 16 * i];
            #pragma unroll
            for (int j = 0; j < 4; j++) bb[j] = Kst[d * KST + tx + 16 * j];
            #pragma unroll
            for (int i = 0; i < 8; i++)
                #pragma unroll
                for (int j = 0; j < 4; j++)
                    s[i][j] = fmaf(a[i], bb[j], s[i][j]);
        }

        if (CAUSAL && kbase + KT - 1 > qbase) {
            #pragma unroll
            for (int i = 0; i < 8; i++) {
                const int qg = qbase + ty + 16 * i;
                #pragma unroll
                for (int j = 0; j < 4; j++) {
                    const int kg = kbase + tx + 16 * j;
                    if (kg > qg) s[i][j] = -1e30f;
                }
            }
        }

        #pragma unroll
        for (int i = 0; i < 8; i++) {
            float rm = s[i][0];
            #pragma unroll
            for (int j = 1; j < 4; j++) rm = fmaxf(rm, s[i][j]);
            #pragma unroll
            for (int off = 8; off; off >>= 1)
                rm = fmaxf(rm, __shfl_xor_sync(0xffffffffu, rm, off));
            const float mn = fmaxf(m[i], rm);
            const float corr = __expf(m[i] - mn);
            m[i] = mn;
            float rs = 0.f;
            #pragma unroll
            for (int j = 0; j < 4; j++) {
                const float p = __expf(s[i][j] - mn);
                s[i][j] = p;
                rs += p;
            }
            #pragma unroll
            for (int off = 8; off; off >>= 1)
                rs += __shfl_xor_sync(0xffffffffu, rs, off);
            l[i] = l[i] * corr + rs;
            #pragma unroll
            for (int j = 0; j < 4; j++) o[i][j] *= corr;
            #pragma unroll
            for (int j = 0; j < 4; j++)
                Pt[(tx + 16 * j) * QST + ty + 16 * i] = s[i][j];
        }
        __syncthreads();

        for (int k = 0; k < KT; k++) {
            float a[8], bb[4];
            #pragma unroll
            for (int i = 0; i < 8; i++) a[i] = Pt[k * QST + ty + 16 * i];
            #pragma unroll
            for (int j = 0; j < 4; j++) bb[j] = Vs[k * KST + tx + 16 * j];
            #pragma unroll
            for (int i = 0; i < 8; i++)
                #pragma unroll
                for (int j = 0; j < 4; j++)
                    o[i][j] = fmaf(a[i], bb[j], o[i][j]);
        }
    }

    #pragma unroll
    for (int i = 0; i < 8; i++) {
        const float inv = 1.f / l[i];
        const int qg = qbase + ty + 16 * i;
        float* orow = O + (size_t)(b * TT + qg) * CC + h * DD;
        #pragma unroll
        for (int j = 0; j < 4; j++)
            orow[tx + 16 * j] = o[i][j] * inv;
    }
}

// ---------------- LayerNorm (one block per row of 768) ----------------------
__global__ __launch_bounds__(256)
void layernorm_k(const float* __restrict__ in, const float* __restrict__ g,
                 const float* __restrict__ b, float* __restrict__ out)
{
    const int row = blockIdx.x;
    const int tid = threadIdx.x;
    const float* x = in + (size_t)row * CC;

    const float v0 = x[tid], v1 = x[tid + 256], v2 = x[tid + 512];
    float s = v0 + v1 + v2;
    float sq = v0 * v0 + v1 * v1 + v2 * v2;

    #pragma unroll
    for (int off = 16; off; off >>= 1) {
        s  += __shfl_xor_sync(0xffffffffu, s, off);
        sq += __shfl_xor_sync(0xffffffffu, sq, off);
    }
    __shared__ float red[16];
    const int wid = tid >> 5, lane = tid & 31;
    if (lane == 0) { red[wid] = s; red[wid + 8] = sq; }
    __syncthreads();

    float ts = 0.f, tq = 0.f;
    #pragma unroll
    for (int i = 0; i < 8; i++) { ts += red[i]; tq += red[i + 8]; }

    const float mu = ts * (1.f / CC);
    const float var = tq * (1.f / CC) - mu * mu;
    const float rstd = rsqrtf(var + 1e-5f);

    float* orow = out + (size_t)row * CC;
    orow[tid]       = (v0 - mu) * rstd * g[tid]       + b[tid];
    orow[tid + 256] = (v1 - mu) * rstd * g[tid + 256] + b[tid + 256];
    orow[tid + 512] = (v2 - mu) * rstd * g[tid + 512] + b[tid + 512];
}

// ---------------- launch ----------------------------------------------------
extern "C" void kernel_launch(void* const* d_in, const int* in_sizes, int n_in,
                              void* d_out, int out_size)
{
    const float* x      = (const float*)d_in[0];
    const float* enc    = (const float*)d_in[1];
    const float* ln1_g  = (const float*)d_in[2];
    const float* ln1_b  = (const float*)d_in[3];
    const float* qkv_w  = (const float*)d_in[4];
    const float* qkv_b  = (const float*)d_in[5];
    const float* proj_w = (const float*)d_in[6];
    const float* proj_b = (const float*)d_in[7];
    const float* ln2_g  = (const float*)d_in[8];
    const float* ln2_b  = (const float*)d_in[9];
    const float* caq_w  = (const float*)d_in[10];
    const float* caq_b  = (const float*)d_in[11];
    const float* cak_w  = (const float*)d_in[12];
    const float* cak_b  = (const float*)d_in[13];
    const float* cav_w  = (const float*)d_in[14];
    const float* cav_b  = (const float*)d_in[15];
    const float* cao_w  = (const float*)d_in[16];
    const float* cao_b  = (const float*)d_in[17];
    const float* ln3_g  = (const float*)d_in[18];
    const float* ln3_b  = (const float*)d_in[19];
    const float* fc_w   = (const float*)d_in[20];
    const float* fc_b   = (const float*)d_in[21];
    const float* fc2_w  = (const float*)d_in[22];
    const float* fc2_b  = (const float*)d_in[23];
    float* out = (float*)d_out;

    float *qkv, *att, *res, *x1, *cq, *ck, *cv, *x2, *hbuf;
    cudaGetSymbolAddress((void**)&qkv,  g_qkv);
    cudaGetSymbolAddress((void**)&att,  g_att);
    cudaGetSymbolAddress((void**)&res,  g_res);
    cudaGetSymbolAddress((void**)&x1,   g_x1);
    cudaGetSymbolAddress((void**)&cq,   g_cq);
    cudaGetSymbolAddress((void**)&ck,   g_ck);
    cudaGetSymbolAddress((void**)&cv,   g_cv);
    cudaGetSymbolAddress((void**)&x2,   g_x2);
    cudaGetSymbolAddress((void**)&hbuf, g_h);

    const int attn_smem = SM_TOT * sizeof(float);
    cudaFuncSetAttribute(attn_tiled<true>,
                         cudaFuncAttributeMaxDynamicSharedMemorySize, attn_smem);
    cudaFuncSetAttribute(attn_tiled<false>,
                         cudaFuncAttributeMaxDynamicSharedMemorySize, attn_smem);
    cudaFuncSetAttribute(tgemm_bias<EPI_NONE>,
                         cudaFuncAttributeMaxDynamicSharedMemorySize, GSMEM);
    cudaFuncSetAttribute(tgemm_bias<EPI_RELU>,
                         cudaFuncAttributeMaxDynamicSharedMemorySize, GSMEM);
    cudaFuncSetAttribute(tgemm_bias<EPI_RES>,
                         cudaFuncAttributeMaxDynamicSharedMemorySize, GSMEM);

    const dim3 thr(256);
    const dim3 g768(CC / 128, MROWS / 128);          // (6, 32)
    const dim3 gqkv(3 * CC / 128, MROWS / 128);      // (18, 32)
    const dim3 gfc(4 * CC / 128, MROWS / 128);       // (24, 32)
    const dim3 gattn(TT / QT, HH, BB);               // (16, 12, 2)

    // 1) qkv = x @ W_qkv + b
    tgemm_bias<EPI_NONE><<<gqkv, thr, GSMEM>>>(x, qkv_w, qkv_b, nullptr, qkv,
                                               MROWS, 3 * CC, CC);
    // 2) causal self-attention
    attn_tiled<true><<<gattn, thr, attn_smem>>>(qkv, qkv + CC, qkv + 2 * CC, att,
                                                3 * CC, 3 * CC);
    // 3) sa @ proj + b + x -> res ; LN1 -> x1
    tgemm_bias<EPI_RES><<<g768, thr, GSMEM>>>(att, proj_w, proj_b, x, res,
                                              MROWS, CC, CC);
    layernorm_k<<<MROWS, thr>>>(res, ln1_g, ln1_b, x1);
    // 4) cross-attn projections
    tgemm_bias<EPI_NONE><<<g768, thr, GSMEM>>>(x1,  caq_w, caq_b, nullptr, cq, MROWS, CC, CC);
    tgemm_bias<EPI_NONE><<<g768, thr, GSMEM>>>(enc, cak_w, cak_b, nullptr, ck, MROWS, CC, CC);
    tgemm_bias<EPI_NONE><<<g768, thr, GSMEM>>>(enc, cav_w, cav_b, nullptr, cv, MROWS, CC, CC);
    // 5) cross attention
    attn_tiled<false><<<gattn, thr, attn_smem>>>(cq, ck, cv, att, CC, CC);
    // 6) ca @ o_w + b + x1 -> res ; LN2 -> x2
    tgemm_bias<EPI_RES><<<g768, thr, GSMEM>>>(att, cao_w, cao_b, x1, res,
                                              MROWS, CC, CC);
    layernorm_k<<<MROWS, thr>>>(res, ln2_g, ln2_b, x2);
    // 7) MLP
    tgemm_bias<EPI_RELU><<<gfc, thr, GSMEM>>>(x2, fc_w, fc_b, nullptr, hbuf,
                                              MROWS, 4 * CC, CC);
    tgemm_bias<EPI_RES><<<g768, thr, GSMEM>>>(hbuf, fc2_w, fc2_b, x2, res,
                                              MROWS, CC, 4 * CC);
    // 8) LN3 -> out
    layernorm_k<<<MROWS, thr>>>(res, ln3_g, ln3_b, out);
}

// round 4
// speedup vs baseline: 6.4679x; 1.7939x over previous
#include <cuda_runtime.h>
#include <math.h>
#include <stdint.h>

#define BB 2
#define TT 2048
#define CC 768
#define HH 12
#define DD 64
#define MROWS (BB*TT)   // 4096

// ---------------- scratch ----------------------------------------------------
__device__ float g_qkv[(size_t)MROWS * 3 * CC];
__device__ float g_att[(size_t)MROWS * CC];
__device__ float g_res[(size_t)MROWS * CC];
__device__ float g_x1 [(size_t)MROWS * CC];
__device__ float g_cq [(size_t)MROWS * CC];
__device__ float g_ck [(size_t)MROWS * CC];
__device__ float g_cv [(size_t)MROWS * CC];
__device__ float g_x2 [(size_t)MROWS * CC];
__device__ float g_h  [(size_t)MROWS * 4 * CC];

enum { EPI_NONE = 0, EPI_RELU = 1, EPI_RES = 2 };

__device__ __forceinline__ void cp16(uint32_t s, const void* g) {
    asm volatile("cp.async.cg.shared.global [%0], [%1], 16;" :: "r"(s), "l"(g));
}
__device__ __forceinline__ uint32_t f2tf(float x) {
    uint32_t r;
    asm("cvt.rna.tf32.f32 %0, %1;" : "=r"(r) : "f"(x));
    return r;
}
__device__ __forceinline__ void mma_tf32(float* d, const uint32_t* a,
                                         const uint32_t* b) {
    asm volatile(
        "mma.sync.aligned.m16n8k8.row.col.f32.tf32.tf32.f32 "
        "{%0,%1,%2,%3}, {%4,%5,%6,%7}, {%8,%9}, {%0,%1,%2,%3};\n"
        : "+f"(d[0]), "+f"(d[1]), "+f"(d[2]), "+f"(d[3])
        : "r"(a[0]), "r"(a[1]), "r"(a[2]), "r"(a[3]), "r"(b[0]), "r"(b[1]));
}

// ---------------- tf32 GEMM 128x128x32, cp.async 2-stage, RNA-rounded -------
#define ASTR 36
#define BSTR 132
#define ABUF (128*ASTR)
#define GBUFSZ (ABUF + 32*BSTR)   // 8832 floats/stage
#define GSMEM (2*GBUFSZ*4)

template<int EPI>
__device__ __forceinline__
void tgemm_body(float* sm, const float* __restrict__ A,
                const float* __restrict__ Bm, const float* __restrict__ bias,
                const float* __restrict__ res, float* __restrict__ Cm,
                int M, int N, int K, int mBase, int nBase)
{
    const int tid = threadIdx.x;
    const int lane = tid & 31, warp = tid >> 5;
    const int wm = warp >> 2, wn = warp & 3;
    const int r = lane >> 2, q = lane & 3;
    const uint32_t smemBase = (uint32_t)__cvta_generic_to_shared(sm);

    float acc[4][4][4];
    #pragma unroll
    for (int mt = 0; mt < 4; mt++)
        #pragma unroll
        for (int nt = 0; nt < 4; nt++)
            #pragma unroll
            for (int e = 0; e < 4; e++) acc[mt][nt][e] = 0.f;

    const int nchunk = K >> 5;

    auto issue = [&](int c) {
        const int kc = c << 5;
        const uint32_t sb = smemBase + (uint32_t)((c & 1) * GBUFSZ * 4);
        #pragma unroll
        for (int i = 0; i < 4; i++) {
            const int fid = tid + (i << 8);
            const int row = fid >> 3, k4 = (fid & 7) << 2;
            cp16(sb + (uint32_t)((row * ASTR + k4) * 4),
                 A + (size_t)(mBase + row) * K + kc + k4);
        }
        #pragma unroll
        for (int i = 0; i < 4; i++) {
            const int fid = tid + (i << 8);
            const int kr = fid >> 5, n4 = (fid & 31) << 2;
            cp16(sb + (uint32_t)((ABUF + kr * BSTR + n4) * 4),
                 Bm + (size_t)(kc + kr) * N + nBase + n4);
        }
        asm volatile("cp.async.commit_group;");
    };

    issue(0);

    for (int c = 0; c < nchunk; c++) {
        if (c + 1 < nchunk) {
            issue(c + 1);
            asm volatile("cp.async.wait_group 1;");
        } else {
            asm volatile("cp.async.wait_group 0;");
        }
        __syncthreads();

        const float* As = sm + (c & 1) * GBUFSZ;
        const float* Bs = As + ABUF;

        #pragma unroll
        for (int ks = 0; ks < 4; ks++) {
            uint32_t af[4][4], bf[4][2];
            #pragma unroll
            for (int mt = 0; mt < 4; mt++) {
                const int base = (wm * 64 + mt * 16 + r) * ASTR + ks * 8 + q;
                af[mt][0] = f2tf(As[base]);
                af[mt][1] = f2tf(As[base + 8 * ASTR]);
                af[mt][2] = f2tf(As[base + 4]);
                af[mt][3] = f2tf(As[base + 8 * ASTR + 4]);
            }
            #pragma unroll
            for (int nt = 0; nt < 4; nt++) {
                const int base = (ks * 8 + q) * BSTR + wn * 32 + nt * 8 + r;
                bf[nt][0] = f2tf(Bs[base]);
                bf[nt][1] = f2tf(Bs[base + 4 * BSTR]);
            }
            #pragma unroll
            for (int mt = 0; mt < 4; mt++)
                #pragma unroll
                for (int nt = 0; nt < 4; nt++)
                    mma_tf32(acc[mt][nt], af[mt], bf[nt]);
        }
        __syncthreads();
    }

    #pragma unroll
    for (int mt = 0; mt < 4; mt++) {
        const int row0 = mBase + wm * 64 + mt * 16 + r;
        #pragma unroll
        for (int nt = 0; nt < 4; nt++) {
            const int col = nBase + wn * 32 + nt * 8 + 2 * q;
            const float2 bv = *(const float2*)(bias + col);
            float2 v0 = make_float2(acc[mt][nt][0] + bv.x, acc[mt][nt][1] + bv.y);
            float2 v1 = make_float2(acc[mt][nt][2] + bv.x, acc[mt][nt][3] + bv.y);
            if (EPI == EPI_RELU) {
                v0.x = fmaxf(v0.x, 0.f); v0.y = fmaxf(v0.y, 0.f);
                v1.x = fmaxf(v1.x, 0.f); v1.y = fmaxf(v1.y, 0.f);
            }
            if (EPI == EPI_RES) {
                const float2 r0 = *(const float2*)(res + (size_t)row0 * N + col);
                const float2 r1 = *(const float2*)(res + (size_t)(row0 + 8) * N + col);
                v0.x += r0.x; v0.y += r0.y;
                v1.x += r1.x; v1.y += r1.y;
            }
            *(float2*)(Cm + (size_t)row0 * N + col) = v0;
            *(float2*)(Cm + (size_t)(row0 + 8) * N + col) = v1;
        }
    }
}

template<int EPI>
__global__ __launch_bounds__(256, 2)
void tgemm_bias(const float* __restrict__ A, const float* __restrict__ Bm,
                const float* __restrict__ bias, const float* __restrict__ res,
                float* __restrict__ Cm, int M, int N, int K)
{
    extern __shared__ float sm[];
    tgemm_body<EPI>(sm, A, Bm, bias, res, Cm, M, N, K,
                    blockIdx.y * 128, blockIdx.x * 128);
}

// merged cq/ck/cv projections: blockIdx.z selects the (A,B,bias,C) set
__global__ __launch_bounds__(256, 2)
void tgemm3(const float* __restrict__ x1, const float* __restrict__ enc,
            const float* qw, const float* qb,
            const float* kw, const float* kb,
            const float* vw, const float* vb,
            float* cq, float* ck, float* cv)
{
    extern __shared__ float sm[];
    const int z = blockIdx.z;
    const float* A    = (z == 0) ? x1 : enc;
    const float* Bm   = (z == 0) ? qw : (z == 1) ? kw : vw;
    const float* bias = (z == 0) ? qb : (z == 1) ? kb : vb;
    float* Cm         = (z == 0) ? cq : (z == 1) ? ck : cv;
    tgemm_body<EPI_NONE>(sm, A, Bm, bias, nullptr, Cm, MROWS, CC, CC,
                         blockIdx.y * 128, blockIdx.x * 128);
}

// ---------------- tensor-core flash attention --------------------------------
// Tile 128q x 64k, d=64. 8 warps; warp w owns q-rows [w*16, w*16+16).
// SMEM (floats, stride 68 everywhere -> conflict-free fragment LDS):
//   Qs[128][68] @0 ; 3 KV stages @8704 (K[64][68] then V[64][68] per stage);
//   Ps[128][68] @34816.  Total 43520 floats = 174080 B.
#define AT_STR 68
#define AT_SMQ 0
#define AT_SMKV 8704
#define AT_STAGE 8704
#define AT_SMP 34816
#define AT_SMEM (43520*4)

template<bool CAUSAL>
__global__ __launch_bounds__(256, 1)
void attn_mma(const float* __restrict__ Q, const float* __restrict__ Kp,
              const float* __restrict__ Vp, float* __restrict__ O,
              int qstride, int kvstride)
{
    extern __shared__ float sm[];
    float* Qs = sm + AT_SMQ;
    float* Ps = sm + AT_SMP;

    const int b = blockIdx.z, h = blockIdx.y, qt = blockIdx.x;
    const int tid = threadIdx.x;
    const int lane = tid & 31, warp = tid >> 5;
    const int r = lane >> 2, q = lane & 3;
    const int qbase = qt * 128;
    const int qw16 = warp * 16;               // warp's local q-row base
    const uint32_t smemBase = (uint32_t)__cvta_generic_to_shared(sm);

    // fill Q (scaled, tf32-rounded)
    const float* Qbase = Q + (size_t)(b * TT + qbase) * qstride + h * DD;
    #pragma unroll
    for (int i = 0; i < 8; i++) {
        const int lin = tid + (i << 8);
        const int row = lin >> 4, c4 = (lin & 15) << 2;
        float4 v = *(const float4*)(Qbase + (size_t)row * qstride + c4);
        float4 o;
        o.x = __uint_as_float(f2tf(v.x * 0.125f));
        o.y = __uint_as_float(f2tf(v.y * 0.125f));
        o.z = __uint_as_float(f2tf(v.z * 0.125f));
        o.w = __uint_as_float(f2tf(v.w * 0.125f));
        *(float4*)(Qs + row * AT_STR + c4) = o;
    }

    const float* Kbase = Kp + (size_t)(b * TT) * kvstride + h * DD;
    const float* Vbase = Vp + (size_t)(b * TT) * kvstride + h * DD;

    const int nkt = CAUSAL ? (2 * qt + 2) : (TT / 64);

    auto issueKV = [&](int kt) {
        if (kt < nkt) {
            const int kb = kt * 64;
            const uint32_t sb = smemBase +
                (uint32_t)((AT_SMKV + (kt % 3) * AT_STAGE) * 4);
            #pragma unroll
            for (int i = 0; i < 4; i++) {
                const int lin = tid + (i << 8);
                const int row = lin >> 4, c4 = (lin & 15) << 2;
                const size_t goff = (size_t)(kb + row) * kvstride + c4;
                cp16(sb + (uint32_t)((row * AT_STR + c4) * 4), Kbase + goff);
                cp16(sb + (uint32_t)((4352 + row * AT_STR + c4) * 4), Vbase + goff);
            }
        }
        asm volatile("cp.async.commit_group;");
    };

    issueKV(0);
    issueKV(1);

    float oacc[8][4];
    float m0 = -1e30f, m1 = -1e30f, l0 = 0.f, l1 = 0.f;
    #pragma unroll
    for (int nt = 0; nt < 8; nt++)
        #pragma unroll
        for (int e = 0; e < 4; e++) oacc[nt][e] = 0.f;

    for (int kt = 0; kt < nkt; kt++) {
        asm volatile("cp.async.wait_group 1;");
        __syncthreads();
        issueKV(kt + 2);

        const float* Ks = sm + AT_SMKV + (kt % 3) * AT_STAGE;
        const float* Vs = Ks + 4352;
        const int kbase = kt * 64;

        // ---- S = Q K^T ----
        float sacc[8][4];
        #pragma unroll
        for (int nt = 0; nt < 8; nt++)
            #pragma unroll
            for (int e = 0; e < 4; e++) sacc[nt][e] = 0.f;

        #pragma unroll
        for (int ks = 0; ks < 8; ks++) {
            uint32_t af[4];
            const float* qp = Qs + (qw16 + r) * AT_STR + ks * 8 + q;
            af[0] = __float_as_uint(qp[0]);
            af[1] = __float_as_uint(qp[8 * AT_STR]);
            af[2] = __float_as_uint(qp[4]);
            af[3] = __float_as_uint(qp[8 * AT_STR + 4]);
            #pragma unroll
            for (int nt = 0; nt < 8; nt++) {
                const float* kp = Ks + (nt * 8 + r) * AT_STR + ks * 8 + q;
                uint32_t bf[2];
                bf[0] = f2tf(kp[0]);
                bf[1] = f2tf(kp[4]);
                mma_tf32(sacc[nt], af, bf);
            }
        }

        // ---- causal mask ----
        if (CAUSAL && kbase + 63 > qbase + qw16) {
            const int row0 = qbase + qw16 + r, row1 = row0 + 8;
            #pragma unroll
            for (int nt = 0; nt < 8; nt++) {
                const int c0 = kbase + nt * 8 + 2 * q, c1 = c0 + 1;
                if (c0 > row0) sacc[nt][0] = -1e30f;
                if (c1 > row0) sacc[nt][1] = -1e30f;
                if (c0 > row1) sacc[nt][2] = -1e30f;
                if (c1 > row1) sacc[nt][3] = -1e30f;
            }
        }

        // ---- online softmax (rows r0 = qw16+r, r1 = +8) ----
        float rm0 = -1e30f, rm1 = -1e30f;
        #pragma unroll
        for (int nt = 0; nt < 8; nt++) {
            rm0 = fmaxf(rm0, fmaxf(sacc[nt][0], sacc[nt][1]));
            rm1 = fmaxf(rm1, fmaxf(sacc[nt][2], sacc[nt][3]));
        }
        rm0 = fmaxf(rm0, __shfl_xor_sync(0xffffffffu, rm0, 1));
        rm0 = fmaxf(rm0, __shfl_xor_sync(0xffffffffu, rm0, 2));
        rm1 = fmaxf(rm1, __shfl_xor_sync(0xffffffffu, rm1, 1));
        rm1 = fmaxf(rm1, __shfl_xor_sync(0xffffffffu, rm1, 2));

        const float mn0 = fmaxf(m0, rm0), mn1 = fmaxf(m1, rm1);
        const float cr0 = __expf(m0 - mn0), cr1 = __expf(m1 - mn1);
        m0 = mn0; m1 = mn1;

        float rs0 = 0.f, rs1 = 0.f;
        float* p0 = Ps + (qw16 + r) * AT_STR + 2 * q;
        float* p1 = p0 + 8 * AT_STR;
        #pragma unroll
        for (int nt = 0; nt < 8; nt++) {
            const float e00 = __expf(sacc[nt][0] - mn0);
            const float e01 = __expf(sacc[nt][1] - mn0);
            const float e10 = __expf(sacc[nt][2] - mn1);
            const float e11 = __expf(sacc[nt][3] - mn1);
            rs0 += e00 + e01;
            rs1 += e10 + e11;
            *(float2*)(p0 + nt * 8) = make_float2(__uint_as_float(f2tf(e00)),
                                                  __uint_as_float(f2tf(e01)));
            *(float2*)(p1 + nt * 8) = make_float2(__uint_as_float(f2tf(e10)),
                                                  __uint_as_float(f2tf(e11)));
        }
        rs0 += __shfl_xor_sync(0xffffffffu, rs0, 1);
        rs0 += __shfl_xor_sync(0xffffffffu, rs0, 2);
        rs1 += __shfl_xor_sync(0xffffffffu, rs1, 1);
        rs1 += __shfl_xor_sync(0xffffffffu, rs1, 2);
        l0 = l0 * cr0 + rs0;
        l1 = l1 * cr1 + rs1;

        #pragma unroll
        for (int nt = 0; nt < 8; nt++) {
            oacc[nt][0] *= cr0; oacc[nt][1] *= cr0;
            oacc[nt][2] *= cr1; oacc[nt][3] *= cr1;
        }

        __syncwarp();

        // ---- O += P V ----
        #pragma unroll
        for (int ks = 0; ks < 8; ks++) {
            uint32_t af[4];
            const float* pp = Ps + (qw16 + r) * AT_STR + ks * 8 + q;
            af[0] = __float_as_uint(pp[0]);
            af[1] = __float_as_uint(pp[8 * AT_STR]);
            af[2] = __float_as_uint(pp[4]);
            af[3] = __float_as_uint(pp[8 * AT_STR + 4]);
            #pragma unroll
            for (int nt = 0; nt < 8; nt++) {
                uint32_t bf[2];
                bf[0] = f2tf(Vs[(ks * 8 + q) * AT_STR + nt * 8 + r]);
                bf[1] = f2tf(Vs[(ks * 8 + q + 4) * AT_STR + nt * 8 + r]);
                mma_tf32(oacc[nt], af, bf);
            }
        }
        __syncwarp();   // protect Ps against next iteration's overwrite
    }

    // ---- epilogue ----
    const float inv0 = 1.f / l0, inv1 = 1.f / l1;
    const int row0 = qbase + qw16 + r;
    float* og0 = O + (size_t)(b * TT + row0) * CC + h * DD + 2 * q;
    float* og1 = O + (size_t)(b * TT + row0 + 8) * CC + h * DD + 2 * q;
    #pragma unroll
    for (int nt = 0; nt < 8; nt++) {
        *(float2*)(og0 + nt * 8) = make_float2(oacc[nt][0] * inv0,
                                               oacc[nt][1] * inv0);
        *(float2*)(og1 + nt * 8) = make_float2(oacc[nt][2] * inv1,
                                               oacc[nt][3] * inv1);
    }
}

// ---------------- LayerNorm --------------------------------------------------
__global__ __launch_bounds__(256)
void layernorm_k(const float* __restrict__ in, const float* __restrict__ g,
                 const float* __restrict__ b, float* __restrict__ out)
{
    const int row = blockIdx.x;
    const int tid = threadIdx.x;
    const float* x = in + (size_t)row * CC;

    const float v0 = x[tid], v1 = x[tid + 256], v2 = x[tid + 512];
    float s = v0 + v1 + v2;
    float sq = v0 * v0 + v1 * v1 + v2 * v2;

    #pragma unroll
    for (int off = 16; off; off >>= 1) {
        s  += __shfl_xor_sync(0xffffffffu, s, off);
        sq += __shfl_xor_sync(0xffffffffu, sq, off);
    }
    __shared__ float red[16];
    const int wid = tid >> 5, lane = tid & 31;
    if (lane == 0) { red[wid] = s; red[wid + 8] = sq; }
    __syncthreads();

    float ts = 0.f, tq = 0.f;
    #pragma unroll
    for (int i = 0; i < 8; i++) { ts += red[i]; tq += red[i + 8]; }

    const float mu = ts * (1.f / CC);
    const float var = tq * (1.f / CC) - mu * mu;
    const float rstd = rsqrtf(var + 1e-5f);

    float* orow = out + (size_t)row * CC;
    orow[tid]       = (v0 - mu) * rstd * g[tid]       + b[tid];
    orow[tid + 256] = (v1 - mu) * rstd * g[tid + 256] + b[tid + 256];
    orow[tid + 512] = (v2 - mu) * rstd * g[tid + 512] + b[tid + 512];
}

// ---------------- launch ------------------------------------------------------
extern "C" void kernel_launch(void* const* d_in, const int* in_sizes, int n_in,
                              void* d_out, int out_size)
{
    const float* x      = (const float*)d_in[0];
    const float* enc    = (const float*)d_in[1];
    const float* ln1_g  = (const float*)d_in[2];
    const float* ln1_b  = (const float*)d_in[3];
    const float* qkv_w  = (const float*)d_in[4];
    const float* qkv_b  = (const float*)d_in[5];
    const float* proj_w = (const float*)d_in[6];
    const float* proj_b = (const float*)d_in[7];
    const float* ln2_g  = (const float*)d_in[8];
    const float* ln2_b  = (const float*)d_in[9];
    const float* caq_w  = (const float*)d_in[10];
    const float* caq_b  = (const float*)d_in[11];
    const float* cak_w  = (const float*)d_in[12];
    const float* cak_b  = (const float*)d_in[13];
    const float* cav_w  = (const float*)d_in[14];
    const float* cav_b  = (const float*)d_in[15];
    const float* cao_w  = (const float*)d_in[16];
    const float* cao_b  = (const float*)d_in[17];
    const float* ln3_g  = (const float*)d_in[18];
    const float* ln3_b  = (const float*)d_in[19];
    const float* fc_w   = (const float*)d_in[20];
    const float* fc_b   = (const float*)d_in[21];
    const float* fc2_w  = (const float*)d_in[22];
    const float* fc2_b  = (const float*)d_in[23];
    float* out = (float*)d_out;

    float *qkv, *att, *res, *x1, *cq, *ck, *cv, *x2, *hbuf;
    cudaGetSymbolAddress((void**)&qkv,  g_qkv);
    cudaGetSymbolAddress((void**)&att,  g_att);
    cudaGetSymbolAddress((void**)&res,  g_res);
    cudaGetSymbolAddress((void**)&x1,   g_x1);
    cudaGetSymbolAddress((void**)&cq,   g_cq);
    cudaGetSymbolAddress((void**)&ck,   g_ck);
    cudaGetSymbolAddress((void**)&cv,   g_cv);
    cudaGetSymbolAddress((void**)&x2,   g_x2);
    cudaGetSymbolAddress((void**)&hbuf, g_h);

    cudaFuncSetAttribute(attn_mma<true>,
                         cudaFuncAttributeMaxDynamicSharedMemorySize, AT_SMEM);
    cudaFuncSetAttribute(attn_mma<false>,
                         cudaFuncAttributeMaxDynamicSharedMemorySize, AT_SMEM);
    cudaFuncSetAttribute(tgemm_bias<EPI_NONE>,
                         cudaFuncAttributeMaxDynamicSharedMemorySize, GSMEM);
    cudaFuncSetAttribute(tgemm_bias<EPI_RELU>,
                         cudaFuncAttributeMaxDynamicSharedMemorySize, GSMEM);
    cudaFuncSetAttribute(tgemm_bias<EPI_RES>,
                         cudaFuncAttributeMaxDynamicSharedMemorySize, GSMEM);
    cudaFuncSetAttribute(tgemm3,
                         cudaFuncAttributeMaxDynamicSharedMemorySize, GSMEM);

    const dim3 thr(256);
    const dim3 g768(CC / 128, MROWS / 128);
    const dim3 gqkv(3 * CC / 128, MROWS / 128);
    const dim3 gfc(4 * CC / 128, MROWS / 128);
    const dim3 g3(CC / 128, MROWS / 128, 3);
    const dim3 gattn(TT / 128, HH, BB);          // (16, 12, 2)

    tgemm_bias<EPI_NONE><<<gqkv, thr, GSMEM>>>(x, qkv_w, qkv_b, nullptr, qkv,
                                               MROWS, 3 * CC, CC);
    attn_mma<true><<<gattn, thr, AT_SMEM>>>(qkv, qkv + CC, qkv + 2 * CC, att,
                                            3 * CC, 3 * CC);
    tgemm_bias<EPI_RES><<<g768, thr, GSMEM>>>(att, proj_w, proj_b, x, res,
                                              MROWS, CC, CC);
    layernorm_k<<<MROWS, thr>>>(res, ln1_g, ln1_b, x1);

    tgemm3<<<g3, thr, GSMEM>>>(x1, enc, caq_w, caq_b, cak_w, cak_b,
                               cav_w, cav_b, cq, ck, cv);

    attn_mma<false><<<gattn, thr, AT_SMEM>>>(cq, ck, cv, att, CC, CC);
    tgemm_bias<EPI_RES><<<g768, thr, GSMEM>>>(att, cao_w, cao_b, x1, res,
                                              MROWS, CC, CC);
    layernorm_k<<<MROWS, thr>>>(res, ln2_g, ln2_b, x2);

    tgemm_bias<EPI_RELU><<<gfc, thr, GSMEM>>>(x2, fc_w, fc_b, nullptr, hbuf,
                                              MROWS, 4 * CC, CC);
    tgemm_bias<EPI_RES><<<g768, thr, GSMEM>>>(hbuf, fc2_w, fc2_b, x2, res,
                                              MROWS, CC, 4 * CC);
    layernorm_k<<<MROWS, thr>>>(res, ln3_g, ln3_b, out);
}

// round 5
// speedup vs baseline: 6.6731x; 1.0317x over previous
#include <cuda_runtime.h>
#include <math.h>
#include <stdint.h>

#define BB 2
#define TT 2048
#define CC 768
#define HH 12
#define DD 64
#define MROWS (BB*TT)   // 4096

// ---------------- scratch ----------------------------------------------------
__device__ float g_qkv[(size_t)MROWS * 3 * CC];
__device__ float g_att[(size_t)MROWS * CC];
__device__ float g_res[(size_t)MROWS * CC];
__device__ float g_x1 [(size_t)MROWS * CC];
__device__ float g_cq [(size_t)MROWS * CC];
__device__ float g_ck [(size_t)MROWS * CC];
__device__ float g_cv [(size_t)MROWS * CC];
__device__ float g_x2 [(size_t)MROWS * CC];
__device__ float g_h  [(size_t)MROWS * 4 * CC];
// rounded copies (tf32-RNA, stored as fp32 bit patterns)
__device__ float g_xr  [(size_t)MROWS * CC];
__device__ float g_encr[(size_t)MROWS * CC];
__device__ float g_x1r [(size_t)MROWS * CC];
__device__ float g_x2r [(size_t)MROWS * CC];
__device__ float g_wq  [(size_t)CC * 3 * CC];
__device__ float g_wp  [(size_t)CC * CC];
__device__ float g_wcq [(size_t)CC * CC];
__device__ float g_wck [(size_t)CC * CC];
__device__ float g_wcv [(size_t)CC * CC];
__device__ float g_wco [(size_t)CC * CC];
__device__ float g_wfc [(size_t)CC * 4 * CC];
__device__ float g_wfc2[(size_t)4 * CC * CC];

enum { EPI_NONE = 0, EPI_RELU = 1, EPI_RES = 2 };

__device__ __forceinline__ void cp16(uint32_t s, const void* g) {
    asm volatile("cp.async.cg.shared.global [%0], [%1], 16;" :: "r"(s), "l"(g));
}
__device__ __forceinline__ uint32_t f2tf(float x) {
    uint32_t r;
    asm("cvt.rna.tf32.f32 %0, %1;" : "=r"(r) : "f"(x));
    return r;
}
__device__ __forceinline__ float rndf(float x) { return __uint_as_float(f2tf(x)); }
__device__ __forceinline__ void mma_tf32(float* d, const uint32_t* a,
                                         const uint32_t* b) {
    asm volatile(
        "mma.sync.aligned.m16n8k8.row.col.f32.tf32.tf32.f32 "
        "{%0,%1,%2,%3}, {%4,%5,%6,%7}, {%8,%9}, {%0,%1,%2,%3};\n"
        : "+f"(d[0]), "+f"(d[1]), "+f"(d[2]), "+f"(d[3])
        : "r"(a[0]), "r"(a[1]), "r"(a[2]), "r"(a[3]), "r"(b[0]), "r"(b[1]));
}

// ---------------- fused pre-rounding pass (x, enc, all weights) --------------
// segment prefix offsets (floats); all divisible by 4
#define R_XR   3145728u
#define R_ENC  6291456u
#define R_WQ   8060928u
#define R_WP   8650752u
#define R_WCQ  9240576u
#define R_WCK  9830400u
#define R_WCV  10420224u
#define R_WCO  11010048u
#define R_WFC  13369344u
#define R_TOT  15728640u   // / 1024 = 15360 blocks

__global__ __launch_bounds__(256)
void round_all(const float* x, const float* enc, const float* qw,
               const float* pw, const float* cqw, const float* ckw,
               const float* cvw, const float* cow, const float* fcw,
               const float* fc2w,
               float* xr, float* encr, float* wq, float* wp, float* wcq,
               float* wck, float* wcv, float* wco, float* wfc, float* wfc2)
{
    const uint32_t i4 = (blockIdx.x * 256u + threadIdx.x) * 4u;
    const float* s; float* d; uint32_t off;
    if      (i4 < R_XR)  { s = x;    d = xr;   off = i4; }
    else if (i4 < R_ENC) { s = enc;  d = encr; off = i4 - R_XR; }
    else if (i4 < R_WQ)  { s = qw;   d = wq;   off = i4 - R_ENC; }
    else if (i4 < R_WP)  { s = pw;   d = wp;   off = i4 - R_WQ; }
    else if (i4 < R_WCQ) { s = cqw;  d = wcq;  off = i4 - R_WP; }
    else if (i4 < R_WCK) { s = ckw;  d = wck;  off = i4 - R_WCQ; }
    else if (i4 < R_WCV) { s = cvw;  d = wcv;  off = i4 - R_WCK; }
    else if (i4 < R_WCO) { s = cow;  d = wco;  off = i4 - R_WCV; }
    else if (i4 < R_WFC) { s = fcw;  d = wfc;  off = i4 - R_WCO; }
    else                 { s = fc2w; d = wfc2; off = i4 - R_WFC; }
    float4 v = *(const float4*)(s + off);
    v.x = rndf(v.x); v.y = rndf(v.y); v.z = rndf(v.z); v.w = rndf(v.w);
    *(float4*)(d + off) = v;
}

// ---------------- tf32 GEMM 128x128x32, cp.async 3-stage, pre-rounded -------
#define ASTR 36
#define BSTR 132
#define ABUF (128*ASTR)
#define GBUFSZ (ABUF + 32*BSTR)   // 8832 floats/stage
#define GSMEM (3*GBUFSZ*4)        // 105984 B

template<int EPI, int RND>
__device__ __forceinline__
void tgemm_body(float* sm, const float* __restrict__ A,
                const float* __restrict__ Bm, const float* __restrict__ bias,
                const float* __restrict__ res, float* __restrict__ Cm,
                int M, int N, int K, int mBase, int nBase)
{
    const int tid = threadIdx.x;
    const int lane = tid & 31, warp = tid >> 5;
    const int wm = warp >> 2, wn = warp & 3;
    const int r = lane >> 2, q = lane & 3;
    const uint32_t smemBase = (uint32_t)__cvta_generic_to_shared(sm);

    float acc[4][4][4];
    #pragma unroll
    for (int mt = 0; mt < 4; mt++)
        #pragma unroll
        for (int nt = 0; nt < 4; nt++)
            #pragma unroll
            for (int e = 0; e < 4; e++) acc[mt][nt][e] = 0.f;

    const int nchunk = K >> 5;

    auto issue = [&](int c) {
        if (c < nchunk) {
            const int kc = c << 5;
            const uint32_t sb = smemBase + (uint32_t)((c % 3) * GBUFSZ * 4);
            #pragma unroll
            for (int i = 0; i < 4; i++) {
                const int fid = tid + (i << 8);
                const int row = fid >> 3, k4 = (fid & 7) << 2;
                cp16(sb + (uint32_t)((row * ASTR + k4) * 4),
                     A + (size_t)(mBase + row) * K + kc + k4);
            }
            #pragma unroll
            for (int i = 0; i < 4; i++) {
                const int fid = tid + (i << 8);
                const int kr = fid >> 5, n4 = (fid & 31) << 2;
                cp16(sb + (uint32_t)((ABUF + kr * BSTR + n4) * 4),
                     Bm + (size_t)(kc + kr) * N + nBase + n4);
            }
        }
        asm volatile("cp.async.commit_group;");
    };

    issue(0);
    issue(1);

    for (int c = 0; c < nchunk; c++) {
        asm volatile("cp.async.wait_group 1;");
        __syncthreads();
        issue(c + 2);

        const uint32_t* AsU = (const uint32_t*)sm + (c % 3) * GBUFSZ;
        const uint32_t* BsU = AsU + ABUF;

        #pragma unroll
        for (int ks = 0; ks < 4; ks++) {
            uint32_t af[4][4], bf[4][2];
            #pragma unroll
            for (int mt = 0; mt < 4; mt++) {
                const int base = (wm * 64 + mt * 16 + r) * ASTR + ks * 8 + q;
                af[mt][0] = AsU[base];
                af[mt][1] = AsU[base + 8 * ASTR];
                af[mt][2] = AsU[base + 4];
                af[mt][3] = AsU[base + 8 * ASTR + 4];
            }
            #pragma unroll
            for (int nt = 0; nt < 4; nt++) {
                const int base = (ks * 8 + q) * BSTR + wn * 32 + nt * 8 + r;
                bf[nt][0] = BsU[base];
                bf[nt][1] = BsU[base + 4 * BSTR];
            }
            #pragma unroll
            for (int mt = 0; mt < 4; mt++)
                #pragma unroll
                for (int nt = 0; nt < 4; nt++)
                    mma_tf32(acc[mt][nt], af[mt], bf[nt]);
        }
    }

    #pragma unroll
    for (int mt = 0; mt < 4; mt++) {
        const int row0 = mBase + wm * 64 + mt * 16 + r;
        #pragma unroll
        for (int nt = 0; nt < 4; nt++) {
            const int col = nBase + wn * 32 + nt * 8 + 2 * q;
            const float2 bv = *(const float2*)(bias + col);
            float2 v0 = make_float2(acc[mt][nt][0] + bv.x, acc[mt][nt][1] + bv.y);
            float2 v1 = make_float2(acc[mt][nt][2] + bv.x, acc[mt][nt][3] + bv.y);
            if (EPI == EPI_RELU) {
                v0.x = fmaxf(v0.x, 0.f); v0.y = fmaxf(v0.y, 0.f);
                v1.x = fmaxf(v1.x, 0.f); v1.y = fmaxf(v1.y, 0.f);
            }
            if (EPI == EPI_RES) {
                const float2 r0 = *(const float2*)(res + (size_t)row0 * N + col);
                const float2 r1 = *(const float2*)(res + (size_t)(row0 + 8) * N + col);
                v0.x += r0.x; v0.y += r0.y;
                v1.x += r1.x; v1.y += r1.y;
            }
            if (RND) {
                v0.x = rndf(v0.x); v0.y = rndf(v0.y);
                v1.x = rndf(v1.x); v1.y = rndf(v1.y);
            }
            *(float2*)(Cm + (size_t)row0 * N + col) = v0;
            *(float2*)(Cm + (size_t)(row0 + 8) * N + col) = v1;
        }
    }
}

template<int EPI, int RND>
__global__ __launch_bounds__(256, 2)
void tgemm_bias(const float* __restrict__ A, const float* __restrict__ Bm,
                const float* __restrict__ bias, const float* __restrict__ res,
                float* __restrict__ Cm, int M, int N, int K)
{
    extern __shared__ float sm[];
    tgemm_body<EPI, RND>(sm, A, Bm, bias, res, Cm, M, N, K,
                         blockIdx.y * 128, blockIdx.x * 128);
}

// merged cq/ck/cv projections
__global__ __launch_bounds__(256, 2)
void tgemm3(const float* __restrict__ x1r, const float* __restrict__ encr,
            const float* qw, const float* qb,
            const float* kw, const float* kb,
            const float* vw, const float* vb,
            float* cq, float* ck, float* cv)
{
    extern __shared__ float sm[];
    const int z = blockIdx.z;
    const float* A    = (z == 0) ? x1r : encr;
    const float* Bm   = (z == 0) ? qw : (z == 1) ? kw : vw;
    const float* bias = (z == 0) ? qb : (z == 1) ? kb : vb;
    float* Cm         = (z == 0) ? cq : (z == 1) ? ck : cv;
    tgemm_body<EPI_NONE, 1>(sm, A, Bm, bias, nullptr, Cm, MROWS, CC, CC,
                            blockIdx.y * 128, blockIdx.x * 128);
}

// ---------------- tensor-core flash attention (inputs pre-rounded) -----------
#define AT_STR 68
#define AT_SMQ 0
#define AT_SMKV 8704
#define AT_STAGE 8704
#define AT_SMP 34816
#define AT_SMEM (43520*4)

template<bool CAUSAL>
__global__ __launch_bounds__(256, 1)
void attn_mma(const float* __restrict__ Q, const float* __restrict__ Kp,
              const float* __restrict__ Vp, float* __restrict__ O,
              int qstride, int kvstride)
{
    extern __shared__ float sm[];
    float* Qs = sm + AT_SMQ;
    float* Ps = sm + AT_SMP;

    const int b = blockIdx.z, h = blockIdx.y, qt = blockIdx.x;
    const int tid = threadIdx.x;
    const int lane = tid & 31, warp = tid >> 5;
    const int r = lane >> 2, q = lane & 3;
    const int qbase = qt * 128;
    const int qw16 = warp * 16;
    const uint32_t smemBase = (uint32_t)__cvta_generic_to_shared(sm);

    // Q is pre-rounded; *0.125 is a power of two -> stays tf32-exact
    const float* Qbase = Q + (size_t)(b * TT + qbase) * qstride + h * DD;
    #pragma unroll
    for (int i = 0; i < 8; i++) {
        const int lin = tid + (i << 8);
        const int row = lin >> 4, c4 = (lin & 15) << 2;
        float4 v = *(const float4*)(Qbase + (size_t)row * qstride + c4);
        v.x *= 0.125f; v.y *= 0.125f; v.z *= 0.125f; v.w *= 0.125f;
        *(float4*)(Qs + row * AT_STR + c4) = v;
    }

    const float* Kbase = Kp + (size_t)(b * TT) * kvstride + h * DD;
    const float* Vbase = Vp + (size_t)(b * TT) * kvstride + h * DD;

    const int nkt = CAUSAL ? (2 * qt + 2) : (TT / 64);

    auto issueKV = [&](int kt) {
        if (kt < nkt) {
            const int kb = kt * 64;
            const uint32_t sb = smemBase +
                (uint32_t)((AT_SMKV + (kt % 3) * AT_STAGE) * 4);
            #pragma unroll
            for (int i = 0; i < 4; i++) {
                const int lin = tid + (i << 8);
                const int row = lin >> 4, c4 = (lin & 15) << 2;
                const size_t goff = (size_t)(kb + row) * kvstride + c4;
                cp16(sb + (uint32_t)((row * AT_STR + c4) * 4), Kbase + goff);
                cp16(sb + (uint32_t)((4352 + row * AT_STR + c4) * 4), Vbase + goff);
            }
        }
        asm volatile("cp.async.commit_group;");
    };

    issueKV(0);
    issueKV(1);

    float oacc[8][4];
    float m0 = -1e30f, m1 = -1e30f, l0 = 0.f, l1 = 0.f;
    #pragma unroll
    for (int nt = 0; nt < 8; nt++)
        #pragma unroll
        for (int e = 0; e < 4; e++) oacc[nt][e] = 0.f;

    for (int kt = 0; kt < nkt; kt++) {
        asm volatile("cp.async.wait_group 1;");
        __syncthreads();
        issueKV(kt + 2);

        const float* Ks = sm + AT_SMKV + (kt % 3) * AT_STAGE;
        const float* Vs = Ks + 4352;
        const int kbase = kt * 64;

        float sacc[8][4];
        #pragma unroll
        for (int nt = 0; nt < 8; nt++)
            #pragma unroll
            for (int e = 0; e < 4; e++) sacc[nt][e] = 0.f;

        #pragma unroll
        for (int ks = 0; ks < 8; ks++) {
            uint32_t af[4];
            const float* qp = Qs + (qw16 + r) * AT_STR + ks * 8 + q;
            af[0] = __float_as_uint(qp[0]);
            af[1] = __float_as_uint(qp[8 * AT_STR]);
            af[2] = __float_as_uint(qp[4]);
            af[3] = __float_as_uint(qp[8 * AT_STR + 4]);
            #pragma unroll
            for (int nt = 0; nt < 8; nt++) {
                const float* kp = Ks + (nt * 8 + r) * AT_STR + ks * 8 + q;
                uint32_t bf[2];
                bf[0] = __float_as_uint(kp[0]);
                bf[1] = __float_as_uint(kp[4]);
                mma_tf32(sacc[nt], af, bf);
            }
        }

        if (CAUSAL && kbase + 63 > qbase + qw16) {
            const int row0 = qbase + qw16 + r, row1 = row0 + 8;
            #pragma unroll
            for (int nt = 0; nt < 8; nt++) {
                const int c0 = kbase + nt * 8 + 2 * q, c1 = c0 + 1;
                if (c0 > row0) sacc[nt][0] = -1e30f;
                if (c1 > row0) sacc[nt][1] = -1e30f;
                if (c0 > row1) sacc[nt][2] = -1e30f;
                if (c1 > row1) sacc[nt][3] = -1e30f;
            }
        }

        float rm0 = -1e30f, rm1 = -1e30f;
        #pragma unroll
        for (int nt = 0; nt < 8; nt++) {
            rm0 = fmaxf(rm0, fmaxf(sacc[nt][0], sacc[nt][1]));
            rm1 = fmaxf(rm1, fmaxf(sacc[nt][2], sacc[nt][3]));
        }
        rm0 = fmaxf(rm0, __shfl_xor_sync(0xffffffffu, rm0, 1));
        rm0 = fmaxf(rm0, __shfl_xor_sync(0xffffffffu, rm0, 2));
        rm1 = fmaxf(rm1, __shfl_xor_sync(0xffffffffu, rm1, 1));
        rm1 = fmaxf(rm1, __shfl_xor_sync(0xffffffffu, rm1, 2));

        const float mn0 = fmaxf(m0, rm0), mn1 = fmaxf(m1, rm1);
        const float cr0 = __expf(m0 - mn0), cr1 = __expf(m1 - mn1);
        m0 = mn0; m1 = mn1;

        float rs0 = 0.f, rs1 = 0.f;
        float* p0 = Ps + (qw16 + r) * AT_STR + 2 * q;
        float* p1 = p0 + 8 * AT_STR;
        #pragma unroll
        for (int nt = 0; nt < 8; nt++) {
            const float e00 = __expf(sacc[nt][0] - mn0);
            const float e01 = __expf(sacc[nt][1] - mn0);
            const float e10 = __expf(sacc[nt][2] - mn1);
            const float e11 = __expf(sacc[nt][3] - mn1);
            rs0 += e00 + e01;
            rs1 += e10 + e11;
            *(float2*)(p0 + nt * 8) = make_float2(rndf(e00), rndf(e01));
            *(float2*)(p1 + nt * 8) = make_float2(rndf(e10), rndf(e11));
        }
        rs0 += __shfl_xor_sync(0xffffffffu, rs0, 1);
        rs0 += __shfl_xor_sync(0xffffffffu, rs0, 2);
        rs1 += __shfl_xor_sync(0xffffffffu, rs1, 1);
        rs1 += __shfl_xor_sync(0xffffffffu, rs1, 2);
        l0 = l0 * cr0 + rs0;
        l1 = l1 * cr1 + rs1;

        #pragma unroll
        for (int nt = 0; nt < 8; nt++) {
            oacc[nt][0] *= cr0; oacc[nt][1] *= cr0;
            oacc[nt][2] *= cr1; oacc[nt][3] *= cr1;
        }

        __syncwarp();

        #pragma unroll
        for (int ks = 0; ks < 8; ks++) {
            uint32_t af[4];
            const float* pp = Ps + (qw16 + r) * AT_STR + ks * 8 + q;
            af[0] = __float_as_uint(pp[0]);
            af[1] = __float_as_uint(pp[8 * AT_STR]);
            af[2] = __float_as_uint(pp[4]);
            af[3] = __float_as_uint(pp[8 * AT_STR + 4]);
            #pragma unroll
            for (int nt = 0; nt < 8; nt++) {
                uint32_t bf[2];
                bf[0] = __float_as_uint(Vs[(ks * 8 + q) * AT_STR + nt * 8 + r]);
                bf[1] = __float_as_uint(Vs[(ks * 8 + q + 4) * AT_STR + nt * 8 + r]);
                mma_tf32(oacc[nt], af, bf);
            }
        }
        __syncwarp();
    }

    // epilogue: output feeds only GEMM A -> store tf32-rounded
    const float inv0 = 1.f / l0, inv1 = 1.f / l1;
    const int row0 = qbase + qw16 + r;
    float* og0 = O + (size_t)(b * TT + row0) * CC + h * DD + 2 * q;
    float* og1 = O + (size_t)(b * TT + row0 + 8) * CC + h * DD + 2 * q;
    #pragma unroll
    for (int nt = 0; nt < 8; nt++) {
        *(float2*)(og0 + nt * 8) = make_float2(rndf(oacc[nt][0] * inv0),
                                               rndf(oacc[nt][1] * inv0));
        *(float2*)(og1 + nt * 8) = make_float2(rndf(oacc[nt][2] * inv1),
                                               rndf(oacc[nt][3] * inv1));
    }
}

// ---------------- LayerNorm (optional second rounded output) -----------------
__global__ __launch_bounds__(256)
void layernorm_k(const float* __restrict__ in, const float* __restrict__ g,
                 const float* __restrict__ b, float* __restrict__ out,
                 float* __restrict__ outr)
{
    const int row = blockIdx.x;
    const int tid = threadIdx.x;
    const float* x = in + (size_t)row * CC;

    const float v0 = x[tid], v1 = x[tid + 256], v2 = x[tid + 512];
    float s = v0 + v1 + v2;
    float sq = v0 * v0 + v1 * v1 + v2 * v2;

    #pragma unroll
    for (int off = 16; off; off >>= 1) {
        s  += __shfl_xor_sync(0xffffffffu, s, off);
        sq += __shfl_xor_sync(0xffffffffu, sq, off);
    }
    __shared__ float red[16];
    const int wid = tid >> 5, lane = tid & 31;
    if (lane == 0) { red[wid] = s; red[wid + 8] = sq; }
    __syncthreads();

    float ts = 0.f, tq = 0.f;
    #pragma unroll
    for (int i = 0; i < 8; i++) { ts += red[i]; tq += red[i + 8]; }

    const float mu = ts * (1.f / CC);
    const float var = tq * (1.f / CC) - mu * mu;
    const float rstd = rsqrtf(var + 1e-5f);

    const float y0 = (v0 - mu) * rstd * g[tid]       + b[tid];
    const float y1 = (v1 - mu) * rstd * g[tid + 256] + b[tid + 256];
    const float y2 = (v2 - mu) * rstd * g[tid + 512] + b[tid + 512];

    float* orow = out + (size_t)row * CC;
    orow[tid] = y0; orow[tid + 256] = y1; orow[tid + 512] = y2;
    if (outr) {
        float* rrow = outr + (size_t)row * CC;
        rrow[tid] = rndf(y0); rrow[tid + 256] = rndf(y1); rrow[tid + 512] = rndf(y2);
    }
}

// ---------------- launch ------------------------------------------------------
extern "C" void kernel_launch(void* const* d_in, const int* in_sizes, int n_in,
                              void* d_out, int out_size)
{
    const float* x      = (const float*)d_in[0];
    const float* enc    = (const float*)d_in[1];
    const float* ln1_g  = (const float*)d_in[2];
    const float* ln1_b  = (const float*)d_in[3];
    const float* qkv_w  = (const float*)d_in[4];
    const float* qkv_b  = (const float*)d_in[5];
    const float* proj_w = (const float*)d_in[6];
    const float* proj_b = (const float*)d_in[7];
    const float* ln2_g  = (const float*)d_in[8];
    const float* ln2_b  = (const float*)d_in[9];
    const float* caq_w  = (const float*)d_in[10];
    const float* caq_b  = (const float*)d_in[11];
    const float* cak_w  = (const float*)d_in[12];
    const float* cak_b  = (const float*)d_in[13];
    const float* cav_w  = (const float*)d_in[14];
    const float* cav_b  = (const float*)d_in[15];
    const float* cao_w  = (const float*)d_in[16];
    const float* cao_b  = (const float*)d_in[17];
    const float* ln3_g  = (const float*)d_in[18];
    const float* ln3_b  = (const float*)d_in[19];
    const float* fc_w   = (const float*)d_in[20];
    const float* fc_b   = (const float*)d_in[21];
    const float* fc2_w  = (const float*)d_in[22];
    const float* fc2_b  = (const float*)d_in[23];
    float* out = (float*)d_out;

    float *qkv, *att, *res, *x1, *cq, *ck, *cv, *x2, *hbuf;
    float *xr, *encr, *x1r, *x2r, *wq, *wp, *wcq, *wck, *wcv, *wco, *wfc, *wfc2;
    cudaGetSymbolAddress((void**)&qkv,  g_qkv);
    cudaGetSymbolAddress((void**)&att,  g_att);
    cudaGetSymbolAddress((void**)&res,  g_res);
    cudaGetSymbolAddress((void**)&x1,   g_x1);
    cudaGetSymbolAddress((void**)&cq,   g_cq);
    cudaGetSymbolAddress((void**)&ck,   g_ck);
    cudaGetSymbolAddress((void**)&cv,   g_cv);
    cudaGetSymbolAddress((void**)&x2,   g_x2);
    cudaGetSymbolAddress((void**)&hbuf, g_h);
    cudaGetSymbolAddress((void**)&xr,   g_xr);
    cudaGetSymbolAddress((void**)&encr, g_encr);
    cudaGetSymbolAddress((void**)&x1r,  g_x1r);
    cudaGetSymbolAddress((void**)&x2r,  g_x2r);
    cudaGetSymbolAddress((void**)&wq,   g_wq);
    cudaGetSymbolAddress((void**)&wp,   g_wp);
    cudaGetSymbolAddress((void**)&wcq,  g_wcq);
    cudaGetSymbolAddress((void**)&wck,  g_wck);
    cudaGetSymbolAddress((void**)&wcv,  g_wcv);
    cudaGetSymbolAddress((void**)&wco,  g_wco);
    cudaGetSymbolAddress((void**)&wfc,  g_wfc);
    cudaGetSymbolAddress((void**)&wfc2, g_wfc2);

    cudaFuncSetAttribute(attn_mma<true>,
                         cudaFuncAttributeMaxDynamicSharedMemorySize, AT_SMEM);
    cudaFuncSetAttribute(attn_mma<false>,
                         cudaFuncAttributeMaxDynamicSharedMemorySize, AT_SMEM);
    cudaFuncSetAttribute((const void*)tgemm_bias<EPI_NONE, 1>,
                         cudaFuncAttributeMaxDynamicSharedMemorySize, GSMEM);
    cudaFuncSetAttribute((const void*)tgemm_bias<EPI_RELU, 1>,
                         cudaFuncAttributeMaxDynamicSharedMemorySize, GSMEM);
    cudaFuncSetAttribute((const void*)tgemm_bias<EPI_RES, 0>,
                         cudaFuncAttributeMaxDynamicSharedMemorySize, GSMEM);
    cudaFuncSetAttribute((const void*)tgemm3,
                         cudaFuncAttributeMaxDynamicSharedMemorySize, GSMEM);

    const dim3 thr(256);
    const dim3 g768(CC / 128, MROWS / 128);
    const dim3 gqkv(3 * CC / 128, MROWS / 128);
    const dim3 gfc(4 * CC / 128, MROWS / 128);
    const dim3 g3(CC / 128, MROWS / 128, 3);
    const dim3 gattn(TT / 128, HH, BB);

    // 0) pre-round x, enc, and all weight matrices (tf32 RNA)
    round_all<<<15360, thr>>>(x, enc, qkv_w, proj_w, caq_w, cak_w, cav_w,
                              cao_w, fc_w, fc2_w,
                              xr, encr, wq, wp, wcq, wck, wcv, wco, wfc, wfc2);

    tgemm_bias<EPI_NONE, 1><<<gqkv, thr, GSMEM>>>(xr, wq, qkv_b, nullptr, qkv,
                                                  MROWS, 3 * CC, CC);
    attn_mma<true><<<gattn, thr, AT_SMEM>>>(qkv, qkv + CC, qkv + 2 * CC, att,
                                            3 * CC, 3 * CC);
    tgemm_bias<EPI_RES, 0><<<g768, thr, GSMEM>>>(att, wp, proj_b, x, res,
                                                 MROWS, CC, CC);
    layernorm_k<<<MROWS, thr>>>(res, ln1_g, ln1_b, x1, x1r);

    tgemm3<<<g3, thr, GSMEM>>>(x1r, encr, wcq, caq_b, wck, cak_b,
                               wcv, cav_b, cq, ck, cv);

    attn_mma<false><<<gattn, thr, AT_SMEM>>>(cq, ck, cv, att, CC, CC);
    tgemm_bias<EPI_RES, 0><<<g768, thr, GSMEM>>>(att, wco, cao_b, x1, res,
                                                 MROWS, CC, CC);
    layernorm_k<<<MROWS, thr>>>(res, ln2_g, ln2_b, x2, x2r);

    tgemm_bias<EPI_RELU, 1><<<gfc, thr, GSMEM>>>(x2r, wfc, fc_b, nullptr, hbuf,
                                                 MROWS, 4 * CC, CC);
    tgemm_bias<EPI_RES, 0><<<g768, thr, GSMEM>>>(hbuf, wfc2, fc2_b, x2, res,
                                                 MROWS, CC, 4 * CC);
    layernorm_k<<<MROWS, thr>>>(res, ln3_g, ln3_b, out, nullptr);
}

// round 7
// speedup vs baseline: 13.0445x; 1.9548x over previous
#include <cuda_runtime.h>
#include <cuda_fp16.h>
#include <math.h>
#include <stdint.h>

#define BB 2
#define TT 2048
#define CC 768
#define HH 12
#define DD 64
#define MROWS (BB*TT)   // 4096

// ---------------- scratch ----------------------------------------------------
// fp32 residual-path buffers
__device__ float g_res[(size_t)MROWS * CC];
__device__ float g_x1 [(size_t)MROWS * CC];
__device__ float g_x2 [(size_t)MROWS * CC];
// fp16 operand buffers
__device__ __half g_x16  [(size_t)MROWS * CC];
__device__ __half g_enc16[(size_t)MROWS * CC];
__device__ __half g_qkv16[(size_t)MROWS * 3 * CC];   // q,k rowmajor (v cols unused)
__device__ __half g_vpk  [(size_t)MROWS * CC];       // v pair-packed [tok/2][768][2]
__device__ __half g_att16[(size_t)MROWS * CC];
__device__ __half g_x1r  [(size_t)MROWS * CC];
__device__ __half g_x2r  [(size_t)MROWS * CC];
__device__ __half g_cq16 [(size_t)MROWS * CC];
__device__ __half g_ck16 [(size_t)MROWS * CC];
__device__ __half g_cvp  [(size_t)MROWS * CC];       // cv pair-packed
__device__ __half g_h16  [(size_t)MROWS * 4 * CC];
// fp16 k-pair-packed weights, stored as u32 rows [K/2][N]
__device__ uint32_t g_wq  [(size_t)CC/2 * 3 * CC];
__device__ uint32_t g_wp  [(size_t)CC/2 * CC];
__device__ uint32_t g_wcq [(size_t)CC/2 * CC];
__device__ uint32_t g_wck [(size_t)CC/2 * CC];
__device__ uint32_t g_wcv [(size_t)CC/2 * CC];
__device__ uint32_t g_wco [(size_t)CC/2 * CC];
__device__ uint32_t g_wfc [(size_t)CC/2 * 4 * CC];
__device__ uint32_t g_wfc2[(size_t)4*CC/2 * CC];

enum { EPI_NONE = 0, EPI_RELU = 1, EPI_RES = 2 };
enum { OUT_F32 = 0, OUT_H = 1, OUT_QKV = 2, OUT_HP = 3 };

__device__ __forceinline__ void cp16(uint32_t s, const void* g) {
    asm volatile("cp.async.cg.shared.global [%0], [%1], 16;" :: "r"(s), "l"(g));
}
__device__ __forceinline__ void mma_f16(float* d, const uint32_t* a,
                                        const uint32_t* b) {
    asm volatile(
        "mma.sync.aligned.m16n8k16.row.col.f32.f16.f16.f32 "
        "{%0,%1,%2,%3}, {%4,%5,%6,%7}, {%8,%9}, {%0,%1,%2,%3};\n"
        : "+f"(d[0]), "+f"(d[1]), "+f"(d[2]), "+f"(d[3])
        : "r"(a[0]), "r"(a[1]), "r"(a[2]), "r"(a[3]), "r"(b[0]), "r"(b[1]));
}

// ---------------- pre-pass: fp16-convert + pack --------------------------------
// u32-output index space; activations pack along-row pairs, weights pack k-pairs.
#define S_X    1572864u
#define S_ENC  3145728u
#define S_WQ   4030464u
#define S_WP   4325376u
#define S_WCQ  4620288u
#define S_WCK  4915200u
#define S_WCV  5210112u
#define S_WCO  5505024u
#define S_WFC  6684672u
#define S_TOT  7864320u   // /256 = 30720 blocks

__global__ __launch_bounds__(256)
void round_pack(const float* x, const float* enc, const float* qw,
                const float* pw, const float* cqw, const float* ckw,
                const float* cvw, const float* cow, const float* fcw,
                const float* fc2w,
                __half* x16, __half* enc16, uint32_t* wq, uint32_t* wp,
                uint32_t* wcq, uint32_t* wck, uint32_t* wcv, uint32_t* wco,
                uint32_t* wfc, uint32_t* wfc2)
{
    const uint32_t i = blockIdx.x * 256u + threadIdx.x;
    if (i < S_ENC) {   // activations: contiguous pair
        const float* s; __half* d; uint32_t l;
        if (i < S_X) { s = x; d = x16; l = i; }
        else         { s = enc; d = enc16; l = i - S_X; }
        const float2 v = *(const float2*)(s + 2 * l);
        *(__half2*)(d + 2 * l) = __floats2half2_rn(v.x, v.y);
        return;
    }
    const float* s; uint32_t* d; uint32_t l, N;
    if      (i < S_WQ)  { s = qw;   d = wq;   l = i - S_ENC; N = 3*CC; }
    else if (i < S_WP)  { s = pw;   d = wp;   l = i - S_WQ;  N = CC; }
    else if (i < S_WCQ) { s = cqw;  d = wcq;  l = i - S_WP;  N = CC; }
    else if (i < S_WCK) { s = ckw;  d = wck;  l = i - S_WCQ; N = CC; }
    else if (i < S_WCV) { s = cvw;  d = wcv;  l = i - S_WCK; N = CC; }
    else if (i < S_WCO) { s = cow;  d = wco;  l = i - S_WCV; N = CC; }
    else if (i < S_WFC) { s = fcw;  d = wfc;  l = i - S_WCO; N = 4*CC; }
    else                { s = fc2w; d = wfc2; l = i - S_WFC; N = CC; }
    const uint32_t n = l % N, k2 = l / N;
    const float a = s[(size_t)(2*k2) * N + n];
    const float b = s[(size_t)(2*k2+1) * N + n];
    __half2 h = __floats2half2_rn(a, b);
    d[l] = *(uint32_t*)&h;
}

// ---------------- fp16 GEMM 128x128x64, mma m16n8k16, 3-stage cp.async -------
#define AS32 36                       // A row stride (u32): 32 data + 4 pad
#define BS32 136                      // B row stride (u32): 128 data + 8 pad
#define ABUF32 (128*AS32)             // 4608
#define STG32  (ABUF32 + 32*BS32)     // 8960 u32 / stage
#define GSMEM  (3*STG32*4)            // 107520 B

template<int EPI, int OUT>
__device__ __forceinline__
void tgemm_body(uint32_t* sm, const __half* __restrict__ Ah,
                const uint32_t* __restrict__ Bp, const float* __restrict__ bias,
                const float* __restrict__ res, float* __restrict__ Cf,
                __half* __restrict__ Ch, __half* __restrict__ Vp,
                int M, int N, int K, int mBase, int nBase)
{
    const int tid = threadIdx.x;
    const int lane = tid & 31, warp = tid >> 5;
    const int wm = warp >> 2, wn = warp & 3;
    const int r = lane >> 2, q = lane & 3;
    const uint32_t smemBase = (uint32_t)__cvta_generic_to_shared(sm);

    float acc[4][4][4];
    #pragma unroll
    for (int mt = 0; mt < 4; mt++)
        #pragma unroll
        for (int nt = 0; nt < 4; nt++)
            #pragma unroll
            for (int e = 0; e < 4; e++) acc[mt][nt][e] = 0.f;

    const int nchunk = K >> 6;   // K-chunk = 64

    auto issue = [&](int c) {
        if (c < nchunk) {
            const int kc = c << 6;          // fp16 k offset
            const int kc2 = c << 5;         // packed-row offset
            const uint32_t sb = smemBase + (uint32_t)((c % 3) * STG32 * 4);
            #pragma unroll
            for (int i = 0; i < 4; i++) {   // A tile 128x64 fp16 = 16KB : 4/thread
                const int fid = tid + (i << 8);
                const int row = fid >> 3, k4 = (fid & 7) << 2;   // u32 units
                cp16(sb + (uint32_t)((row * AS32 + k4) * 4),
                     Ah + (size_t)(mBase + row) * K + kc + (fid & 7) * 8);
            }
            #pragma unroll
            for (int i = 0; i < 4; i++) {   // B tile 32x128 u32 = 16KB : 4/thread
                const int fid = tid + (i << 8);
                const int kr = fid >> 5, nu = (fid & 31) << 2;
                cp16(sb + (uint32_t)((ABUF32 + kr * BS32 + nu) * 4),
                     Bp + (size_t)(kc2 + kr) * N + nBase + nu);
            }
        }
        asm volatile("cp.async.commit_group;");
    };

    issue(0);
    issue(1);

    for (int c = 0; c < nchunk; c++) {
        asm volatile("cp.async.wait_group 1;");
        __syncthreads();
        issue(c + 2);

        const uint32_t* As = sm + (c % 3) * STG32;
        const uint32_t* Bs = As + ABUF32;

        #pragma unroll
        for (int ks = 0; ks < 4; ks++) {
            uint32_t af[4][4], bf[4][2];
            #pragma unroll
            for (int mt = 0; mt < 4; mt++) {
                const int base = (wm * 64 + mt * 16 + r) * AS32 + ks * 8 + q;
                af[mt][0] = As[base];
                af[mt][1] = As[base + 8 * AS32];
                af[mt][2] = As[base + 4];
                af[mt][3] = As[base + 8 * AS32 + 4];
            }
            #pragma unroll
            for (int nt = 0; nt < 4; nt++) {
                const int base = (ks * 8 + q) * BS32 + wn * 32 + nt * 8 + r;
                bf[nt][0] = Bs[base];
                bf[nt][1] = Bs[base + 4 * BS32];
            }
            #pragma unroll
            for (int mt = 0; mt < 4; mt++)
                #pragma unroll
                for (int nt = 0; nt < 4; nt++)
                    mma_f16(acc[mt][nt], af[mt], bf[nt]);
        }
    }

    #pragma unroll
    for (int mt = 0; mt < 4; mt++) {
        const int row0 = mBase + wm * 64 + mt * 16 + r;
        #pragma unroll
        for (int nt = 0; nt < 4; nt++) {
            const int col = nBase + wn * 32 + nt * 8 + 2 * q;
            const float2 bv = *(const float2*)(bias + col);
            float2 v0 = make_float2(acc[mt][nt][0] + bv.x, acc[mt][nt][1] + bv.y);
            float2 v1 = make_float2(acc[mt][nt][2] + bv.x, acc[mt][nt][3] + bv.y);
            if (EPI == EPI_RELU) {
                v0.x = fmaxf(v0.x, 0.f); v0.y = fmaxf(v0.y, 0.f);
                v1.x = fmaxf(v1.x, 0.f); v1.y = fmaxf(v1.y, 0.f);
            }
            if (EPI == EPI_RES) {
                const float2 r0 = *(const float2*)(res + (size_t)row0 * N + col);
                const float2 r1 = *(const float2*)(res + (size_t)(row0 + 8) * N + col);
                v0.x += r0.x; v0.y += r0.y;
                v1.x += r1.x; v1.y += r1.y;
            }
            if (OUT == OUT_F32) {
                *(float2*)(Cf + (size_t)row0 * N + col) = v0;
                *(float2*)(Cf + (size_t)(row0 + 8) * N + col) = v1;
            }
            if (OUT == OUT_H || OUT == OUT_QKV) {
                *(__half2*)(Ch + (size_t)row0 * N + col) = __floats2half2_rn(v0.x, v0.y);
                *(__half2*)(Ch + (size_t)(row0 + 8) * N + col) = __floats2half2_rn(v1.x, v1.y);
            }
            if ((OUT == OUT_QKV && nBase >= 2 * CC) || OUT == OUT_HP) {
                const int vc = (OUT == OUT_QKV ? col - 2 * CC : col);
                const int p0 = row0 & 1;
                __half* b0 = Vp + ((size_t)(row0 >> 1) * CC + vc) * 2 + p0;
                __half* b1 = Vp + ((size_t)((row0 + 8) >> 1) * CC + vc) * 2 + p0;
                b0[0] = __float2half_rn(v0.x); b0[2] = __float2half_rn(v0.y);
                b1[0] = __float2half_rn(v1.x); b1[2] = __float2half_rn(v1.y);
            }
        }
    }
}

template<int EPI, int OUT>
__global__ __launch_bounds__(256, 2)
void tgemm(const __half* __restrict__ A, const uint32_t* __restrict__ Bp,
           const float* __restrict__ bias, const float* __restrict__ res,
           float* __restrict__ Cf, __half* __restrict__ Ch,
           __half* __restrict__ Vp, int M, int N, int K)
{
    extern __shared__ uint32_t sm32[];
    tgemm_body<EPI, OUT>(sm32, A, Bp, bias, res, Cf, Ch, Vp, M, N, K,
                         blockIdx.y * 128, blockIdx.x * 128);
}

// merged cq/ck/cv projections
__global__ __launch_bounds__(256, 2)
void tgemm3(const __half* __restrict__ x1r, const __half* __restrict__ encr,
            const uint32_t* qw, const float* qb,
            const uint32_t* kw, const float* kb,
            const uint32_t* vw, const float* vb,
            __half* cq, __half* ck, __half* cvp)
{
    extern __shared__ uint32_t sm32[];
    const int z = blockIdx.z;
    const int mB = blockIdx.y * 128, nB = blockIdx.x * 128;
    if (z == 0)
        tgemm_body<EPI_NONE, OUT_H>(sm32, x1r, qw, qb, nullptr, nullptr, cq,
                                    nullptr, MROWS, CC, CC, mB, nB);
    else if (z == 1)
        tgemm_body<EPI_NONE, OUT_H>(sm32, encr, kw, kb, nullptr, nullptr, ck,
                                    nullptr, MROWS, CC, CC, mB, nB);
    else
        tgemm_body<EPI_NONE, OUT_HP>(sm32, encr, vw, vb, nullptr, nullptr,
                                     nullptr, cvp, MROWS, CC, CC, mB, nB);
}

// ---------------- fp16 tensor-core flash attention ----------------------------
// Tile 128q x 64k, d=64, 8 warps (16 q-rows each), 3-stage KV cp.async.
// SMEM u32 layout: Qs[128][36] @0, Ps[128][36] @4608,
//   stages @9216: per stage K[64][36] then V[32][72] (4608 u32).
#define TQS 36
#define TVS 72
#define TSMP 4608
#define TSMKV 9216
#define TSTG 4608
#define AT_SMEM (23040*4)   // 92160 B -> 2 CTAs/SM

template<bool CAUSAL>
__global__ __launch_bounds__(256, 2)
void attn_h(const __half* __restrict__ Q, const __half* __restrict__ Kp,
            const __half* __restrict__ Vp, __half* __restrict__ O,
            int qstride, int kstride)
{
    extern __shared__ uint32_t sm32[];
    uint32_t* Qs = sm32;
    uint32_t* Ps = sm32 + TSMP;

    const int b = blockIdx.z, h = blockIdx.y, qt = blockIdx.x;
    const int tid = threadIdx.x;
    const int lane = tid & 31, warp = tid >> 5;
    const int r = lane >> 2, q = lane & 3;
    const int qbase = qt * 128;
    const int qw16 = warp * 16;
    const uint32_t smemBase = (uint32_t)__cvta_generic_to_shared(sm32);

    // Q tile: load fp16, scale by 0.125 (exact), store smem
    const __half2 hscale = __floats2half2_rn(0.125f, 0.125f);
    #pragma unroll
    for (int i = 0; i < 4; i++) {
        const int lin = tid + (i << 8);          // 0..1023
        const int row = lin >> 3, c8 = lin & 7;  // 8 fp16 per load
        float4 v = *(const float4*)(Q + (size_t)(b * TT + qbase + row) * qstride
                                    + h * DD + c8 * 8);
        __half2* hv = (__half2*)&v;
        #pragma unroll
        for (int e = 0; e < 4; e++) hv[e] = __hmul2(hv[e], hscale);
        *(float4*)(Qs + row * TQS + c8 * 4) = v;
    }

    const int nkt = CAUSAL ? (2 * qt + 2) : (TT / 64);

    auto issueKV = [&](int kt) {
        if (kt < nkt) {
            const int kb = kt * 64;
            const uint32_t sb = smemBase + (uint32_t)((TSMKV + (kt % 3) * TSTG) * 4);
            #pragma unroll
            for (int i = 0; i < 2; i++) {        // K: 512 cp16
                const int lin = tid + (i << 8);
                const int row = lin >> 3, c8 = lin & 7;
                cp16(sb + (uint32_t)((row * TQS + c8 * 4) * 4),
                     Kp + (size_t)(b * TT + kb + row) * kstride + h * DD + c8 * 8);
            }
            #pragma unroll
            for (int i = 0; i < 2; i++) {        // V: 512 cp16 (pair-packed)
                const int lin = tid + (i << 8);
                const int row = lin >> 4, c16 = lin & 15;
                cp16(sb + (uint32_t)((2304 + row * TVS + c16 * 4) * 4),
                     Vp + ((size_t)(b * TT + kb) / 2 + row) * (2 * CC)
                        + h * 2 * DD + c16 * 8);
            }
        }
        asm volatile("cp.async.commit_group;");
    };

    issueKV(0);
    issueKV(1);

    float oacc[8][4];
    float m0 = -1e30f, m1 = -1e30f, l0 = 0.f, l1 = 0.f;
    #pragma unroll
    for (int nt = 0; nt < 8; nt++)
        #pragma unroll
        for (int e = 0; e < 4; e++) oacc[nt][e] = 0.f;

    for (int kt = 0; kt < nkt; kt++) {
        asm volatile("cp.async.wait_group 1;");
        __syncthreads();
        issueKV(kt + 2);

        const uint32_t* Ks = sm32 + TSMKV + (kt % 3) * TSTG;
        const uint32_t* Vs = Ks + 2304;
        const int kbase = kt * 64;

        // ---- S = Q K^T ----
        float sacc[8][4];
        #pragma unroll
        for (int nt = 0; nt < 8; nt++)
            #pragma unroll
            for (int e = 0; e < 4; e++) sacc[nt][e] = 0.f;

        #pragma unroll
        for (int ks = 0; ks < 4; ks++) {
            uint32_t af[4];
            const uint32_t* qp = Qs + (qw16 + r) * TQS + ks * 8 + q;
            af[0] = qp[0];
            af[1] = qp[8 * TQS];
            af[2] = qp[4];
            af[3] = qp[8 * TQS + 4];
            #pragma unroll
            for (int nt = 0; nt < 8; nt++) {
                const uint32_t* kp = Ks + (nt * 8 + r) * TQS + ks * 8 + q;
                uint32_t bf[2] = { kp[0], kp[4] };
                mma_f16(sacc[nt], af, bf);
            }
        }

        if (CAUSAL && kbase + 63 > qbase + qw16) {
            const int row0 = qbase + qw16 + r, row1 = row0 + 8;
            #pragma unroll
            for (int nt = 0; nt < 8; nt++) {
                const int c0 = kbase + nt * 8 + 2 * q, c1 = c0 + 1;
                if (c0 > row0) sacc[nt][0] = -1e30f;
                if (c1 > row0) sacc[nt][1] = -1e30f;
                if (c0 > row1) sacc[nt][2] = -1e30f;
                if (c1 > row1) sacc[nt][3] = -1e30f;
            }
        }

        // ---- online softmax ----
        float rm0 = -1e30f, rm1 = -1e30f;
        #pragma unroll
        for (int nt = 0; nt < 8; nt++) {
            rm0 = fmaxf(rm0, fmaxf(sacc[nt][0], sacc[nt][1]));
            rm1 = fmaxf(rm1, fmaxf(sacc[nt][2], sacc[nt][3]));
        }
        rm0 = fmaxf(rm0, __shfl_xor_sync(0xffffffffu, rm0, 1));
        rm0 = fmaxf(rm0, __shfl_xor_sync(0xffffffffu, rm0, 2));
        rm1 = fmaxf(rm1, __shfl_xor_sync(0xffffffffu, rm1, 1));
        rm1 = fmaxf(rm1, __shfl_xor_sync(0xffffffffu, rm1, 2));

        const float mn0 = fmaxf(m0, rm0), mn1 = fmaxf(m1, rm1);
        const float cr0 = __expf(m0 - mn0), cr1 = __expf(m1 - mn1);
        m0 = mn0; m1 = mn1;

        float rs0 = 0.f, rs1 = 0.f;
        uint32_t* p0 = Ps + (qw16 + r) * TQS + q;
        uint32_t* p1 = p0 + 8 * TQS;
        #pragma unroll
        for (int nt = 0; nt < 8; nt++) {
            const float e00 = __expf(sacc[nt][0] - mn0);
            const float e01 = __expf(sacc[nt][1] - mn0);
            const float e10 = __expf(sacc[nt][2] - mn1);
            const float e11 = __expf(sacc[nt][3] - mn1);
            rs0 += e00 + e01;
            rs1 += e10 + e11;
            __half2 h0 = __floats2half2_rn(e00, e01);
            __half2 h1 = __floats2half2_rn(e10, e11);
            p0[nt * 4] = *(uint32_t*)&h0;
            p1[nt * 4] = *(uint32_t*)&h1;
        }
        rs0 += __shfl_xor_sync(0xffffffffu, rs0, 1);
        rs0 += __shfl_xor_sync(0xffffffffu, rs0, 2);
        rs1 += __shfl_xor_sync(0xffffffffu, rs1, 1);
        rs1 += __shfl_xor_sync(0xffffffffu, rs1, 2);
        l0 = l0 * cr0 + rs0;
        l1 = l1 * cr1 + rs1;

        #pragma unroll
        for (int nt = 0; nt < 8; nt++) {
            oacc[nt][0] *= cr0; oacc[nt][1] *= cr0;
            oacc[nt][2] *= cr1; oacc[nt][3] *= cr1;
        }

        __syncwarp();

        // ---- O += P V ----
        #pragma unroll
        for (int ks = 0; ks < 4; ks++) {
            uint32_t af[4];
            const uint32_t* pp = Ps + (qw16 + r) * TQS + ks * 8 + q;
            af[0] = pp[0];
            af[1] = pp[8 * TQS];
            af[2] = pp[4];
            af[3] = pp[8 * TQS + 4];
            #pragma unroll
            for (int nt = 0; nt < 8; nt++) {
                const uint32_t* vp = Vs + (ks * 8 + q) * TVS + nt * 8 + r;
                uint32_t bf[2] = { vp[0], vp[4 * TVS] };
                mma_f16(oacc[nt], af, bf);
            }
        }
        __syncwarp();
    }

    // epilogue -> fp16 rowmajor (feeds proj/cao GEMM A)
    const float inv0 = 1.f / l0, inv1 = 1.f / l1;
    const int row0 = qbase + qw16 + r;
    __half* og0 = O + (size_t)(b * TT + row0) * CC + h * DD + 2 * q;
    __half* og1 = O + (size_t)(b * TT + row0 + 8) * CC + h * DD + 2 * q;
    #pragma unroll
    for (int nt = 0; nt < 8; nt++) {
        *(__half2*)(og0 + nt * 8) = __floats2half2_rn(oacc[nt][0] * inv0,
                                                      oacc[nt][1] * inv0);
        *(__half2*)(og1 + nt * 8) = __floats2half2_rn(oacc[nt][2] * inv1,
                                                      oacc[nt][3] * inv1);
    }
}

// ---------------- LayerNorm (fp32 out + optional fp16 out) -------------------
__global__ __launch_bounds__(256)
void layernorm_k(const float* __restrict__ in, const float* __restrict__ g,
                 const float* __restrict__ b, float* __restrict__ out,
                 __half* __restrict__ outh)
{
    const int row = blockIdx.x;
    const int tid = threadIdx.x;
    const float* x = in + (size_t)row * CC;

    const float v0 = x[tid], v1 = x[tid + 256], v2 = x[tid + 512];
    float s = v0 + v1 + v2;
    float sq = v0 * v0 + v1 * v1 + v2 * v2;

    #pragma unroll
    for (int off = 16; off; off >>= 1) {
        s  += __shfl_xor_sync(0xffffffffu, s, off);
        sq += __shfl_xor_sync(0xffffffffu, sq, off);
    }
    __shared__ float red[16];
    const int wid = tid >> 5, lane = tid & 31;
    if (lane == 0) { red[wid] = s; red[wid + 8] = sq; }
    __syncthreads();

    float ts = 0.f, tq = 0.f;
    #pragma unroll
    for (int i = 0; i < 8; i++) { ts += red[i]; tq += red[i + 8]; }

    const float mu = ts * (1.f / CC);
    const float var = tq * (1.f / CC) - mu * mu;
    const float rstd = rsqrtf(var + 1e-5f);

    const float y0 = (v0 - mu) * rstd * g[tid]       + b[tid];
    const float y1 = (v1 - mu) * rstd * g[tid + 256] + b[tid + 256];
    const float y2 = (v2 - mu) * rstd * g[tid + 512] + b[tid + 512];

    float* orow = out + (size_t)row * CC;
    orow[tid] = y0; orow[tid + 256] = y1; orow[tid + 512] = y2;
    if (outh) {
        __half* hrow = outh + (size_t)row * CC;
        hrow[tid]       = __float2half_rn(y0);
        hrow[tid + 256] = __float2half_rn(y1);
        hrow[tid + 512] = __float2half_rn(y2);
    }
}

// ---------------- launch ------------------------------------------------------
extern "C" void kernel_launch(void* const* d_in, const int* in_sizes, int n_in,
                              void* d_out, int out_size)
{
    const float* x      = (const float*)d_in[0];
    const float* enc    = (const float*)d_in[1];
    const float* ln1_g  = (const float*)d_in[2];
    const float* ln1_b  = (const float*)d_in[3];
    const float* qkv_w  = (const float*)d_in[4];
    const float* qkv_b  = (const float*)d_in[5];
    const float* proj_w = (const float*)d_in[6];
    const float* proj_b = (const float*)d_in[7];
    const float* ln2_g  = (const float*)d_in[8];
    const float* ln2_b  = (const float*)d_in[9];
    const float* caq_w  = (const float*)d_in[10];
    const float* caq_b  = (const float*)d_in[11];
    const float* cak_w  = (const float*)d_in[12];
    const float* cak_b  = (const float*)d_in[13];
    const float* cav_w  = (const float*)d_in[14];
    const float* cav_b  = (const float*)d_in[15];
    const float* cao_w  = (const float*)d_in[16];
    const float* cao_b  = (const float*)d_in[17];
    const float* ln3_g  = (const float*)d_in[18];
    const float* ln3_b  = (const float*)d_in[19];
    const float* fc_w   = (const float*)d_in[20];
    const float* fc_b   = (const float*)d_in[21];
    const float* fc2_w  = (const float*)d_in[22];
    const float* fc2_b  = (const float*)d_in[23];
    float* out = (float*)d_out;

    float *res, *x1, *x2;
    __half *x16, *enc16, *qkv16, *vpk, *att16, *x1r, *x2r, *cq16, *ck16, *cvp, *h16;
    uint32_t *wq, *wp, *wcq, *wck, *wcv, *wco, *wfc, *wfc2;
    cudaGetSymbolAddress((void**)&res,   g_res);
    cudaGetSymbolAddress((void**)&x1,    g_x1);
    cudaGetSymbolAddress((void**)&x2,    g_x2);
    cudaGetSymbolAddress((void**)&x16,   g_x16);
    cudaGetSymbolAddress((void**)&enc16, g_enc16);
    cudaGetSymbolAddress((void**)&qkv16, g_qkv16);
    cudaGetSymbolAddress((void**)&vpk,   g_vpk);
    cudaGetSymbolAddress((void**)&att16, g_att16);
    cudaGetSymbolAddress((void**)&x1r,   g_x1r);
    cudaGetSymbolAddress((void**)&x2r,   g_x2r);
    cudaGetSymbolAddress((void**)&cq16,  g_cq16);
    cudaGetSymbolAddress((void**)&ck16,  g_ck16);
    cudaGetSymbolAddress((void**)&cvp,   g_cvp);
    cudaGetSymbolAddress((void**)&h16,   g_h16);
    cudaGetSymbolAddress((void**)&wq,    g_wq);
    cudaGetSymbolAddress((void**)&wp,    g_wp);
    cudaGetSymbolAddress((void**)&wcq,   g_wcq);
    cudaGetSymbolAddress((void**)&wck,   g_wck);
    cudaGetSymbolAddress((void**)&wcv,   g_wcv);
    cudaGetSymbolAddress((void**)&wco,   g_wco);
    cudaGetSymbolAddress((void**)&wfc,   g_wfc);
    cudaGetSymbolAddress((void**)&wfc2,  g_wfc2);

    cudaFuncSetAttribute(attn_h<true>,
                         cudaFuncAttributeMaxDynamicSharedMemorySize, AT_SMEM);
    cudaFuncSetAttribute(attn_h<false>,
                         cudaFuncAttributeMaxDynamicSharedMemorySize, AT_SMEM);
    cudaFuncSetAttribute((const void*)tgemm<EPI_NONE, OUT_QKV>,
                         cudaFuncAttributeMaxDynamicSharedMemorySize, GSMEM);
    cudaFuncSetAttribute((const void*)tgemm<EPI_RES, OUT_F32>,
                         cudaFuncAttributeMaxDynamicSharedMemorySize, GSMEM);
    cudaFuncSetAttribute((const void*)tgemm<EPI_RELU, OUT_H>,
                         cudaFuncAttributeMaxDynamicSharedMemorySize, GSMEM);
    cudaFuncSetAttribute((const void*)tgemm3,
                         cudaFuncAttributeMaxDynamicSharedMemorySize, GSMEM);

    const dim3 thr(256);
    const dim3 g768(CC / 128, MROWS / 128);          // (6,32)
    const dim3 gqkv(3 * CC / 128, MROWS / 128);      // (18,32)
    const dim3 gfc(4 * CC / 128, MROWS / 128);       // (24,32)
    const dim3 g3(CC / 128, MROWS / 128, 3);
    const dim3 gattn(TT / 128, HH, BB);              // (16,12,2)

    // 0) fp16 convert + pack
    round_pack<<<S_TOT / 256, thr>>>(x, enc, qkv_w, proj_w, caq_w, cak_w,
                                     cav_w, cao_w, fc_w, fc2_w,
                                     x16, enc16, wq, wp, wcq, wck, wcv, wco,
                                     wfc, wfc2);

    // 1) qkv (fp16 rowmajor + packed V)
    tgemm<EPI_NONE, OUT_QKV><<<gqkv, thr, GSMEM>>>(x16, wq, qkv_b, nullptr,
                                                   nullptr, qkv16, vpk,
                                                   MROWS, 3 * CC, CC);
    // 2) causal self-attention
    attn_h<true><<<gattn, thr, AT_SMEM>>>(qkv16, qkv16 + CC, vpk, att16,
                                          3 * CC, 3 * CC);
    // 3) proj + residual -> res ; LN1
    tgemm<EPI_RES, OUT_F32><<<g768, thr, GSMEM>>>(att16, wp, proj_b, x, res,
                                                  nullptr, nullptr,
                                                  MROWS, CC, CC);
    layernorm_k<<<MROWS, thr>>>(res, ln1_g, ln1_b, x1, x1r);

    // 4) cross projections
    tgemm3<<<g3, thr, GSMEM>>>(x1r, enc16, wcq, caq_b, wck, cak_b,
                               wcv, cav_b, cq16, ck16, cvp);
    // 5) cross attention
    attn_h<false><<<gattn, thr, AT_SMEM>>>(cq16, ck16, cvp, att16, CC, CC);
    // 6) cao + residual ; LN2
    tgemm<EPI_RES, OUT_F32><<<g768, thr, GSMEM>>>(att16, wco, cao_b, x1, res,
                                                  nullptr, nullptr,
                                                  MROWS, CC, CC);
    layernorm_k<<<MROWS, thr>>>(res, ln2_g, ln2_b, x2, x2r);

    // 7) MLP
    tgemm<EPI_RELU, OUT_H><<<gfc, thr, GSMEM>>>(x2r, wfc, fc_b, nullptr,
                                                nullptr, h16, nullptr,
                                                MROWS, 4 * CC, CC);
    tgemm<EPI_RES, OUT_F32><<<g768, thr, GSMEM>>>(h16, wfc2, fc2_b, x2, res,
                                                  nullptr, nullptr,
                                                  MROWS, CC, 4 * CC);
    // 8) LN3 -> out
    layernorm_k<<<MROWS, thr>>>(res, ln3_g, ln3_b, out, nullptr);
}

// round 8
// speedup vs baseline: 13.6769x; 1.0485x over previous
#include <cuda_runtime.h>
#include <cuda_fp16.h>
#include <math.h>
#include <stdint.h>

#define BB 2
#define TT 2048
#define CC 768
#define HH 12
#define DD 64
#define MROWS (BB*TT)   // 4096

// ---------------- scratch ----------------------------------------------------
__device__ float g_res[(size_t)MROWS * CC];
__device__ float g_x1 [(size_t)MROWS * CC];
__device__ float g_x2 [(size_t)MROWS * CC];
__device__ __half g_x16  [(size_t)MROWS * CC];
__device__ __half g_enc16[(size_t)MROWS * CC];
__device__ __half g_qkv16[(size_t)MROWS * 3 * CC];
__device__ __half g_vpk  [(size_t)MROWS * CC];       // v pair-packed [tok/2][768][2]
__device__ __half g_att16[(size_t)MROWS * CC];
__device__ __half g_x1r  [(size_t)MROWS * CC];
__device__ __half g_x2r  [(size_t)MROWS * CC];
__device__ __half g_cq16 [(size_t)MROWS * CC];
__device__ __half g_ck16 [(size_t)MROWS * CC];
__device__ __half g_cvp  [(size_t)MROWS * CC];
__device__ __half g_h16  [(size_t)MROWS * 4 * CC];
// fp16 weights TRANSPOSED to [N][K], k-pair-packed as u32 [N][K/2]
__device__ uint32_t g_wq  [(size_t)3*CC * CC/2];
__device__ uint32_t g_wp  [(size_t)CC * CC/2];
__device__ uint32_t g_wcq [(size_t)CC * CC/2];
__device__ uint32_t g_wck [(size_t)CC * CC/2];
__device__ uint32_t g_wcv [(size_t)CC * CC/2];
__device__ uint32_t g_wco [(size_t)CC * CC/2];
__device__ uint32_t g_wfc [(size_t)4*CC * CC/2];
__device__ uint32_t g_wfc2[(size_t)CC * 4*CC/2];

enum { EPI_NONE = 0, EPI_RELU = 1, EPI_RES = 2 };
enum { OUT_F32 = 0, OUT_H = 1, OUT_QKV = 2, OUT_HP = 3 };

__device__ __forceinline__ void cp16(uint32_t s, const void* g) {
    asm volatile("cp.async.cg.shared.global [%0], [%1], 16;" :: "r"(s), "l"(g));
}
__device__ __forceinline__ void ldsm4(uint32_t* d, uint32_t addr) {
    asm volatile("ldmatrix.sync.aligned.m8n8.x4.shared.b16 {%0,%1,%2,%3}, [%4];"
        : "=r"(d[0]), "=r"(d[1]), "=r"(d[2]), "=r"(d[3]) : "r"(addr));
}
__device__ __forceinline__ void mma_f16(float* d, const uint32_t* a,
                                        uint32_t b0, uint32_t b1) {
    asm volatile(
        "mma.sync.aligned.m16n8k16.row.col.f32.f16.f16.f32 "
        "{%0,%1,%2,%3}, {%4,%5,%6,%7}, {%8,%9}, {%0,%1,%2,%3};\n"
        : "+f"(d[0]), "+f"(d[1]), "+f"(d[2]), "+f"(d[3])
        : "r"(a[0]), "r"(a[1]), "r"(a[2]), "r"(a[3]), "r"(b0), "r"(b1));
}

// ---------------- pre-pass 1: activations fp32 -> fp16 ------------------------
#define S_X 1572864u       // pair count per tensor
__global__ __launch_bounds__(256)
void act16(const float* x, const float* enc, __half* x16, __half* enc16)
{
    const uint32_t i = blockIdx.x * 256u + threadIdx.x;   // < 2*S_X
    const float* s; __half* d; uint32_t l;
    if (i < S_X) { s = x;   d = x16;   l = i; }
    else         { s = enc; d = enc16; l = i - S_X; }
    const float2 v = *(const float2*)(s + 2 * l);
    *(__half2*)(d + 2 * l) = __floats2half2_rn(v.x, v.y);
}

// ---------------- pre-pass 2: weight transpose+pack  W[K][N] -> Wt[N][K/2 u32]
// 32x32 tiles; tile ids flat across all 8 weights.
__global__ __launch_bounds__(256)
void wtrans(const float* qw, const float* pw, const float* cqw,
            const float* ckw, const float* cvw, const float* cow,
            const float* fcw, const float* fc2w,
            uint32_t* wq, uint32_t* wp, uint32_t* wcq, uint32_t* wck,
            uint32_t* wcv, uint32_t* wco, uint32_t* wfc, uint32_t* wfc2)
{
    __shared__ float s[32][33];
    const uint32_t t = blockIdx.x;
    const float* src; uint32_t* dst; uint32_t K, N, lt;
    if      (t < 1728u) { src = qw;   dst = wq;   K = 768;  N = 2304; lt = t; }
    else if (t < 2304u) { src = pw;   dst = wp;   K = 768;  N = 768;  lt = t - 1728u; }
    else if (t < 2880u) { src = cqw;  dst = wcq;  K = 768;  N = 768;  lt = t - 2304u; }
    else if (t < 3456u) { src = ckw;  dst = wck;  K = 768;  N = 768;  lt = t - 2880u; }
    else if (t < 4032u) { src = cvw;  dst = wcv;  K = 768;  N = 768;  lt = t - 3456u; }
    else if (t < 4608u) { src = cow;  dst = wco;  K = 768;  N = 768;  lt = t - 4032u; }
    else if (t < 6912u) { src = fcw;  dst = wfc;  K = 768;  N = 3072; lt = t - 4608u; }
    else                { src = fc2w; dst = wfc2; K = 3072; N = 768;  lt = t - 6912u; }
    const uint32_t KT = K >> 5;
    const uint32_t k0 = (lt % KT) << 5, n0 = (lt / KT) << 5;
    const int tx = threadIdx.x & 31, ty = threadIdx.x >> 5;
    #pragma unroll
    for (int j = 0; j < 4; j++)
        s[ty + j * 8][tx] = src[(size_t)(k0 + ty + j * 8) * N + n0 + tx];
    __syncthreads();
    #pragma unroll
    for (int j = 0; j < 2; j++) {
        const int idx = threadIdx.x + j * 256;
        const int n = idx >> 4, k2 = idx & 15;
        __half2 h = __floats2half2_rn(s[2 * k2][n], s[2 * k2 + 1][n]);
        dst[(size_t)(n0 + n) * (K >> 1) + (k0 >> 1) + k2] = *(uint32_t*)&h;
    }
}

// ---------------- fp16 GEMM (MT*32)x128x64, ldmatrix + 3-stage cp.async ------
// A smem [MT*32][36 u32], B smem [128 n-rows][36 u32] (both k-major rows).
template<int MT, int EPI, int OUT>
__device__ __forceinline__
void tgemm_body(uint32_t* sm, const __half* __restrict__ Ah,
                const uint32_t* __restrict__ Bt, const float* __restrict__ bias,
                const float* __restrict__ res, float* __restrict__ Cf,
                __half* __restrict__ Ch, __half* __restrict__ Vp,
                int M, int N, int K, int mBase, int nBase)
{
    constexpr int ABUF = MT * 32 * 36;
    constexpr int STG  = ABUF + 128 * 36;

    const int tid = threadIdx.x;
    const int lane = tid & 31, warp = tid >> 5;
    const int wm = warp >> 2, wn = warp & 3;
    const int r = lane >> 2, q = lane & 3;
    const int j8 = lane >> 3, t8 = lane & 7;
    const uint32_t smemBase = (uint32_t)__cvta_generic_to_shared(sm);
    const int K2 = K >> 1;

    float acc[MT][4][4];
    #pragma unroll
    for (int mt = 0; mt < MT; mt++)
        #pragma unroll
        for (int nt = 0; nt < 4; nt++)
            #pragma unroll
            for (int e = 0; e < 4; e++) acc[mt][nt][e] = 0.f;

    const int nchunk = K >> 6;

    auto issue = [&](int c) {
        if (c < nchunk) {
            const int kc = c << 6;          // fp16 k offset
            const int kc2 = c << 5;         // u32 k offset
            const uint32_t sb = smemBase + (uint32_t)((c % 3) * STG * 4);
            #pragma unroll
            for (int i = 0; i < MT; i++) {  // A tile MT*32 x 64 fp16
                const int fid = tid + (i << 8);
                const int row = fid >> 3, k4 = (fid & 7) << 2;
                cp16(sb + (uint32_t)((row * 36 + k4) * 4),
                     Ah + (size_t)(mBase + row) * K + kc + (fid & 7) * 8);
            }
            #pragma unroll
            for (int i = 0; i < 4; i++) {   // B tile 128 n-rows x 32 u32
                const int fid = tid + (i << 8);
                const int row = fid >> 3, k4 = (fid & 7) << 2;
                cp16(sb + (uint32_t)((ABUF + row * 36 + k4) * 4),
                     Bt + (size_t)(nBase + row) * K2 + kc2 + (fid & 7) * 4);
            }
        }
        asm volatile("cp.async.commit_group;");
    };

    issue(0);
    issue(1);

    for (int c = 0; c < nchunk; c++) {
        asm volatile("cp.async.wait_group 1;");
        __syncthreads();
        issue(c + 2);

        const uint32_t smA = smemBase + (uint32_t)((c % 3) * STG * 4);
        const uint32_t smB = smA + (uint32_t)(ABUF * 4);
        // lane-fixed ldmatrix address bases
        const uint32_t aBase = smA +
            (uint32_t)(((wm * (MT * 16) + (j8 & 1) * 8 + t8) * 36 + (j8 >> 1) * 4) * 4);
        const uint32_t bBase = smB +
            (uint32_t)(((wn * 32 + (j8 >> 1) * 8 + t8) * 36 + (j8 & 1) * 4) * 4);

        #pragma unroll
        for (int ks = 0; ks < 4; ks++) {
            uint32_t af[MT][4], bq[2][4];
            #pragma unroll
            for (int mt = 0; mt < MT; mt++)
                ldsm4(af[mt], aBase + (uint32_t)((mt * 16 * 36 + ks * 8) * 4));
            #pragma unroll
            for (int p = 0; p < 2; p++)
                ldsm4(bq[p], bBase + (uint32_t)((p * 16 * 36 + ks * 8) * 4));
            #pragma unroll
            for (int mt = 0; mt < MT; mt++)
                #pragma unroll
                for (int nt = 0; nt < 4; nt++)
                    mma_f16(acc[mt][nt], af[mt],
                            bq[nt >> 1][(nt & 1) * 2], bq[nt >> 1][(nt & 1) * 2 + 1]);
        }
    }

    #pragma unroll
    for (int mt = 0; mt < MT; mt++) {
        const int row0 = mBase + wm * (MT * 16) + mt * 16 + r;
        #pragma unroll
        for (int nt = 0; nt < 4; nt++) {
            const int col = nBase + wn * 32 + nt * 8 + 2 * q;
            const float2 bv = *(const float2*)(bias + col);
            float2 v0 = make_float2(acc[mt][nt][0] + bv.x, acc[mt][nt][1] + bv.y);
            float2 v1 = make_float2(acc[mt][nt][2] + bv.x, acc[mt][nt][3] + bv.y);
            if (EPI == EPI_RELU) {
                v0.x = fmaxf(v0.x, 0.f); v0.y = fmaxf(v0.y, 0.f);
                v1.x = fmaxf(v1.x, 0.f); v1.y = fmaxf(v1.y, 0.f);
            }
            if (EPI == EPI_RES) {
                const float2 r0 = *(const float2*)(res + (size_t)row0 * N + col);
                const float2 r1 = *(const float2*)(res + (size_t)(row0 + 8) * N + col);
                v0.x += r0.x; v0.y += r0.y;
                v1.x += r1.x; v1.y += r1.y;
            }
            if (OUT == OUT_F32) {
                *(float2*)(Cf + (size_t)row0 * N + col) = v0;
                *(float2*)(Cf + (size_t)(row0 + 8) * N + col) = v1;
            }
            if (OUT == OUT_H || OUT == OUT_QKV) {
                *(__half2*)(Ch + (size_t)row0 * N + col) = __floats2half2_rn(v0.x, v0.y);
                *(__half2*)(Ch + (size_t)(row0 + 8) * N + col) = __floats2half2_rn(v1.x, v1.y);
            }
            if ((OUT == OUT_QKV && nBase >= 2 * CC) || OUT == OUT_HP) {
                const int vc = (OUT == OUT_QKV ? col - 2 * CC : col);
                const int p0 = row0 & 1;
                __half* b0 = Vp + ((size_t)(row0 >> 1) * CC + vc) * 2 + p0;
                __half* b1 = Vp + ((size_t)((row0 + 8) >> 1) * CC + vc) * 2 + p0;
                b0[0] = __float2half_rn(v0.x); b0[2] = __float2half_rn(v0.y);
                b1[0] = __float2half_rn(v1.x); b1[2] = __float2half_rn(v1.y);
            }
        }
    }
}

template<int MT, int EPI, int OUT>
__global__ __launch_bounds__(256, 2)
void tgemm(const __half* __restrict__ A, const uint32_t* __restrict__ Bt,
           const float* __restrict__ bias, const float* __restrict__ res,
           float* __restrict__ Cf, __half* __restrict__ Ch,
           __half* __restrict__ Vp, int M, int N, int K)
{
    extern __shared__ uint32_t sm32[];
    tgemm_body<MT, EPI, OUT>(sm32, A, Bt, bias, res, Cf, Ch, Vp, M, N, K,
                             blockIdx.y * (MT * 32), blockIdx.x * 128);
}

// merged cq/ck/cv projections (MT=4)
__global__ __launch_bounds__(256, 2)
void tgemm3(const __half* __restrict__ x1r, const __half* __restrict__ encr,
            const uint32_t* qw, const float* qb,
            const uint32_t* kw, const float* kb,
            const uint32_t* vw, const float* vb,
            __half* cq, __half* ck, __half* cvp)
{
    extern __shared__ uint32_t sm32[];
    const int z = blockIdx.z;
    const int mB = blockIdx.y * 128, nB = blockIdx.x * 128;
    if (z == 0)
        tgemm_body<4, EPI_NONE, OUT_H>(sm32, x1r, qw, qb, nullptr, nullptr, cq,
                                       nullptr, MROWS, CC, CC, mB, nB);
    else if (z == 1)
        tgemm_body<4, EPI_NONE, OUT_H>(sm32, encr, kw, kb, nullptr, nullptr, ck,
                                       nullptr, MROWS, CC, CC, mB, nB);
    else
        tgemm_body<4, EPI_NONE, OUT_HP>(sm32, encr, vw, vb, nullptr, nullptr,
                                        nullptr, cvp, MROWS, CC, CC, mB, nB);
}

#define GSMEM4 (3*(4*32*36 + 128*36)*4)   // 110592 B
#define GSMEM2 (3*(2*32*36 + 128*36)*4)   // 82944 B

// ---------------- fp16 tensor-core flash attention (unchanged from R7) -------
#define TQS 36
#define TVS 72
#define TSMP 4608
#define TSMKV 9216
#define TSTG 4608
#define AT_SMEM (23040*4)   // 92160 B -> 2 CTAs/SM

__device__ __forceinline__ void mma_f16a(float* d, const uint32_t* a,
                                         const uint32_t* b) {
    mma_f16(d, a, b[0], b[1]);
}

template<bool CAUSAL>
__global__ __launch_bounds__(256, 2)
void attn_h(const __half* __restrict__ Q, const __half* __restrict__ Kp,
            const __half* __restrict__ Vp, __half* __restrict__ O,
            int qstride, int kstride)
{
    extern __shared__ uint32_t sm32[];
    uint32_t* Qs = sm32;
    uint32_t* Ps = sm32 + TSMP;

    const int b = blockIdx.z, h = blockIdx.y, qt = blockIdx.x;
    const int tid = threadIdx.x;
    const int lane = tid & 31, warp = tid >> 5;
    const int r = lane >> 2, q = lane & 3;
    const int qbase = qt * 128;
    const int qw16 = warp * 16;
    const uint32_t smemBase = (uint32_t)__cvta_generic_to_shared(sm32);

    const __half2 hscale = __floats2half2_rn(0.125f, 0.125f);
    #pragma unroll
    for (int i = 0; i < 4; i++) {
        const int lin = tid + (i << 8);
        const int row = lin >> 3, c8 = lin & 7;
        float4 v = *(const float4*)(Q + (size_t)(b * TT + qbase + row) * qstride
                                    + h * DD + c8 * 8);
        __half2* hv = (__half2*)&v;
        #pragma unroll
        for (int e = 0; e < 4; e++) hv[e] = __hmul2(hv[e], hscale);
        *(float4*)(Qs + row * TQS + c8 * 4) = v;
    }

    const int nkt = CAUSAL ? (2 * qt + 2) : (TT / 64);

    auto issueKV = [&](int kt) {
        if (kt < nkt) {
            const int kb = kt * 64;
            const uint32_t sb = smemBase + (uint32_t)((TSMKV + (kt % 3) * TSTG) * 4);
            #pragma unroll
            for (int i = 0; i < 2; i++) {
                const int lin = tid + (i << 8);
                const int row = lin >> 3, c8 = lin & 7;
                cp16(sb + (uint32_t)((row * TQS + c8 * 4) * 4),
                     Kp + (size_t)(b * TT + kb + row) * kstride + h * DD + c8 * 8);
            }
            #pragma unroll
            for (int i = 0; i < 2; i++) {
                const int lin = tid + (i << 8);
                const int row = lin >> 4, c16 = lin & 15;
                cp16(sb + (uint32_t)((2304 + row * TVS + c16 * 4) * 4),
                     Vp + ((size_t)(b * TT + kb) / 2 + row) * (2 * CC)
                        + h * 2 * DD + c16 * 8);
            }
        }
        asm volatile("cp.async.commit_group;");
    };

    issueKV(0);
    issueKV(1);

    float oacc[8][4];
    float m0 = -1e30f, m1 = -1e30f, l0 = 0.f, l1 = 0.f;
    #pragma unroll
    for (int nt = 0; nt < 8; nt++)
        #pragma unroll
        for (int e = 0; e < 4; e++) oacc[nt][e] = 0.f;

    for (int kt = 0; kt < nkt; kt++) {
        asm volatile("cp.async.wait_group 1;");
        __syncthreads();
        issueKV(kt + 2);

        const uint32_t* Ks = sm32 + TSMKV + (kt % 3) * TSTG;
        const uint32_t* Vs = Ks + 2304;
        const int kbase = kt * 64;

        float sacc[8][4];
        #pragma unroll
        for (int nt = 0; nt < 8; nt++)
            #pragma unroll
            for (int e = 0; e < 4; e++) sacc[nt][e] = 0.f;

        #pragma unroll
        for (int ks = 0; ks < 4; ks++) {
            uint32_t af[4];
            const uint32_t* qp = Qs + (qw16 + r) * TQS + ks * 8 + q;
            af[0] = qp[0];
            af[1] = qp[8 * TQS];
            af[2] = qp[4];
            af[3] = qp[8 * TQS + 4];
            #pragma unroll
            for (int nt = 0; nt < 8; nt++) {
                const uint32_t* kp = Ks + (nt * 8 + r) * TQS + ks * 8 + q;
                mma_f16(sacc[nt], af, kp[0], kp[4]);
            }
        }

        if (CAUSAL && kbase + 63 > qbase + qw16) {
            const int row0 = qbase + qw16 + r, row1 = row0 + 8;
            #pragma unroll
            for (int nt = 0; nt < 8; nt++) {
                const int c0 = kbase + nt * 8 + 2 * q, c1 = c0 + 1;
                if (c0 > row0) sacc[nt][0] = -1e30f;
                if (c1 > row0) sacc[nt][1] = -1e30f;
                if (c0 > row1) sacc[nt][2] = -1e30f;
                if (c1 > row1) sacc[nt][3] = -1e30f;
            }
        }

        float rm0 = -1e30f, rm1 = -1e30f;
        #pragma unroll
        for (int nt = 0; nt < 8; nt++) {
            rm0 = fmaxf(rm0, fmaxf(sacc[nt][0], sacc[nt][1]));
            rm1 = fmaxf(rm1, fmaxf(sacc[nt][2], sacc[nt][3]));
        }
        rm0 = fmaxf(rm0, __shfl_xor_sync(0xffffffffu, rm0, 1));
        rm0 = fmaxf(rm0, __shfl_xor_sync(0xffffffffu, rm0, 2));
        rm1 = fmaxf(rm1, __shfl_xor_sync(0xffffffffu, rm1, 1));
        rm1 = fmaxf(rm1, __shfl_xor_sync(0xffffffffu, rm1, 2));

        const float mn0 = fmaxf(m0, rm0), mn1 = fmaxf(m1, rm1);
        const float cr0 = __expf(m0 - mn0), cr1 = __expf(m1 - mn1);
        m0 = mn0; m1 = mn1;

        float rs0 = 0.f, rs1 = 0.f;
        uint32_t* p0 = Ps + (qw16 + r) * TQS + q;
        uint32_t* p1 = p0 + 8 * TQS;
        #pragma unroll
        for (int nt = 0; nt < 8; nt++) {
            const float e00 = __expf(sacc[nt][0] - mn0);
            const float e01 = __expf(sacc[nt][1] - mn0);
            const float e10 = __expf(sacc[nt][2] - mn1);
            const float e11 = __expf(sacc[nt][3] - mn1);
            rs0 += e00 + e01;
            rs1 += e10 + e11;
            __half2 h0 = __floats2half2_rn(e00, e01);
            __half2 h1 = __floats2half2_rn(e10, e11);
            p0[nt * 4] = *(uint32_t*)&h0;
            p1[nt * 4] = *(uint32_t*)&h1;
        }
        rs0 += __shfl_xor_sync(0xffffffffu, rs0, 1);
        rs0 += __shfl_xor_sync(0xffffffffu, rs0, 2);
        rs1 += __shfl_xor_sync(0xffffffffu, rs1, 1);
        rs1 += __shfl_xor_sync(0xffffffffu, rs1, 2);
        l0 = l0 * cr0 + rs0;
        l1 = l1 * cr1 + rs1;

        #pragma unroll
        for (int nt = 0; nt < 8; nt++) {
            oacc[nt][0] *= cr0; oacc[nt][1] *= cr0;
            oacc[nt][2] *= cr1; oacc[nt][3] *= cr1;
        }

        __syncwarp();

        #pragma unroll
        for (int ks = 0; ks < 4; ks++) {
            uint32_t af[4];
            const uint32_t* pp = Ps + (qw16 + r) * TQS + ks * 8 + q;
            af[0] = pp[0];
            af[1] = pp[8 * TQS];
            af[2] = pp[4];
            af[3] = pp[8 * TQS + 4];
            #pragma unroll
            for (int nt = 0; nt < 8; nt++) {
                const uint32_t* vp = Vs + (ks * 8 + q) * TVS + nt * 8 + r;
                mma_f16(oacc[nt], af, vp[0], vp[4 * TVS]);
            }
        }
        __syncwarp();
    }

    const float inv0 = 1.f / l0, inv1 = 1.f / l1;
    const int row0 = qbase + qw16 + r;
    __half* og0 = O + (size_t)(b * TT + row0) * CC + h * DD + 2 * q;
    __half* og1 = O + (size_t)(b * TT + row0 + 8) * CC + h * DD + 2 * q;
    #pragma unroll
    for (int nt = 0; nt < 8; nt++) {
        *(__half2*)(og0 + nt * 8) = __floats2half2_rn(oacc[nt][0] * inv0,
                                                      oacc[nt][1] * inv0);
        *(__half2*)(og1 + nt * 8) = __floats2half2_rn(oacc[nt][2] * inv1,
                                                      oacc[nt][3] * inv1);
    }
}

// ---------------- LayerNorm ---------------------------------------------------
__global__ __launch_bounds__(256)
void layernorm_k(const float* __restrict__ in, const float* __restrict__ g,
                 const float* __restrict__ b, float* __restrict__ out,
                 __half* __restrict__ outh)
{
    const int row = blockIdx.x;
    const int tid = threadIdx.x;
    const float* x = in + (size_t)row * CC;

    const float v0 = x[tid], v1 = x[tid + 256], v2 = x[tid + 512];
    float s = v0 + v1 + v2;
    float sq = v0 * v0 + v1 * v1 + v2 * v2;

    #pragma unroll
    for (int off = 16; off; off >>= 1) {
        s  += __shfl_xor_sync(0xffffffffu, s, off);
        sq += __shfl_xor_sync(0xffffffffu, sq, off);
    }
    __shared__ float red[16];
    const int wid = tid >> 5, lane = tid & 31;
    if (lane == 0) { red[wid] = s; red[wid + 8] = sq; }
    __syncthreads();

    float ts = 0.f, tq = 0.f;
    #pragma unroll
    for (int i = 0; i < 8; i++) { ts += red[i]; tq += red[i + 8]; }

    const float mu = ts * (1.f / CC);
    const float var = tq * (1.f / CC) - mu * mu;
    const float rstd = rsqrtf(var + 1e-5f);

    const float y0 = (v0 - mu) * rstd * g[tid]       + b[tid];
    const float y1 = (v1 - mu) * rstd * g[tid + 256] + b[tid + 256];
    const float y2 = (v2 - mu) * rstd * g[tid + 512] + b[tid + 512];

    float* orow = out + (size_t)row * CC;
    orow[tid] = y0; orow[tid + 256] = y1; orow[tid + 512] = y2;
    if (outh) {
        __half* hrow = outh + (size_t)row * CC;
        hrow[tid]       = __float2half_rn(y0);
        hrow[tid + 256] = __float2half_rn(y1);
        hrow[tid + 512] = __float2half_rn(y2);
    }
}

// ---------------- launch ------------------------------------------------------
extern "C" void kernel_launch(void* const* d_in, const int* in_sizes, int n_in,
                              void* d_out, int out_size)
{
    const float* x      = (const float*)d_in[0];
    const float* enc    = (const float*)d_in[1];
    const float* ln1_g  = (const float*)d_in[2];
    const float* ln1_b  = (const float*)d_in[3];
    const float* qkv_w  = (const float*)d_in[4];
    const float* qkv_b  = (const float*)d_in[5];
    const float* proj_w = (const float*)d_in[6];
    const float* proj_b = (const float*)d_in[7];
    const float* ln2_g  = (const float*)d_in[8];
    const float* ln2_b  = (const float*)d_in[9];
    const float* caq_w  = (const float*)d_in[10];
    const float* caq_b  = (const float*)d_in[11];
    const float* cak_w  = (const float*)d_in[12];
    const float* cak_b  = (const float*)d_in[13];
    const float* cav_w  = (const float*)d_in[14];
    const float* cav_b  = (const float*)d_in[15];
    const float* cao_w  = (const float*)d_in[16];
    const float* cao_b  = (const float*)d_in[17];
    const float* ln3_g  = (const float*)d_in[18];
    const float* ln3_b  = (const float*)d_in[19];
    const float* fc_w   = (const float*)d_in[20];
    const float* fc_b   = (const float*)d_in[21];
    const float* fc2_w  = (const float*)d_in[22];
    const float* fc2_b  = (const float*)d_in[23];
    float* out = (float*)d_out;

    float *res, *x1, *x2;
    __half *x16, *enc16, *qkv16, *vpk, *att16, *x1r, *x2r, *cq16, *ck16, *cvp, *h16;
    uint32_t *wq, *wp, *wcq, *wck, *wcv, *wco, *wfc, *wfc2;
    cudaGetSymbolAddress((void**)&res,   g_res);
    cudaGetSymbolAddress((void**)&x1,    g_x1);
    cudaGetSymbolAddress((void**)&x2,    g_x2);
    cudaGetSymbolAddress((void**)&x16,   g_x16);
    cudaGetSymbolAddress((void**)&enc16, g_enc16);
    cudaGetSymbolAddress((void**)&qkv16, g_qkv16);
    cudaGetSymbolAddress((void**)&vpk,   g_vpk);
    cudaGetSymbolAddress((void**)&att16, g_att16);
    cudaGetSymbolAddress((void**)&x1r,   g_x1r);
    cudaGetSymbolAddress((void**)&x2r,   g_x2r);
    cudaGetSymbolAddress((void**)&cq16,  g_cq16);
    cudaGetSymbolAddress((void**)&ck16,  g_ck16);
    cudaGetSymbolAddress((void**)&cvp,   g_cvp);
    cudaGetSymbolAddress((void**)&h16,   g_h16);
    cudaGetSymbolAddress((void**)&wq,    g_wq);
    cudaGetSymbolAddress((void**)&wp,    g_wp);
    cudaGetSymbolAddress((void**)&wcq,   g_wcq);
    cudaGetSymbolAddress((void**)&wck,   g_wck);
    cudaGetSymbolAddress((void**)&wcv,   g_wcv);
    cudaGetSymbolAddress((void**)&wco,   g_wco);
    cudaGetSymbolAddress((void**)&wfc,   g_wfc);
    cudaGetSymbolAddress((void**)&wfc2,  g_wfc2);

    cudaFuncSetAttribute(attn_h<true>,
                         cudaFuncAttributeMaxDynamicSharedMemorySize, AT_SMEM);
    cudaFuncSetAttribute(attn_h<false>,
                         cudaFuncAttributeMaxDynamicSharedMemorySize, AT_SMEM);
    cudaFuncSetAttribute((const void*)tgemm<4, EPI_NONE, OUT_QKV>,
                         cudaFuncAttributeMaxDynamicSharedMemorySize, GSMEM4);
    cudaFuncSetAttribute((const void*)tgemm<4, EPI_RELU, OUT_H>,
                         cudaFuncAttributeMaxDynamicSharedMemorySize, GSMEM4);
    cudaFuncSetAttribute((const void*)tgemm<2, EPI_RES, OUT_F32>,
                         cudaFuncAttributeMaxDynamicSharedMemorySize, GSMEM2);
    cudaFuncSetAttribute((const void*)tgemm3,
                         cudaFuncAttributeMaxDynamicSharedMemorySize, GSMEM4);

    const dim3 thr(256);
    const dim3 gqkv(3 * CC / 128, MROWS / 128);      // (18,32)
    const dim3 g768s(CC / 128, MROWS / 64);          // (6,64) MT=2
    const dim3 gfc(4 * CC / 128, MROWS / 128);       // (24,32)
    const dim3 g3(CC / 128, MROWS / 128, 3);         // (6,32,3)
    const dim3 gattn(TT / 128, HH, BB);              // (16,12,2)

    // 0) pre-passes
    act16<<<2 * S_X / 256, thr>>>(x, enc, x16, enc16);
    wtrans<<<9216, thr>>>(qkv_w, proj_w, caq_w, cak_w, cav_w, cao_w, fc_w, fc2_w,
                          wq, wp, wcq, wck, wcv, wco, wfc, wfc2);

    // 1) qkv
    tgemm<4, EPI_NONE, OUT_QKV><<<gqkv, thr, GSMEM4>>>(x16, wq, qkv_b, nullptr,
                                                       nullptr, qkv16, vpk,
                                                       MROWS, 3 * CC, CC);
    // 2) causal self-attention
    attn_h<true><<<gattn, thr, AT_SMEM>>>(qkv16, qkv16 + CC, vpk, att16,
                                          3 * CC, 3 * CC);
    // 3) proj + residual ; LN1
    tgemm<2, EPI_RES, OUT_F32><<<g768s, thr, GSMEM2>>>(att16, wp, proj_b, x, res,
                                                       nullptr, nullptr,
                                                       MROWS, CC, CC);
    layernorm_k<<<MROWS, thr>>>(res, ln1_g, ln1_b, x1, x1r);

    // 4) cross projections
    tgemm3<<<g3, thr, GSMEM4>>>(x1r, enc16, wcq, caq_b, wck, cak_b,
                                wcv, cav_b, cq16, ck16, cvp);
    // 5) cross attention
    attn_h<false><<<gattn, thr, AT_SMEM>>>(cq16, ck16, cvp, att16, CC, CC);
    // 6) cao + residual ; LN2
    tgemm<2, EPI_RES, OUT_F32><<<g768s, thr, GSMEM2>>>(att16, wco, cao_b, x1, res,
                                                       nullptr, nullptr,
                                                       MROWS, CC, CC);
    layernorm_k<<<MROWS, thr>>>(res, ln2_g, ln2_b, x2, x2r);

    // 7) MLP
    tgemm<4, EPI_RELU, OUT_H><<<gfc, thr, GSMEM4>>>(x2r, wfc, fc_b, nullptr,
                                                    nullptr, h16, nullptr,
                                                    MROWS, 4 * CC, CC);
    tgemm<2, EPI_RES, OUT_F32><<<g768s, thr, GSMEM2>>>(h16, wfc2, fc2_b, x2, res,
                                                       nullptr, nullptr,
                                                       MROWS, CC, 4 * CC);
    // 8) LN3 -> out
    layernorm_k<<<MROWS, thr>>>(res, ln3_g, ln3_b, out, nullptr);
}

// round 9
// speedup vs baseline: 14.5059x; 1.0606x over previous
#include <cuda_runtime.h>
#include <cuda_fp16.h>
#include <math.h>
#include <stdint.h>

#define BB 2
#define TT 2048
#define CC 768
#define HH 12
#define DD 64
#define MROWS (BB*TT)   // 4096
#define L2E 1.4426950408889634f

// ---------------- scratch ----------------------------------------------------
__device__ float g_res[(size_t)MROWS * CC];
__device__ float g_x1 [(size_t)MROWS * CC];
__device__ float g_x2 [(size_t)MROWS * CC];
__device__ __half g_x16  [(size_t)MROWS * CC];
__device__ __half g_enc16[(size_t)MROWS * CC];
__device__ __half g_qkv16[(size_t)MROWS * 3 * CC];
__device__ __half g_vt   [(size_t)BB * HH * DD * TT];   // V transposed [b][h][d][t]
__device__ __half g_att16[(size_t)MROWS * CC];
__device__ __half g_x1r  [(size_t)MROWS * CC];
__device__ __half g_x2r  [(size_t)MROWS * CC];
__device__ __half g_cq16 [(size_t)MROWS * CC];
__device__ __half g_ck16 [(size_t)MROWS * CC];
__device__ __half g_cvt  [(size_t)BB * HH * DD * TT];   // cross V transposed
__device__ __half g_h16  [(size_t)MROWS * 4 * CC];
// fp16 weights TRANSPOSED to [N][K], k-pair-packed as u32 [N][K/2]
__device__ uint32_t g_wq  [(size_t)3*CC * CC/2];
__device__ uint32_t g_wp  [(size_t)CC * CC/2];
__device__ uint32_t g_wcq [(size_t)CC * CC/2];
__device__ uint32_t g_wck [(size_t)CC * CC/2];
__device__ uint32_t g_wcv [(size_t)CC * CC/2];
__device__ uint32_t g_wco [(size_t)CC * CC/2];
__device__ uint32_t g_wfc [(size_t)4*CC * CC/2];
__device__ uint32_t g_wfc2[(size_t)CC * 4*CC/2];

enum { EPI_NONE = 0, EPI_RELU = 1, EPI_RES = 2 };
enum { OUT_F32 = 0, OUT_H = 1, OUT_QKV = 2, OUT_HP = 3 };

__device__ __forceinline__ void cp16(uint32_t s, const void* g) {
    asm volatile("cp.async.cg.shared.global [%0], [%1], 16;" :: "r"(s), "l"(g));
}
__device__ __forceinline__ void ldsm4(uint32_t* d, uint32_t addr) {
    asm volatile("ldmatrix.sync.aligned.m8n8.x4.shared.b16 {%0,%1,%2,%3}, [%4];"
        : "=r"(d[0]), "=r"(d[1]), "=r"(d[2]), "=r"(d[3]) : "r"(addr));
}
__device__ __forceinline__ void mma_f16(float* d, const uint32_t* a,
                                        uint32_t b0, uint32_t b1) {
    asm volatile(
        "mma.sync.aligned.m16n8k16.row.col.f32.f16.f16.f32 "
        "{%0,%1,%2,%3}, {%4,%5,%6,%7}, {%8,%9}, {%0,%1,%2,%3};\n"
        : "+f"(d[0]), "+f"(d[1]), "+f"(d[2]), "+f"(d[3])
        : "r"(a[0]), "r"(a[1]), "r"(a[2]), "r"(a[3]), "r"(b0), "r"(b1));
}
__device__ __forceinline__ float ex2(float x) {
    float y;
    asm("ex2.approx.f32 %0, %1;" : "=f"(y) : "f"(x));
    return y;
}

// ---------------- pre-pass 1: activations fp32 -> fp16 ------------------------
#define S_X 1572864u
__global__ __launch_bounds__(256)
void act16(const float* x, const float* enc, __half* x16, __half* enc16)
{
    const uint32_t i = blockIdx.x * 256u + threadIdx.x;
    const float* s; __half* d; uint32_t l;
    if (i < S_X) { s = x;   d = x16;   l = i; }
    else         { s = enc; d = enc16; l = i - S_X; }
    const float2 v = *(const float2*)(s + 2 * l);
    *(__half2*)(d + 2 * l) = __floats2half2_rn(v.x, v.y);
}

// ---------------- pre-pass 2: weight transpose+pack ---------------------------
__global__ __launch_bounds__(256)
void wtrans(const float* qw, const float* pw, const float* cqw,
            const float* ckw, const float* cvw, const float* cow,
            const float* fcw, const float* fc2w,
            uint32_t* wq, uint32_t* wp, uint32_t* wcq, uint32_t* wck,
            uint32_t* wcv, uint32_t* wco, uint32_t* wfc, uint32_t* wfc2)
{
    __shared__ float s[32][33];
    const uint32_t t = blockIdx.x;
    const float* src; uint32_t* dst; uint32_t K, N, lt;
    if      (t < 1728u) { src = qw;   dst = wq;   K = 768;  N = 2304; lt = t; }
    else if (t < 2304u) { src = pw;   dst = wp;   K = 768;  N = 768;  lt = t - 1728u; }
    else if (t < 2880u) { src = cqw;  dst = wcq;  K = 768;  N = 768;  lt = t - 2304u; }
    else if (t < 3456u) { src = ckw;  dst = wck;  K = 768;  N = 768;  lt = t - 2880u; }
    else if (t < 4032u) { src = cvw;  dst = wcv;  K = 768;  N = 768;  lt = t - 3456u; }
    else if (t < 4608u) { src = cow;  dst = wco;  K = 768;  N = 768;  lt = t - 4032u; }
    else if (t < 6912u) { src = fcw;  dst = wfc;  K = 768;  N = 3072; lt = t - 4608u; }
    else                { src = fc2w; dst = wfc2; K = 3072; N = 768;  lt = t - 6912u; }
    const uint32_t KT = K >> 5;
    const uint32_t k0 = (lt % KT) << 5, n0 = (lt / KT) << 5;
    const int tx = threadIdx.x & 31, ty = threadIdx.x >> 5;
    #pragma unroll
    for (int j = 0; j < 4; j++)
        s[ty + j * 8][tx] = src[(size_t)(k0 + ty + j * 8) * N + n0 + tx];
    __syncthreads();
    #pragma unroll
    for (int j = 0; j < 2; j++) {
        const int idx = threadIdx.x + j * 256;
        const int n = idx >> 4, k2 = idx & 15;
        __half2 h = __floats2half2_rn(s[2 * k2][n], s[2 * k2 + 1][n]);
        dst[(size_t)(n0 + n) * (K >> 1) + (k0 >> 1) + k2] = *(uint32_t*)&h;
    }
}

// ---------------- fp16 GEMM (MT*32)x128x64, ldmatrix + 3-stage cp.async ------
template<int MT, int EPI, int OUT>
__device__ __forceinline__
void tgemm_body(uint32_t* sm, const __half* __restrict__ Ah,
                const uint32_t* __restrict__ Bt, const float* __restrict__ bias,
                const float* __restrict__ res, float* __restrict__ Cf,
                __half* __restrict__ Ch, __half* __restrict__ Vp,
                int M, int N, int K, int mBase, int nBase)
{
    constexpr int ABUF = MT * 32 * 36;
    constexpr int STG  = ABUF + 128 * 36;

    const int tid = threadIdx.x;
    const int lane = tid & 31, warp = tid >> 5;
    const int wm = warp >> 2, wn = warp & 3;
    const int r = lane >> 2, q = lane & 3;
    const int j8 = lane >> 3, t8 = lane & 7;
    const uint32_t smemBase = (uint32_t)__cvta_generic_to_shared(sm);
    const int K2 = K >> 1;

    float acc[MT][4][4];
    #pragma unroll
    for (int mt = 0; mt < MT; mt++)
        #pragma unroll
        for (int nt = 0; nt < 4; nt++)
            #pragma unroll
            for (int e = 0; e < 4; e++) acc[mt][nt][e] = 0.f;

    const int nchunk = K >> 6;

    auto issue = [&](int c) {
        if (c < nchunk) {
            const int kc = c << 6;
            const int kc2 = c << 5;
            const uint32_t sb = smemBase + (uint32_t)((c % 3) * STG * 4);
            #pragma unroll
            for (int i = 0; i < MT; i++) {
                const int fid = tid + (i << 8);
                const int row = fid >> 3, k4 = (fid & 7) << 2;
                cp16(sb + (uint32_t)((row * 36 + k4) * 4),
                     Ah + (size_t)(mBase + row) * K + kc + (fid & 7) * 8);
            }
            #pragma unroll
            for (int i = 0; i < 4; i++) {
                const int fid = tid + (i << 8);
                const int row = fid >> 3, k4 = (fid & 7) << 2;
                cp16(sb + (uint32_t)((ABUF + row * 36 + k4) * 4),
                     Bt + (size_t)(nBase + row) * K2 + kc2 + (fid & 7) * 4);
            }
        }
        asm volatile("cp.async.commit_group;");
    };

    issue(0);
    issue(1);

    for (int c = 0; c < nchunk; c++) {
        asm volatile("cp.async.wait_group 1;");
        __syncthreads();
        issue(c + 2);

        const uint32_t smA = smemBase + (uint32_t)((c % 3) * STG * 4);
        const uint32_t smB = smA + (uint32_t)(ABUF * 4);
        const uint32_t aBase = smA +
            (uint32_t)(((wm * (MT * 16) + (j8 & 1) * 8 + t8) * 36 + (j8 >> 1) * 4) * 4);
        const uint32_t bBase = smB +
            (uint32_t)(((wn * 32 + (j8 >> 1) * 8 + t8) * 36 + (j8 & 1) * 4) * 4);

        #pragma unroll
        for (int ks = 0; ks < 4; ks++) {
            uint32_t af[MT][4], bq[2][4];
            #pragma unroll
            for (int mt = 0; mt < MT; mt++)
                ldsm4(af[mt], aBase + (uint32_t)((mt * 16 * 36 + ks * 8) * 4));
            #pragma unroll
            for (int p = 0; p < 2; p++)
                ldsm4(bq[p], bBase + (uint32_t)((p * 16 * 36 + ks * 8) * 4));
            #pragma unroll
            for (int mt = 0; mt < MT; mt++)
                #pragma unroll
                for (int nt = 0; nt < 4; nt++)
                    mma_f16(acc[mt][nt], af[mt],
                            bq[nt >> 1][(nt & 1) * 2], bq[nt >> 1][(nt & 1) * 2 + 1]);
        }
    }

    #pragma unroll
    for (int mt = 0; mt < MT; mt++) {
        const int row0 = mBase + wm * (MT * 16) + mt * 16 + r;
        #pragma unroll
        for (int nt = 0; nt < 4; nt++) {
            const int col = nBase + wn * 32 + nt * 8 + 2 * q;
            const float2 bv = *(const float2*)(bias + col);
            float2 v0 = make_float2(acc[mt][nt][0] + bv.x, acc[mt][nt][1] + bv.y);
            float2 v1 = make_float2(acc[mt][nt][2] + bv.x, acc[mt][nt][3] + bv.y);
            if (EPI == EPI_RELU) {
                v0.x = fmaxf(v0.x, 0.f); v0.y = fmaxf(v0.y, 0.f);
                v1.x = fmaxf(v1.x, 0.f); v1.y = fmaxf(v1.y, 0.f);
            }
            if (EPI == EPI_RES) {
                const float2 r0 = *(const float2*)(res + (size_t)row0 * N + col);
                const float2 r1 = *(const float2*)(res + (size_t)(row0 + 8) * N + col);
                v0.x += r0.x; v0.y += r0.y;
                v1.x += r1.x; v1.y += r1.y;
            }
            if (OUT == OUT_F32) {
                *(float2*)(Cf + (size_t)row0 * N + col) = v0;
                *(float2*)(Cf + (size_t)(row0 + 8) * N + col) = v1;
            }
            if (OUT == OUT_H || OUT == OUT_QKV) {
                *(__half2*)(Ch + (size_t)row0 * N + col) = __floats2half2_rn(v0.x, v0.y);
                *(__half2*)(Ch + (size_t)(row0 + 8) * N + col) = __floats2half2_rn(v1.x, v1.y);
            }
            if ((OUT == OUT_QKV && nBase >= 2 * CC) || OUT == OUT_HP) {
                // V transposed global: Vt[b][h][d][t]
                const int vc = (OUT == OUT_QKV ? col - 2 * CC : col);
                const int hh = vc >> 6, dd = vc & 63;
                const int bb = row0 >> 11, t = row0 & 2047;
                __half* vb = Vp + (((size_t)(bb * HH + hh) * DD + dd) << 11) + t;
                vb[0]           = __float2half_rn(v0.x);
                vb[TT]          = __float2half_rn(v0.y);
                vb[8]           = __float2half_rn(v1.x);
                vb[TT + 8]      = __float2half_rn(v1.y);
            }
        }
    }
}

template<int MT, int EPI, int OUT>
__global__ __launch_bounds__(256, 2)
void tgemm(const __half* __restrict__ A, const uint32_t* __restrict__ Bt,
           const float* __restrict__ bias, const float* __restrict__ res,
           float* __restrict__ Cf, __half* __restrict__ Ch,
           __half* __restrict__ Vp, int M, int N, int K)
{
    extern __shared__ uint32_t sm32[];
    tgemm_body<MT, EPI, OUT>(sm32, A, Bt, bias, res, Cf, Ch, Vp, M, N, K,
                             blockIdx.y * (MT * 32), blockIdx.x * 128);
}

__global__ __launch_bounds__(256, 2)
void tgemm3(const __half* __restrict__ x1r, const __half* __restrict__ encr,
            const uint32_t* qw, const float* qb,
            const uint32_t* kw, const float* kb,
            const uint32_t* vw, const float* vb,
            __half* cq, __half* ck, __half* cvt)
{
    extern __shared__ uint32_t sm32[];
    const int z = blockIdx.z;
    const int mB = blockIdx.y * 128, nB = blockIdx.x * 128;
    if (z == 0)
        tgemm_body<4, EPI_NONE, OUT_H>(sm32, x1r, qw, qb, nullptr, nullptr, cq,
                                       nullptr, MROWS, CC, CC, mB, nB);
    else if (z == 1)
        tgemm_body<4, EPI_NONE, OUT_H>(sm32, encr, kw, kb, nullptr, nullptr, ck,
                                       nullptr, MROWS, CC, CC, mB, nB);
    else
        tgemm_body<4, EPI_NONE, OUT_HP>(sm32, encr, vw, vb, nullptr, nullptr,
                                        nullptr, cvt, MROWS, CC, CC, mB, nB);
}

#define GSMEM4 (3*(4*32*36 + 128*36)*4)   // 110592 B
#define GSMEM2 (3*(2*32*36 + 128*36)*4)   // 82944 B

// ---------------- fp16 flash attention, full ldmatrix ------------------------
// Tile 128q x 64k, 8 warps x 16 q-rows, 3-stage KV cp.async.
// SMEM u32: Qs[128][36] @0, Ps[128][36] @4608, stages @9216:
//   per stage K[64 keys][36] then Vt[64 d][36] (4608 u32).
#define TQS 36
#define TSMP 4608
#define TSMKV 9216
#define TSTG 4608
#define AT_SMEM (23040*4)   // 92160 B -> 2 CTAs/SM

template<bool CAUSAL>
__global__ __launch_bounds__(256, 2)
void attn_h(const __half* __restrict__ Q, const __half* __restrict__ Kp,
            const __half* __restrict__ Vt, __half* __restrict__ O,
            int qstride, int kstride)
{
    extern __shared__ uint32_t sm32[];
    const int b = blockIdx.z, h = blockIdx.y;
    const int qt = CAUSAL ? (gridDim.x - 1 - blockIdx.x) : blockIdx.x;
    const int tid = threadIdx.x;
    const int lane = tid & 31, warp = tid >> 5;
    const int r = lane >> 2, q = lane & 3;
    const int j8 = lane >> 3, t8 = lane & 7;
    const int qbase = qt * 128;
    const int qw16 = warp * 16;
    const uint32_t smemBase = (uint32_t)__cvta_generic_to_shared(sm32);

    const int nkt = CAUSAL ? (2 * qt + 2) : (TT / 64);
    const __half* vtb = Vt + (((size_t)(b * HH + h) * DD) << 11);

    auto issueKV = [&](int kt) {
        if (kt < nkt) {
            const int kb = kt * 64;
            const uint32_t sb = smemBase + (uint32_t)((TSMKV + (kt % 3) * TSTG) * 4);
            #pragma unroll
            for (int i = 0; i < 2; i++) {        // K tile: rows = keys, k-major d
                const int lin = tid + (i << 8);
                const int row = lin >> 3, c8 = lin & 7;
                cp16(sb + (uint32_t)((row * 36 + c8 * 4) * 4),
                     Kp + (size_t)(b * TT + kb + row) * kstride + h * DD + c8 * 8);
            }
            #pragma unroll
            for (int i = 0; i < 2; i++) {        // V tile: rows = d, cols = tokens
                const int lin = tid + (i << 8);
                const int row = lin >> 3, c8 = lin & 7;
                cp16(sb + (uint32_t)((2304 + row * 36 + c8 * 4) * 4),
                     vtb + ((size_t)row << 11) + kb + c8 * 8);
            }
        }
        asm volatile("cp.async.commit_group;");
    };

    issueKV(0);
    issueKV(1);

    // Q tile: scale by 0.125 (exact), smem rows = q-token, k-major d
    uint32_t* Qs = sm32;
    const __half2 hscale = __floats2half2_rn(0.125f, 0.125f);
    #pragma unroll
    for (int i = 0; i < 4; i++) {
        const int lin = tid + (i << 8);
        const int row = lin >> 3, c8 = lin & 7;
        float4 v = *(const float4*)(Q + (size_t)(b * TT + qbase + row) * qstride
                                    + h * DD + c8 * 8);
        __half2* hv = (__half2*)&v;
        #pragma unroll
        for (int e = 0; e < 4; e++) hv[e] = __hmul2(hv[e], hscale);
        *(float4*)(Qs + row * TQS + c8 * 4) = v;
    }

    // lane-fixed ldmatrix bases
    const uint32_t aQ = smemBase +
        (uint32_t)(((qw16 + (j8 & 1) * 8 + t8) * TQS + (j8 >> 1) * 4) * 4);
    const uint32_t aP = smemBase +
        (uint32_t)((TSMP + (qw16 + (j8 & 1) * 8 + t8) * TQS + (j8 >> 1) * 4) * 4);
    const uint32_t bPat =
        (uint32_t)((((j8 >> 1) * 8 + t8) * 36 + (j8 & 1) * 4) * 4);

    float oacc[8][4];
    float m0 = -1e30f, m1 = -1e30f, l0 = 0.f, l1 = 0.f;
    #pragma unroll
    for (int nt = 0; nt < 8; nt++)
        #pragma unroll
        for (int e = 0; e < 4; e++) oacc[nt][e] = 0.f;

    for (int kt = 0; kt < nkt; kt++) {
        asm volatile("cp.async.wait_group 1;");
        __syncthreads();
        issueKV(kt + 2);

        const uint32_t smK = smemBase + (uint32_t)((TSMKV + (kt % 3) * TSTG) * 4);
        const uint32_t smV = smK + 2304 * 4;
        const int kbase = kt * 64;

        // ---- S = Q K^T (ldmatrix) ----
        float sacc[8][4];
        #pragma unroll
        for (int nt = 0; nt < 8; nt++)
            #pragma unroll
            for (int e = 0; e < 4; e++) sacc[nt][e] = 0.f;

        #pragma unroll
        for (int ks = 0; ks < 4; ks++) {
            uint32_t af[4], bk[4][4];
            ldsm4(af, aQ + (uint32_t)(ks * 32));
            #pragma unroll
            for (int p = 0; p < 4; p++)
                ldsm4(bk[p], smK + bPat + (uint32_t)((p * 16 * 36 + ks * 8) * 4));
            #pragma unroll
            for (int nt = 0; nt < 8; nt++)
                mma_f16(sacc[nt], af,
                        bk[nt >> 1][(nt & 1) * 2], bk[nt >> 1][(nt & 1) * 2 + 1]);
        }

        // ---- causal mask ----
        if (CAUSAL && kbase + 63 > qbase + qw16) {
            const int row0 = qbase + qw16 + r, row1 = row0 + 8;
            #pragma unroll
            for (int nt = 0; nt < 8; nt++) {
                const int c0 = kbase + nt * 8 + 2 * q, c1 = c0 + 1;
                if (c0 > row0) sacc[nt][0] = -1e30f;
                if (c1 > row0) sacc[nt][1] = -1e30f;
                if (c0 > row1) sacc[nt][2] = -1e30f;
                if (c1 > row1) sacc[nt][3] = -1e30f;
            }
        }

        // ---- online softmax (base-2 via fused fma+ex2) ----
        float rm0 = -1e30f, rm1 = -1e30f;
        #pragma unroll
        for (int nt = 0; nt < 8; nt++) {
            rm0 = fmaxf(rm0, fmaxf(sacc[nt][0], sacc[nt][1]));
            rm1 = fmaxf(rm1, fmaxf(sacc[nt][2], sacc[nt][3]));
        }
        rm0 = fmaxf(rm0, __shfl_xor_sync(0xffffffffu, rm0, 1));
        rm0 = fmaxf(rm0, __shfl_xor_sync(0xffffffffu, rm0, 2));
        rm1 = fmaxf(rm1, __shfl_xor_sync(0xffffffffu, rm1, 1));
        rm1 = fmaxf(rm1, __shfl_xor_sync(0xffffffffu, rm1, 2));

        const float mn0 = fmaxf(m0, rm0), mn1 = fmaxf(m1, rm1);
        const float mnl0 = mn0 * L2E, mnl1 = mn1 * L2E;
        const float cr0 = ex2(fmaf(m0, L2E, -mnl0));
        const float cr1 = ex2(fmaf(m1, L2E, -mnl1));
        m0 = mn0; m1 = mn1;

        float rs0 = 0.f, rs1 = 0.f;
        uint32_t* p0 = sm32 + TSMP + (qw16 + r) * TQS + q;
        uint32_t* p1 = p0 + 8 * TQS;
        #pragma unroll
        for (int nt = 0; nt < 8; nt++) {
            const float e00 = ex2(fmaf(sacc[nt][0], L2E, -mnl0));
            const float e01 = ex2(fmaf(sacc[nt][1], L2E, -mnl0));
            const float e10 = ex2(fmaf(sacc[nt][2], L2E, -mnl1));
            const float e11 = ex2(fmaf(sacc[nt][3], L2E, -mnl1));
            rs0 += e00 + e01;
            rs1 += e10 + e11;
            __half2 h0 = __floats2half2_rn(e00, e01);
            __half2 h1 = __floats2half2_rn(e10, e11);
            p0[nt * 4] = *(uint32_t*)&h0;
            p1[nt * 4] = *(uint32_t*)&h1;
        }
        rs0 += __shfl_xor_sync(0xffffffffu, rs0, 1);
        rs0 += __shfl_xor_sync(0xffffffffu, rs0, 2);
        rs1 += __shfl_xor_sync(0xffffffffu, rs1, 1);
        rs1 += __shfl_xor_sync(0xffffffffu, rs1, 2);
        l0 = l0 * cr0 + rs0;
        l1 = l1 * cr1 + rs1;

        #pragma unroll
        for (int nt = 0; nt < 8; nt++) {
            oacc[nt][0] *= cr0; oacc[nt][1] *= cr0;
            oacc[nt][2] *= cr1; oacc[nt][3] *= cr1;
        }

        __syncwarp();

        // ---- O += P V (ldmatrix) ----
        #pragma unroll
        for (int ks = 0; ks < 4; ks++) {
            uint32_t af[4], bv[4][4];
            ldsm4(af, aP + (uint32_t)(ks * 32));
            #pragma unroll
            for (int p = 0; p < 4; p++)
                ldsm4(bv[p], smV + bPat + (uint32_t)((p * 16 * 36 + ks * 8) * 4));
            #pragma unroll
            for (int nt = 0; nt < 8; nt++)
                mma_f16(oacc[nt], af,
                        bv[nt >> 1][(nt & 1) * 2], bv[nt >> 1][(nt & 1) * 2 + 1]);
        }
        __syncwarp();
    }

    const float inv0 = 1.f / l0, inv1 = 1.f / l1;
    const int row0 = qbase + qw16 + r;
    __half* og0 = O + (size_t)(b * TT + row0) * CC + h * DD + 2 * q;
    __half* og1 = O + (size_t)(b * TT + row0 + 8) * CC + h * DD + 2 * q;
    #pragma unroll
    for (int nt = 0; nt < 8; nt++) {
        *(__half2*)(og0 + nt * 8) = __floats2half2_rn(oacc[nt][0] * inv0,
                                                      oacc[nt][1] * inv0);
        *(__half2*)(og1 + nt * 8) = __floats2half2_rn(oacc[nt][2] * inv1,
                                                      oacc[nt][3] * inv1);
    }
}

// ---------------- LayerNorm ---------------------------------------------------
__global__ __launch_bounds__(256)
void layernorm_k(const float* __restrict__ in, const float* __restrict__ g,
                 const float* __restrict__ b, float* __restrict__ out,
                 __half* __restrict__ outh)
{
    const int row = blockIdx.x;
    const int tid = threadIdx.x;
    const float* x = in + (size_t)row * CC;

    const float v0 = x[tid], v1 = x[tid + 256], v2 = x[tid + 512];
    float s = v0 + v1 + v2;
    float sq = v0 * v0 + v1 * v1 + v2 * v2;

    #pragma unroll
    for (int off = 16; off; off >>= 1) {
        s  += __shfl_xor_sync(0xffffffffu, s, off);
        sq += __shfl_xor_sync(0xffffffffu, sq, off);
    }
    __shared__ float red[16];
    const int wid = tid >> 5, lane = tid & 31;
    if (lane == 0) { red[wid] = s; red[wid + 8] = sq; }
    __syncthreads();

    float ts = 0.f, tq = 0.f;
    #pragma unroll
    for (int i = 0; i < 8; i++) { ts += red[i]; tq += red[i + 8]; }

    const float mu = ts * (1.f / CC);
    const float var = tq * (1.f / CC) - mu * mu;
    const float rstd = rsqrtf(var + 1e-5f);

    const float y0 = (v0 - mu) * rstd * g[tid]       + b[tid];
    const float y1 = (v1 - mu) * rstd * g[tid + 256] + b[tid + 256];
    const float y2 = (v2 - mu) * rstd * g[tid + 512] + b[tid + 512];

    float* orow = out + (size_t)row * CC;
    orow[tid] = y0; orow[tid + 256] = y1; orow[tid + 512] = y2;
    if (outh) {
        __half* hrow = outh + (size_t)row * CC;
        hrow[tid]       = __float2half_rn(y0);
        hrow[tid + 256] = __float2half_rn(y1);
        hrow[tid + 512] = __float2half_rn(y2);
    }
}

// ---------------- launch ------------------------------------------------------
extern "C" void kernel_launch(void* const* d_in, const int* in_sizes, int n_in,
                              void* d_out, int out_size)
{
    const float* x      = (const float*)d_in[0];
    const float* enc    = (const float*)d_in[1];
    const float* ln1_g  = (const float*)d_in[2];
    const float* ln1_b  = (const float*)d_in[3];
    const float* qkv_w  = (const float*)d_in[4];
    const float* qkv_b  = (const float*)d_in[5];
    const float* proj_w = (const float*)d_in[6];
    const float* proj_b = (const float*)d_in[7];
    const float* ln2_g  = (const float*)d_in[8];
    const float* ln2_b  = (const float*)d_in[9];
    const float* caq_w  = (const float*)d_in[10];
    const float* caq_b  = (const float*)d_in[11];
    const float* cak_w  = (const float*)d_in[12];
    const float* cak_b  = (const float*)d_in[13];
    const float* cav_w  = (const float*)d_in[14];
    const float* cav_b  = (const float*)d_in[15];
    const float* cao_w  = (const float*)d_in[16];
    const float* cao_b  = (const float*)d_in[17];
    const float* ln3_g  = (const float*)d_in[18];
    const float* ln3_b  = (const float*)d_in[19];
    const float* fc_w   = (const float*)d_in[20];
    const float* fc_b   = (const float*)d_in[21];
    const float* fc2_w  = (const float*)d_in[22];
    const float* fc2_b  = (const float*)d_in[23];
    float* out = (float*)d_out;

    float *res, *x1, *x2;
    __half *x16, *enc16, *qkv16, *vt, *att16, *x1r, *x2r, *cq16, *ck16, *cvt, *h16;
    uint32_t *wq, *wp, *wcq, *wck, *wcv, *wco, *wfc, *wfc2;
    cudaGetSymbolAddress((void**)&res,   g_res);
    cudaGetSymbolAddress((void**)&x1,    g_x1);
    cudaGetSymbolAddress((void**)&x2,    g_x2);
    cudaGetSymbolAddress((void**)&x16,   g_x16);
    cudaGetSymbolAddress((void**)&enc16, g_enc16);
    cudaGetSymbolAddress((void**)&qkv16, g_qkv16);
    cudaGetSymbolAddress((void**)&vt,    g_vt);
    cudaGetSymbolAddress((void**)&att16, g_att16);
    cudaGetSymbolAddress((void**)&x1r,   g_x1r);
    cudaGetSymbolAddress((void**)&x2r,   g_x2r);
    cudaGetSymbolAddress((void**)&cq16,  g_cq16);
    cudaGetSymbolAddress((void**)&ck16,  g_ck16);
    cudaGetSymbolAddress((void**)&cvt,   g_cvt);
    cudaGetSymbolAddress((void**)&h16,   g_h16);
    cudaGetSymbolAddress((void**)&wq,    g_wq);
    cudaGetSymbolAddress((void**)&wp,    g_wp);
    cudaGetSymbolAddress((void**)&wcq,   g_wcq);
    cudaGetSymbolAddress((void**)&wck,   g_wck);
    cudaGetSymbolAddress((void**)&wcv,   g_wcv);
    cudaGetSymbolAddress((void**)&wco,   g_wco);
    cudaGetSymbolAddress((void**)&wfc,   g_wfc);
    cudaGetSymbolAddress((void**)&wfc2,  g_wfc2);

    cudaFuncSetAttribute(attn_h<true>,
                         cudaFuncAttributeMaxDynamicSharedMemorySize, AT_SMEM);
    cudaFuncSetAttribute(attn_h<false>,
                         cudaFuncAttributeMaxDynamicSharedMemorySize, AT_SMEM);
    cudaFuncSetAttribute((const void*)tgemm<4, EPI_NONE, OUT_QKV>,
                         cudaFuncAttributeMaxDynamicSharedMemorySize, GSMEM4);
    cudaFuncSetAttribute((const void*)tgemm<4, EPI_RELU, OUT_H>,
                         cudaFuncAttributeMaxDynamicSharedMemorySize, GSMEM4);
    cudaFuncSetAttribute((const void*)tgemm<2, EPI_RES, OUT_F32>,
                         cudaFuncAttributeMaxDynamicSharedMemorySize, GSMEM2);
    cudaFuncSetAttribute((const void*)tgemm3,
                         cudaFuncAttributeMaxDynamicSharedMemorySize, GSMEM4);

    const dim3 thr(256);
    const dim3 gqkv(3 * CC / 128, MROWS / 128);      // (18,32)
    const dim3 g768s(CC / 128, MROWS / 64);          // (6,64) MT=2
    const dim3 gfc(4 * CC / 128, MROWS / 128);       // (24,32)
    const dim3 g3(CC / 128, MROWS / 128, 3);         // (6,32,3)
    const dim3 gattn(TT / 128, HH, BB);              // (16,12,2)

    // 0) pre-passes
    act16<<<2 * S_X / 256, thr>>>(x, enc, x16, enc16);
    wtrans<<<9216, thr>>>(qkv_w, proj_w, caq_w, cak_w, cav_w, cao_w, fc_w, fc2_w,
                          wq, wp, wcq, wck, wcv, wco, wfc, wfc2);

    // 1) qkv (q,k rowmajor fp16 + V transposed)
    tgemm<4, EPI_NONE, OUT_QKV><<<gqkv, thr, GSMEM4>>>(x16, wq, qkv_b, nullptr,
                                                       nullptr, qkv16, vt,
                                                       MROWS, 3 * CC, CC);
    // 2) causal self-attention
    attn_h<true><<<gattn, thr, AT_SMEM>>>(qkv16, qkv16 + CC, vt, att16,
                                          3 * CC, 3 * CC);
    // 3) proj + residual ; LN1
    tgemm<2, EPI_RES, OUT_F32><<<g768s, thr, GSMEM2>>>(att16, wp, proj_b, x, res,
                                                       nullptr, nullptr,
                                                       MROWS, CC, CC);
    layernorm_k<<<MROWS, thr>>>(res, ln1_g, ln1_b, x1, x1r);

    // 4) cross projections (cv written transposed)
    tgemm3<<<g3, thr, GSMEM4>>>(x1r, enc16, wcq, caq_b, wck, cak_b,
                                wcv, cav_b, cq16, ck16, cvt);
    // 5) cross attention
    attn_h<false><<<gattn, thr, AT_SMEM>>>(cq16, ck16, cvt, att16, CC, CC);
    // 6) cao + residual ; LN2
    tgemm<2, EPI_RES, OUT_F32><<<g768s, thr, GSMEM2>>>(att16, wco, cao_b, x1, res,
                                                       nullptr, nullptr,
                                                       MROWS, CC, CC);
    layernorm_k<<<MROWS, thr>>>(res, ln2_g, ln2_b, x2, x2r);

    // 7) MLP
    tgemm<4, EPI_RELU, OUT_H><<<gfc, thr, GSMEM4>>>(x2r, wfc, fc_b, nullptr,
                                                    nullptr, h16, nullptr,
                                                    MROWS, 4 * CC, CC);
    tgemm<2, EPI_RES, OUT_F32><<<g768s, thr, GSMEM2>>>(h16, wfc2, fc2_b, x2, res,
                                                       nullptr, nullptr,
                                                       MROWS, CC, 4 * CC);
    // 8) LN3 -> out
    layernorm_k<<<MROWS, thr>>>(res, ln3_g, ln3_b, out, nullptr);
}

// round 10
// speedup vs baseline: 14.9051x; 1.0275x over previous
#include <cuda_runtime.h>
#include <cuda_fp16.h>
#include <math.h>
#include <stdint.h>

#define BB 2
#define TT 2048
#define CC 768
#define HH 12
#define DD 64
#define MROWS (BB*TT)   // 4096
#define L2E 1.4426950408889634f

// ---------------- scratch ----------------------------------------------------
__device__ float g_res[(size_t)MROWS * CC];
__device__ float g_x1 [(size_t)MROWS * CC];
__device__ float g_x2 [(size_t)MROWS * CC];
__device__ __half g_x16  [(size_t)MROWS * CC];
__device__ __half g_enc16[(size_t)MROWS * CC];
__device__ __half g_qkv16[(size_t)MROWS * 3 * CC];
__device__ __half g_vt   [(size_t)BB * HH * DD * TT];   // V transposed [b][h][d][t]
__device__ __half g_att16[(size_t)MROWS * CC];
__device__ __half g_x1r  [(size_t)MROWS * CC];
__device__ __half g_x2r  [(size_t)MROWS * CC];
__device__ __half g_cq16 [(size_t)MROWS * CC];
__device__ __half g_ck16 [(size_t)MROWS * CC];
__device__ __half g_cvt  [(size_t)BB * HH * DD * TT];   // cross V transposed
__device__ __half g_h16  [(size_t)MROWS * 4 * CC];
// fp16 weights TRANSPOSED to [N][K], k-pair-packed as u32 [N][K/2]
__device__ uint32_t g_wq  [(size_t)3*CC * CC/2];
__device__ uint32_t g_wp  [(size_t)CC * CC/2];
__device__ uint32_t g_wcq [(size_t)CC * CC/2];
__device__ uint32_t g_wck [(size_t)CC * CC/2];
__device__ uint32_t g_wcv [(size_t)CC * CC/2];
__device__ uint32_t g_wco [(size_t)CC * CC/2];
__device__ uint32_t g_wfc [(size_t)4*CC * CC/2];
__device__ uint32_t g_wfc2[(size_t)CC * 4*CC/2];

enum { EPI_NONE = 0, EPI_RELU = 1, EPI_RES = 2 };
enum { OUT_F32 = 0, OUT_H = 1, OUT_QKV = 2, OUT_HP = 3 };

__device__ __forceinline__ void cp16(uint32_t s, const void* g) {
    asm volatile("cp.async.cg.shared.global [%0], [%1], 16;" :: "r"(s), "l"(g));
}
__device__ __forceinline__ void ldsm4(uint32_t* d, uint32_t addr) {
    asm volatile("ldmatrix.sync.aligned.m8n8.x4.shared.b16 {%0,%1,%2,%3}, [%4];"
        : "=r"(d[0]), "=r"(d[1]), "=r"(d[2]), "=r"(d[3]) : "r"(addr));
}
__device__ __forceinline__ void mma_f16(float* d, const uint32_t* a,
                                        uint32_t b0, uint32_t b1) {
    asm volatile(
        "mma.sync.aligned.m16n8k16.row.col.f32.f16.f16.f32 "
        "{%0,%1,%2,%3}, {%4,%5,%6,%7}, {%8,%9}, {%0,%1,%2,%3};\n"
        : "+f"(d[0]), "+f"(d[1]), "+f"(d[2]), "+f"(d[3])
        : "r"(a[0]), "r"(a[1]), "r"(a[2]), "r"(a[3]), "r"(b0), "r"(b1));
}
__device__ __forceinline__ float ex2(float x) {
    float y;
    asm("ex2.approx.f32 %0, %1;" : "=f"(y) : "f"(x));
    return y;
}
__device__ __forceinline__ uint32_t ex2h2(uint32_t x) {
    uint32_t y;
    asm("ex2.approx.f16x2 %0, %1;" : "=r"(y) : "r"(x));
    return y;
}

// ---------------- merged pre-pass: act fp16 + weight transpose/pack ----------
#define S_X 1572864u          // fp16-pair count per activation tensor
#define ACT_BLKS 12288u       // 2*S_X/256

__global__ __launch_bounds__(256)
void prepack(const float* x, const float* enc, const float* qw,
             const float* pw, const float* cqw, const float* ckw,
             const float* cvw, const float* cow, const float* fcw,
             const float* fc2w,
             __half* x16, __half* enc16, uint32_t* wq, uint32_t* wp,
             uint32_t* wcq, uint32_t* wck, uint32_t* wcv, uint32_t* wco,
             uint32_t* wfc, uint32_t* wfc2)
{
    __shared__ float s[32][33];
    if (blockIdx.x < ACT_BLKS) {
        const uint32_t i = blockIdx.x * 256u + threadIdx.x;
        const float* sp; __half* d; uint32_t l;
        if (i < S_X) { sp = x;   d = x16;   l = i; }
        else         { sp = enc; d = enc16; l = i - S_X; }
        const float2 v = *(const float2*)(sp + 2 * l);
        *(__half2*)(d + 2 * l) = __floats2half2_rn(v.x, v.y);
        return;
    }
    const uint32_t t = blockIdx.x - ACT_BLKS;
    const float* src; uint32_t* dst; uint32_t K, N, lt;
    if      (t < 1728u) { src = qw;   dst = wq;   K = 768;  N = 2304; lt = t; }
    else if (t < 2304u) { src = pw;   dst = wp;   K = 768;  N = 768;  lt = t - 1728u; }
    else if (t < 2880u) { src = cqw;  dst = wcq;  K = 768;  N = 768;  lt = t - 2304u; }
    else if (t < 3456u) { src = ckw;  dst = wck;  K = 768;  N = 768;  lt = t - 2880u; }
    else if (t < 4032u) { src = cvw;  dst = wcv;  K = 768;  N = 768;  lt = t - 3456u; }
    else if (t < 4608u) { src = cow;  dst = wco;  K = 768;  N = 768;  lt = t - 4032u; }
    else if (t < 6912u) { src = fcw;  dst = wfc;  K = 768;  N = 3072; lt = t - 4608u; }
    else                { src = fc2w; dst = wfc2; K = 3072; N = 768;  lt = t - 6912u; }
    const uint32_t KT = K >> 5;
    const uint32_t k0 = (lt % KT) << 5, n0 = (lt / KT) << 5;
    const int tx = threadIdx.x & 31, ty = threadIdx.x >> 5;
    #pragma unroll
    for (int j = 0; j < 4; j++)
        s[ty + j * 8][tx] = src[(size_t)(k0 + ty + j * 8) * N + n0 + tx];
    __syncthreads();
    #pragma unroll
    for (int j = 0; j < 2; j++) {
        const int idx = threadIdx.x + j * 256;
        const int n = idx >> 4, k2 = idx & 15;
        __half2 h = __floats2half2_rn(s[2 * k2][n], s[2 * k2 + 1][n]);
        dst[(size_t)(n0 + n) * (K >> 1) + (k0 >> 1) + k2] = *(uint32_t*)&h;
    }
}

// ---------------- fp16 GEMM (MT*32)x128x64, ldmatrix + 3-stage cp.async ------
template<int MT, int EPI, int OUT>
__device__ __forceinline__
void tgemm_body(uint32_t* sm, const __half* __restrict__ Ah,
                const uint32_t* __restrict__ Bt, const float* __restrict__ bias,
                const float* __restrict__ res, float* __restrict__ Cf,
                __half* __restrict__ Ch, __half* __restrict__ Vp,
                int M, int N, int K, int mBase, int nBase)
{
    constexpr int ABUF = MT * 32 * 36;
    constexpr int STG  = ABUF + 128 * 36;

    const int tid = threadIdx.x;
    const int lane = tid & 31, warp = tid >> 5;
    const int wm = warp >> 2, wn = warp & 3;
    const int r = lane >> 2, q = lane & 3;
    const int j8 = lane >> 3, t8 = lane & 7;
    const uint32_t smemBase = (uint32_t)__cvta_generic_to_shared(sm);
    const int K2 = K >> 1;

    float acc[MT][4][4];
    #pragma unroll
    for (int mt = 0; mt < MT; mt++)
        #pragma unroll
        for (int nt = 0; nt < 4; nt++)
            #pragma unroll
            for (int e = 0; e < 4; e++) acc[mt][nt][e] = 0.f;

    const int nchunk = K >> 6;

    auto issue = [&](int c) {
        if (c < nchunk) {
            const int kc = c << 6;
            const int kc2 = c << 5;
            const uint32_t sb = smemBase + (uint32_t)((c % 3) * STG * 4);
            #pragma unroll
            for (int i = 0; i < MT; i++) {
                const int fid = tid + (i << 8);
                const int row = fid >> 3, k4 = (fid & 7) << 2;
                cp16(sb + (uint32_t)((row * 36 + k4) * 4),
                     Ah + (size_t)(mBase + row) * K + kc + (fid & 7) * 8);
            }
            #pragma unroll
            for (int i = 0; i < 4; i++) {
                const int fid = tid + (i << 8);
                const int row = fid >> 3, k4 = (fid & 7) << 2;
                cp16(sb + (uint32_t)((ABUF + row * 36 + k4) * 4),
                     Bt + (size_t)(nBase + row) * K2 + kc2 + (fid & 7) * 4);
            }
        }
        asm volatile("cp.async.commit_group;");
    };

    issue(0);
    issue(1);

    for (int c = 0; c < nchunk; c++) {
        asm volatile("cp.async.wait_group 1;");
        __syncthreads();
        issue(c + 2);

        const uint32_t smA = smemBase + (uint32_t)((c % 3) * STG * 4);
        const uint32_t smB = smA + (uint32_t)(ABUF * 4);
        const uint32_t aBase = smA +
            (uint32_t)(((wm * (MT * 16) + (j8 & 1) * 8 + t8) * 36 + (j8 >> 1) * 4) * 4);
        const uint32_t bBase = smB +
            (uint32_t)(((wn * 32 + (j8 >> 1) * 8 + t8) * 36 + (j8 & 1) * 4) * 4);

        #pragma unroll
        for (int ks = 0; ks < 4; ks++) {
            uint32_t af[MT][4], bq[2][4];
            #pragma unroll
            for (int mt = 0; mt < MT; mt++)
                ldsm4(af[mt], aBase + (uint32_t)((mt * 16 * 36 + ks * 8) * 4));
            #pragma unroll
            for (int p = 0; p < 2; p++)
                ldsm4(bq[p], bBase + (uint32_t)((p * 16 * 36 + ks * 8) * 4));
            #pragma unroll
            for (int mt = 0; mt < MT; mt++)
                #pragma unroll
                for (int nt = 0; nt < 4; nt++)
                    mma_f16(acc[mt][nt], af[mt],
                            bq[nt >> 1][(nt & 1) * 2], bq[nt >> 1][(nt & 1) * 2 + 1]);
        }
    }

    #pragma unroll
    for (int mt = 0; mt < MT; mt++) {
        const int row0 = mBase + wm * (MT * 16) + mt * 16 + r;
        #pragma unroll
        for (int nt = 0; nt < 4; nt++) {
            const int col = nBase + wn * 32 + nt * 8 + 2 * q;
            const float2 bv = *(const float2*)(bias + col);
            float2 v0 = make_float2(acc[mt][nt][0] + bv.x, acc[mt][nt][1] + bv.y);
            float2 v1 = make_float2(acc[mt][nt][2] + bv.x, acc[mt][nt][3] + bv.y);
            if (EPI == EPI_RELU) {
                v0.x = fmaxf(v0.x, 0.f); v0.y = fmaxf(v0.y, 0.f);
                v1.x = fmaxf(v1.x, 0.f); v1.y = fmaxf(v1.y, 0.f);
            }
            if (EPI == EPI_RES) {
                const float2 r0 = *(const float2*)(res + (size_t)row0 * N + col);
                const float2 r1 = *(const float2*)(res + (size_t)(row0 + 8) * N + col);
                v0.x += r0.x; v0.y += r0.y;
                v1.x += r1.x; v1.y += r1.y;
            }
            if (OUT == OUT_F32) {
                *(float2*)(Cf + (size_t)row0 * N + col) = v0;
                *(float2*)(Cf + (size_t)(row0 + 8) * N + col) = v1;
            }
            if (OUT == OUT_H || OUT == OUT_QKV) {
                *(__half2*)(Ch + (size_t)row0 * N + col) = __floats2half2_rn(v0.x, v0.y);
                *(__half2*)(Ch + (size_t)(row0 + 8) * N + col) = __floats2half2_rn(v1.x, v1.y);
            }
            if ((OUT == OUT_QKV && nBase >= 2 * CC) || OUT == OUT_HP) {
                const int vc = (OUT == OUT_QKV ? col - 2 * CC : col);
                const int hh = vc >> 6, dd = vc & 63;
                const int bb = row0 >> 11, t = row0 & 2047;
                __half* vb = Vp + (((size_t)(bb * HH + hh) * DD + dd) << 11) + t;
                vb[0]      = __float2half_rn(v0.x);
                vb[TT]     = __float2half_rn(v0.y);
                vb[8]      = __float2half_rn(v1.x);
                vb[TT + 8] = __float2half_rn(v1.y);
            }
        }
    }
}

template<int MT, int EPI, int OUT>
__global__ __launch_bounds__(256, 2)
void tgemm(const __half* __restrict__ A, const uint32_t* __restrict__ Bt,
           const float* __restrict__ bias, const float* __restrict__ res,
           float* __restrict__ Cf, __half* __restrict__ Ch,
           __half* __restrict__ Vp, int M, int N, int K)
{
    extern __shared__ uint32_t sm32[];
    tgemm_body<MT, EPI, OUT>(sm32, A, Bt, bias, res, Cf, Ch, Vp, M, N, K,
                             blockIdx.y * (MT * 32), blockIdx.x * 128);
}

__global__ __launch_bounds__(256, 2)
void tgemm3(const __half* __restrict__ x1r, const __half* __restrict__ encr,
            const uint32_t* qw, const float* qb,
            const uint32_t* kw, const float* kb,
            const uint32_t* vw, const float* vb,
            __half* cq, __half* ck, __half* cvt)
{
    extern __shared__ uint32_t sm32[];
    const int z = blockIdx.z;
    const int mB = blockIdx.y * 128, nB = blockIdx.x * 128;
    if (z == 0)
        tgemm_body<4, EPI_NONE, OUT_H>(sm32, x1r, qw, qb, nullptr, nullptr, cq,
                                       nullptr, MROWS, CC, CC, mB, nB);
    else if (z == 1)
        tgemm_body<4, EPI_NONE, OUT_H>(sm32, encr, kw, kb, nullptr, nullptr, ck,
                                       nullptr, MROWS, CC, CC, mB, nB);
    else
        tgemm_body<4, EPI_NONE, OUT_HP>(sm32, encr, vw, vb, nullptr, nullptr,
                                        nullptr, cvt, MROWS, CC, CC, mB, nB);
}

#define GSMEM4 (3*(4*32*36 + 128*36)*4)   // 110592 B
#define GSMEM2 (3*(2*32*36 + 128*36)*4)   // 82944 B

// ---------------- fp16 flash attention: ldmatrix + f16x2 exp + MMA row-sums --
#define TQS 36
#define TSMP 4608
#define TSMKV 9216
#define TSTG 4608
#define AT_SMEM (23040*4)   // 92160 B -> 2 CTAs/SM
#define ONESF 0x3C003C00u   // half2(1,1)

template<bool CAUSAL>
__global__ __launch_bounds__(256, 2)
void attn_h(const __half* __restrict__ Q, const __half* __restrict__ Kp,
            const __half* __restrict__ Vt, __half* __restrict__ O,
            int qstride, int kstride)
{
    extern __shared__ uint32_t sm32[];
    const int b = blockIdx.z, h = blockIdx.y;
    const int qt = CAUSAL ? (gridDim.x - 1 - blockIdx.x) : blockIdx.x;
    const int tid = threadIdx.x;
    const int lane = tid & 31, warp = tid >> 5;
    const int r = lane >> 2, q = lane & 3;
    const int j8 = lane >> 3, t8 = lane & 7;
    const int qbase = qt * 128;
    const int qw16 = warp * 16;
    const uint32_t smemBase = (uint32_t)__cvta_generic_to_shared(sm32);

    const int nkt = CAUSAL ? (2 * qt + 2) : (TT / 64);
    const __half* vtb = Vt + (((size_t)(b * HH + h) * DD) << 11);

    auto issueKV = [&](int kt) {
        if (kt < nkt) {
            const int kb = kt * 64;
            const uint32_t sb = smemBase + (uint32_t)((TSMKV + (kt % 3) * TSTG) * 4);
            #pragma unroll
            for (int i = 0; i < 2; i++) {
                const int lin = tid + (i << 8);
                const int row = lin >> 3, c8 = lin & 7;
                cp16(sb + (uint32_t)((row * 36 + c8 * 4) * 4),
                     Kp + (size_t)(b * TT + kb + row) * kstride + h * DD + c8 * 8);
            }
            #pragma unroll
            for (int i = 0; i < 2; i++) {
                const int lin = tid + (i << 8);
                const int row = lin >> 3, c8 = lin & 7;
                cp16(sb + (uint32_t)((2304 + row * 36 + c8 * 4) * 4),
                     vtb + ((size_t)row << 11) + kb + c8 * 8);
            }
        }
        asm volatile("cp.async.commit_group;");
    };

    issueKV(0);
    issueKV(1);

    // Q tile (scaled by 0.125, exact)
    uint32_t* Qs = sm32;
    const __half2 hscale = __floats2half2_rn(0.125f, 0.125f);
    #pragma unroll
    for (int i = 0; i < 4; i++) {
        const int lin = tid + (i << 8);
        const int row = lin >> 3, c8 = lin & 7;
        float4 v = *(const float4*)(Q + (size_t)(b * TT + qbase + row) * qstride
                                    + h * DD + c8 * 8);
        __half2* hv = (__half2*)&v;
        #pragma unroll
        for (int e = 0; e < 4; e++) hv[e] = __hmul2(hv[e], hscale);
        *(float4*)(Qs + row * TQS + c8 * 4) = v;
    }

    const uint32_t aQ = smemBase +
        (uint32_t)(((qw16 + (j8 & 1) * 8 + t8) * TQS + (j8 >> 1) * 4) * 4);
    const uint32_t aP = smemBase +
        (uint32_t)((TSMP + (qw16 + (j8 & 1) * 8 + t8) * TQS + (j8 >> 1) * 4) * 4);
    const uint32_t bPat =
        (uint32_t)((((j8 >> 1) * 8 + t8) * 36 + (j8 & 1) * 4) * 4);

    float oacc[8][4], lacc[4];
    float m0 = -1e30f, m1 = -1e30f;
    #pragma unroll
    for (int nt = 0; nt < 8; nt++)
        #pragma unroll
        for (int e = 0; e < 4; e++) oacc[nt][e] = 0.f;
    #pragma unroll
    for (int e = 0; e < 4; e++) lacc[e] = 0.f;

    for (int kt = 0; kt < nkt; kt++) {
        asm volatile("cp.async.wait_group 1;");
        __syncthreads();
        issueKV(kt + 2);

        const uint32_t smK = smemBase + (uint32_t)((TSMKV + (kt % 3) * TSTG) * 4);
        const uint32_t smV = smK + 2304 * 4;
        const int kbase = kt * 64;

        // ---- S = Q K^T ----
        float sacc[8][4];
        #pragma unroll
        for (int nt = 0; nt < 8; nt++)
            #pragma unroll
            for (int e = 0; e < 4; e++) sacc[nt][e] = 0.f;

        #pragma unroll
        for (int ks = 0; ks < 4; ks++) {
            uint32_t af[4], bk[4][4];
            ldsm4(af, aQ + (uint32_t)(ks * 32));
            #pragma unroll
            for (int p = 0; p < 4; p++)
                ldsm4(bk[p], smK + bPat + (uint32_t)((p * 16 * 36 + ks * 8) * 4));
            #pragma unroll
            for (int nt = 0; nt < 8; nt++)
                mma_f16(sacc[nt], af,
                        bk[nt >> 1][(nt & 1) * 2], bk[nt >> 1][(nt & 1) * 2 + 1]);
        }

        // ---- causal mask ----
        if (CAUSAL && kbase + 63 > qbase + qw16) {
            const int row0 = qbase + qw16 + r, row1 = row0 + 8;
            #pragma unroll
            for (int nt = 0; nt < 8; nt++) {
                const int c0 = kbase + nt * 8 + 2 * q, c1 = c0 + 1;
                if (c0 > row0) sacc[nt][0] = -1e30f;
                if (c1 > row0) sacc[nt][1] = -1e30f;
                if (c0 > row1) sacc[nt][2] = -1e30f;
                if (c1 > row1) sacc[nt][3] = -1e30f;
            }
        }

        // ---- online softmax: row max, then f16x2 exp straight into P ----
        float rm0 = -1e30f, rm1 = -1e30f;
        #pragma unroll
        for (int nt = 0; nt < 8; nt++) {
            rm0 = fmaxf(rm0, fmaxf(sacc[nt][0], sacc[nt][1]));
            rm1 = fmaxf(rm1, fmaxf(sacc[nt][2], sacc[nt][3]));
        }
        rm0 = fmaxf(rm0, __shfl_xor_sync(0xffffffffu, rm0, 1));
        rm0 = fmaxf(rm0, __shfl_xor_sync(0xffffffffu, rm0, 2));
        rm1 = fmaxf(rm1, __shfl_xor_sync(0xffffffffu, rm1, 1));
        rm1 = fmaxf(rm1, __shfl_xor_sync(0xffffffffu, rm1, 2));

        const float mn0 = fmaxf(m0, rm0), mn1 = fmaxf(m1, rm1);
        const float mnl0 = mn0 * L2E, mnl1 = mn1 * L2E;
        const float cr0 = ex2(fmaf(m0, L2E, -mnl0));
        const float cr1 = ex2(fmaf(m1, L2E, -mnl1));
        m0 = mn0; m1 = mn1;

        uint32_t* p0 = sm32 + TSMP + (qw16 + r) * TQS + q;
        uint32_t* p1 = p0 + 8 * TQS;
        #pragma unroll
        for (int nt = 0; nt < 8; nt++) {
            __half2 h0 = __floats2half2_rn(fmaf(sacc[nt][0], L2E, -mnl0),
                                           fmaf(sacc[nt][1], L2E, -mnl0));
            __half2 h1 = __floats2half2_rn(fmaf(sacc[nt][2], L2E, -mnl1),
                                           fmaf(sacc[nt][3], L2E, -mnl1));
            p0[nt * 4] = ex2h2(*(uint32_t*)&h0);
            p1[nt * 4] = ex2h2(*(uint32_t*)&h1);
        }

        // rescale accumulators (l handled identically via lacc)
        #pragma unroll
        for (int nt = 0; nt < 8; nt++) {
            oacc[nt][0] *= cr0; oacc[nt][1] *= cr0;
            oacc[nt][2] *= cr1; oacc[nt][3] *= cr1;
        }
        lacc[0] *= cr0; lacc[1] *= cr0; lacc[2] *= cr1; lacc[3] *= cr1;

        __syncwarp();

        // ---- O += P V ; l += P 1 (tensor-pipe row sums, constant B) ----
        #pragma unroll
        for (int ks = 0; ks < 4; ks++) {
            uint32_t af[4], bv[4][4];
            ldsm4(af, aP + (uint32_t)(ks * 32));
            #pragma unroll
            for (int p = 0; p < 4; p++)
                ldsm4(bv[p], smV + bPat + (uint32_t)((p * 16 * 36 + ks * 8) * 4));
            #pragma unroll
            for (int nt = 0; nt < 8; nt++)
                mma_f16(oacc[nt], af,
                        bv[nt >> 1][(nt & 1) * 2], bv[nt >> 1][(nt & 1) * 2 + 1]);
            mma_f16(lacc, af, ONESF, ONESF);
        }
        __syncwarp();
    }

    const float inv0 = 1.f / lacc[0], inv1 = 1.f / lacc[2];
    const int row0 = qbase + qw16 + r;
    __half* og0 = O + (size_t)(b * TT + row0) * CC + h * DD + 2 * q;
    __half* og1 = O + (size_t)(b * TT + row0 + 8) * CC + h * DD + 2 * q;
    #pragma unroll
    for (int nt = 0; nt < 8; nt++) {
        *(__half2*)(og0 + nt * 8) = __floats2half2_rn(oacc[nt][0] * inv0,
                                                      oacc[nt][1] * inv0);
        *(__half2*)(og1 + nt * 8) = __floats2half2_rn(oacc[nt][2] * inv1,
                                                      oacc[nt][3] * inv1);
    }
}

// ---------------- LayerNorm ---------------------------------------------------
__global__ __launch_bounds__(256)
void layernorm_k(const float* __restrict__ in, const float* __restrict__ g,
                 const float* __restrict__ b, float* __restrict__ out,
                 __half* __restrict__ outh)
{
    const int row = blockIdx.x;
    const int tid = threadIdx.x;
    const float* x = in + (size_t)row * CC;

    const float v0 = x[tid], v1 = x[tid + 256], v2 = x[tid + 512];
    float s = v0 + v1 + v2;
    float sq = v0 * v0 + v1 * v1 + v2 * v2;

    #pragma unroll
    for (int off = 16; off; off >>= 1) {
        s  += __shfl_xor_sync(0xffffffffu, s, off);
        sq += __shfl_xor_sync(0xffffffffu, sq, off);
    }
    __shared__ float red[16];
    const int wid = tid >> 5, lane = tid & 31;
    if (lane == 0) { red[wid] = s; red[wid + 8] = sq; }
    __syncthreads();

    float ts = 0.f, tq = 0.f;
    #pragma unroll
    for (int i = 0; i < 8; i++) { ts += red[i]; tq += red[i + 8]; }

    const float mu = ts * (1.f / CC);
    const float var = tq * (1.f / CC) - mu * mu;
    const float rstd = rsqrtf(var + 1e-5f);

    const float y0 = (v0 - mu) * rstd * g[tid]       + b[tid];
    const float y1 = (v1 - mu) * rstd * g[tid + 256] + b[tid + 256];
    const float y2 = (v2 - mu) * rstd * g[tid + 512] + b[tid + 512];

    float* orow = out + (size_t)row * CC;
    orow[tid] = y0; orow[tid + 256] = y1; orow[tid + 512] = y2;
    if (outh) {
        __half* hrow = outh + (size_t)row * CC;
        hrow[tid]       = __float2half_rn(y0);
        hrow[tid + 256] = __float2half_rn(y1);
        hrow[tid + 512] = __float2half_rn(y2);
    }
}

// ---------------- launch ------------------------------------------------------
extern "C" void kernel_launch(void* const* d_in, const int* in_sizes, int n_in,
                              void* d_out, int out_size)
{
    const float* x      = (const float*)d_in[0];
    const float* enc    = (const float*)d_in[1];
    const float* ln1_g  = (const float*)d_in[2];
    const float* ln1_b  = (const float*)d_in[3];
    const float* qkv_w  = (const float*)d_in[4];
    const float* qkv_b  = (const float*)d_in[5];
    const float* proj_w = (const float*)d_in[6];
    const float* proj_b = (const float*)d_in[7];
    const float* ln2_g  = (const float*)d_in[8];
    const float* ln2_b  = (const float*)d_in[9];
    const float* caq_w  = (const float*)d_in[10];
    const float* caq_b  = (const float*)d_in[11];
    const float* cak_w  = (const float*)d_in[12];
    const float* cak_b  = (const float*)d_in[13];
    const float* cav_w  = (const float*)d_in[14];
    const float* cav_b  = (const float*)d_in[15];
    const float* cao_w  = (const float*)d_in[16];
    const float* cao_b  = (const float*)d_in[17];
    const float* ln3_g  = (const float*)d_in[18];
    const float* ln3_b  = (const float*)d_in[19];
    const float* fc_w   = (const float*)d_in[20];
    const float* fc_b   = (const float*)d_in[21];
    const float* fc2_w  = (const float*)d_in[22];
    const float* fc2_b  = (const float*)d_in[23];
    float* out = (float*)d_out;

    float *res, *x1, *x2;
    __half *x16, *enc16, *qkv16, *vt, *att16, *x1r, *x2r, *cq16, *ck16, *cvt, *h16;
    uint32_t *wq, *wp, *wcq, *wck, *wcv, *wco, *wfc, *wfc2;
    cudaGetSymbolAddress((void**)&res,   g_res);
    cudaGetSymbolAddress((void**)&x1,    g_x1);
    cudaGetSymbolAddress((void**)&x2,    g_x2);
    cudaGetSymbolAddress((void**)&x16,   g_x16);
    cudaGetSymbolAddress((void**)&enc16, g_enc16);
    cudaGetSymbolAddress((void**)&qkv16, g_qkv16);
    cudaGetSymbolAddress((void**)&vt,    g_vt);
    cudaGetSymbolAddress((void**)&att16, g_att16);
    cudaGetSymbolAddress((void**)&x1r,   g_x1r);
    cudaGetSymbolAddress((void**)&x2r,   g_x2r);
    cudaGetSymbolAddress((void**)&cq16,  g_cq16);
    cudaGetSymbolAddress((void**)&ck16,  g_ck16);
    cudaGetSymbolAddress((void**)&cvt,   g_cvt);
    cudaGetSymbolAddress((void**)&h16,   g_h16);
    cudaGetSymbolAddress((void**)&wq,    g_wq);
    cudaGetSymbolAddress((void**)&wp,    g_wp);
    cudaGetSymbolAddress((void**)&wcq,   g_wcq);
    cudaGetSymbolAddress((void**)&wck,   g_wck);
    cudaGetSymbolAddress((void**)&wcv,   g_wcv);
    cudaGetSymbolAddress((void**)&wco,   g_wco);
    cudaGetSymbolAddress((void**)&wfc,   g_wfc);
    cudaGetSymbolAddress((void**)&wfc2,  g_wfc2);

    cudaFuncSetAttribute(attn_h<true>,
                         cudaFuncAttributeMaxDynamicSharedMemorySize, AT_SMEM);
    cudaFuncSetAttribute(attn_h<false>,
                         cudaFuncAttributeMaxDynamicSharedMemorySize, AT_SMEM);
    cudaFuncSetAttribute((const void*)tgemm<4, EPI_NONE, OUT_QKV>,
                         cudaFuncAttributeMaxDynamicSharedMemorySize, GSMEM4);
    cudaFuncSetAttribute((const void*)tgemm<4, EPI_RELU, OUT_H>,
                         cudaFuncAttributeMaxDynamicSharedMemorySize, GSMEM4);
    cudaFuncSetAttribute((const void*)tgemm<2, EPI_RES, OUT_F32>,
                         cudaFuncAttributeMaxDynamicSharedMemorySize, GSMEM2);
    cudaFuncSetAttribute((const void*)tgemm3,
                         cudaFuncAttributeMaxDynamicSharedMemorySize, GSMEM4);

    const dim3 thr(256);
    const dim3 gqkv(3 * CC / 128, MROWS / 128);      // (18,32)
    const dim3 g768s(CC / 128, MROWS / 64);          // (6,64) MT=2
    const dim3 gfc(4 * CC / 128, MROWS / 128);       // (24,32)
    const dim3 g3(CC / 128, MROWS / 128, 3);         // (6,32,3)
    const dim3 gattn(TT / 128, HH, BB);              // (16,12,2)

    // 0) merged pre-pass
    prepack<<<ACT_BLKS + 9216, thr>>>(x, enc, qkv_w, proj_w, caq_w, cak_w,
                                      cav_w, cao_w, fc_w, fc2_w,
                                      x16, enc16, wq, wp, wcq, wck, wcv, wco,
                                      wfc, wfc2);

    // 1) qkv (q,k rowmajor fp16 + V transposed)
    tgemm<4, EPI_NONE, OUT_QKV><<<gqkv, thr, GSMEM4>>>(x16, wq, qkv_b, nullptr,
                                                       nullptr, qkv16, vt,
                                                       MROWS, 3 * CC, CC);
    // 2) causal self-attention
    attn_h<true><<<gattn, thr, AT_SMEM>>>(qkv16, qkv16 + CC, vt, att16,
                                          3 * CC, 3 * CC);
    // 3) proj + residual ; LN1
    tgemm<2, EPI_RES, OUT_F32><<<g768s, thr, GSMEM2>>>(att16, wp, proj_b, x, res,
                                                       nullptr, nullptr,
                                                       MROWS, CC, CC);
    layernorm_k<<<MROWS, thr>>>(res, ln1_g, ln1_b, x1, x1r);

    // 4) cross projections (cv written transposed)
    tgemm3<<<g3, thr, GSMEM4>>>(x1r, enc16, wcq, caq_b, wck, cak_b,
                                wcv, cav_b, cq16, ck16, cvt);
    // 5) cross attention
    attn_h<false><<<gattn, thr, AT_SMEM>>>(cq16, ck16, cvt, att16, CC, CC);
    // 6) cao + residual ; LN2
    tgemm<2, EPI_RES, OUT_F32><<<g768s, thr, GSMEM2>>>(att16, wco, cao_b, x1, res,
                                                       nullptr, nullptr,
                                                       MROWS, CC, CC);
    layernorm_k<<<MROWS, thr>>>(res, ln2_g, ln2_b, x2, x2r);

    // 7) MLP
    tgemm<4, EPI_RELU, OUT_H><<<gfc, thr, GSMEM4>>>(x2r, wfc, fc_b, nullptr,
                                                    nullptr, h16, nullptr,
                                                    MROWS, 4 * CC, CC);
    tgemm<2, EPI_RES, OUT_F32><<<g768s, thr, GSMEM2>>>(h16, wfc2, fc2_b, x2, res,
                                                       nullptr, nullptr,
                                                       MROWS, CC, 4 * CC);
    // 8) LN3 -> out
    layernorm_k<<<MROWS, thr>>>(res, ln3_g, ln3_b, out, nullptr);
}